// round 1
// baseline (speedup 1.0000x reference)
#include <cuda_runtime.h>
#include <math.h>

#define BB 2
#define SS 2048
#define DD 2048
#define HH 16
#define HD 128
#define WIN 1024
#define EPSV 1e-6f
#define SCALEF 0.08838834764831845f   // 128^-0.5

#define NSC (BB * SS * HH * HD)
__device__ float g_q[NSC];
__device__ float g_k[NSC];
__device__ float g_v[NSC];
__device__ float g_attn[NSC];

// ---------------------------------------------------------------------------
// SGEMM: C[M,N] = A[M,K] @ B[K,N], row-major, fp32.
// 128x128 tile, BK=8, 256 threads, 8x8 microtile (split 4+4 to cut smem bank
// conflicts to 2-way), double-buffered smem, float4 everywhere.
// M,N,K assumed multiples of 128/128/8 (true here: 4096/2048/2048).
// ---------------------------------------------------------------------------
__global__ void __launch_bounds__(256) sgemm_kernel(
    const float* __restrict__ A, const float* __restrict__ B,
    float* __restrict__ C, int M, int N, int K)
{
    __shared__ float As[2][8][128];   // transposed: As[k][m]
    __shared__ float Bs[2][8][128];   // Bs[k][n]

    const int tid = threadIdx.x;
    const int ty = tid >> 4, tx = tid & 15;
    const int bm = blockIdx.y * 128, bn = blockIdx.x * 128;
    const int arow = tid >> 1, acol = (tid & 1) * 4;
    const int brow = tid >> 5, bcol = (tid & 31) * 4;

    const float* Ag = A + (size_t)(bm + arow) * K + acol;
    const float* Bg = B + (size_t)brow * N + bn + bcol;

    float acc[8][8];
#pragma unroll
    for (int i = 0; i < 8; i++)
#pragma unroll
        for (int j = 0; j < 8; j++) acc[i][j] = 0.f;

    // prologue: tile 0 -> buffer 0
    {
        const float4 a = *(const float4*)Ag;
        As[0][acol + 0][arow] = a.x; As[0][acol + 1][arow] = a.y;
        As[0][acol + 2][arow] = a.z; As[0][acol + 3][arow] = a.w;
        *(float4*)&Bs[0][brow][bcol] = *(const float4*)Bg;
    }
    __syncthreads();

    const int nk = K >> 3;
    for (int t = 0; t < nk; t++) {
        const int cur = t & 1;
        float4 an, bnv;
        const bool has = (t + 1 < nk);
        if (has) {
            an  = *(const float4*)(Ag + (t + 1) * 8);
            bnv = *(const float4*)(Bg + (size_t)(t + 1) * 8 * N);
        }
#pragma unroll
        for (int k = 0; k < 8; k++) {
            const float4 a0 = *(const float4*)&As[cur][k][ty * 4];
            const float4 a1 = *(const float4*)&As[cur][k][64 + ty * 4];
            const float4 b0 = *(const float4*)&Bs[cur][k][tx * 4];
            const float4 b1 = *(const float4*)&Bs[cur][k][64 + tx * 4];
            const float af[8] = {a0.x, a0.y, a0.z, a0.w, a1.x, a1.y, a1.z, a1.w};
            const float bf[8] = {b0.x, b0.y, b0.z, b0.w, b1.x, b1.y, b1.z, b1.w};
#pragma unroll
            for (int i = 0; i < 8; i++)
#pragma unroll
                for (int j = 0; j < 8; j++)
                    acc[i][j] += af[i] * bf[j];
        }
        if (has) {
            const int nx = cur ^ 1;
            As[nx][acol + 0][arow] = an.x; As[nx][acol + 1][arow] = an.y;
            As[nx][acol + 2][arow] = an.z; As[nx][acol + 3][arow] = an.w;
            *(float4*)&Bs[nx][brow][bcol] = bnv;
        }
        __syncthreads();
    }

#pragma unroll
    for (int i = 0; i < 8; i++) {
        const int r = bm + ((i < 4) ? (ty * 4 + i) : (64 + ty * 4 + i - 4));
        const float4 v0 = make_float4(acc[i][0], acc[i][1], acc[i][2], acc[i][3]);
        const float4 v1 = make_float4(acc[i][4], acc[i][5], acc[i][6], acc[i][7]);
        *(float4*)&C[(size_t)r * N + bn + tx * 4] = v0;
        *(float4*)&C[(size_t)r * N + bn + 64 + tx * 4] = v1;
    }
}

// ---------------------------------------------------------------------------
// Fused per-head RMSNorm + RoPE, in place on x = [B,S,H,HD].
// One block of 128 threads per (b,s,h) row.
// ---------------------------------------------------------------------------
__global__ void __launch_bounds__(128) rmsrope_kernel(
    float* __restrict__ x, const float* __restrict__ scale,
    const float* __restrict__ cosb, const float* __restrict__ sinb)
{
    __shared__ float sh[HD];
    __shared__ float red[4];
    const int row = blockIdx.x;           // (b*S + s)*H + h
    const int d = threadIdx.x;
    const size_t base = (size_t)row * HD;

    const float v = x[base + d];
    float ssum = v * v;
#pragma unroll
    for (int o = 16; o > 0; o >>= 1) ssum += __shfl_xor_sync(0xffffffffu, ssum, o);
    if ((d & 31) == 0) red[d >> 5] = ssum;
    __syncthreads();
    const float tot = red[0] + red[1] + red[2] + red[3];
    const float r = rsqrtf(tot * (1.f / HD) + EPSV);
    const float xn = scale[d] * v * r;
    sh[d] = xn;
    __syncthreads();
    const float rot = (d < 64) ? -sh[d + 64] : sh[d - 64];
    const size_t cbase = (size_t)(row / HH) * HD;   // (b*S + s) * HD
    x[base + d] = xn * cosb[cbase + d] + rot * sinb[cbase + d];
}

// ---------------------------------------------------------------------------
// Sliding-window flash attention. Block = (q-tile of 64 rows, head, batch),
// 256 threads. Q scaled at load. K kept d-major in smem (conflict-free score
// reads). Online softmax: 4 threads per row, O rows in registers (32 f32/thr).
// ---------------------------------------------------------------------------
#define QPAD 132
#define KPAD 68
#define SPAD 68
#define FLASH_SMEM ((64 * QPAD + 128 * KPAD + 64 * 128 + 64 * SPAD) * 4)

__global__ void __launch_bounds__(256) flash_kernel(
    const float* __restrict__ Qg, const float* __restrict__ Kg,
    const float* __restrict__ Vg, float* __restrict__ Og)
{
    extern __shared__ float smf[];
    float* Qs  = smf;                    // [64][QPAD]
    float* Kst = Qs + 64 * QPAD;         // [128][KPAD]   d-major K^T
    float* Vs  = Kst + 128 * KPAD;       // [64][128]
    float* Ss  = Vs + 64 * 128;          // [64][SPAD]

    const int tid = threadIdx.x;
    const int qb = blockIdx.x, h = blockIdx.y, b = blockIdx.z;
    const int qs0 = qb * 64;
    const int ty = tid >> 4, tx = tid & 15;   // score compute mapping (16x16)
    const int rg = tid >> 2, g = tid & 3;     // softmax/PV mapping (64 rows x 4)
    const int d0 = g * 32;

    // load Q tile (pre-scaled)
    for (int i = tid; i < 64 * 32; i += 256) {
        const int r = i >> 5, c = (i & 31) << 2;
        float4 v = *(const float4*)&Qg[(((size_t)b * SS + qs0 + r) * HH + h) * HD + c];
        v.x *= SCALEF; v.y *= SCALEF; v.z *= SCALEF; v.w *= SCALEF;
        *(float4*)&Qs[r * QPAD + c] = v;
    }

    float O[32];
#pragma unroll
    for (int i = 0; i < 32; i++) O[i] = 0.f;
    float m = -1e30f, l = 0.f;

    const int kb_lo = (qs0 >= WIN) ? (qs0 - WIN) / 64 : 0;
    for (int kb = kb_lo; kb <= qb; kb++) {
        __syncthreads();   // prior tile's smem consumers done
        // K tile, stored transposed (d-major); lanes span rows -> conflict-free STS
        for (int i = tid; i < 64 * 32; i += 256) {
            const int r = i & 63, cb = (i >> 6) << 2;
            const float4 kv = *(const float4*)&Kg[(((size_t)b * SS + kb * 64 + r) * HH + h) * HD + cb];
            Kst[(cb + 0) * KPAD + r] = kv.x;
            Kst[(cb + 1) * KPAD + r] = kv.y;
            Kst[(cb + 2) * KPAD + r] = kv.z;
            Kst[(cb + 3) * KPAD + r] = kv.w;
        }
        // V tile (row-major)
        for (int i = tid; i < 64 * 32; i += 256) {
            const int r = i >> 5, c = (i & 31) << 2;
            *(float4*)&Vs[r * HD + c] =
                *(const float4*)&Vg[(((size_t)b * SS + kb * 64 + r) * HH + h) * HD + c];
        }
        __syncthreads();

        // S = Q @ K^T (each thread: 4 rows x 4 cols)
        float acc[4][4];
#pragma unroll
        for (int i = 0; i < 4; i++)
#pragma unroll
            for (int j = 0; j < 4; j++) acc[i][j] = 0.f;

        for (int d4 = 0; d4 < 32; d4++) {
            float am[4][4];
#pragma unroll
            for (int i = 0; i < 4; i++) {
                const float4 aq = *(const float4*)&Qs[(ty * 4 + i) * QPAD + d4 * 4];
                am[i][0] = aq.x; am[i][1] = aq.y; am[i][2] = aq.z; am[i][3] = aq.w;
            }
#pragma unroll
            for (int u = 0; u < 4; u++) {
                const float4 bv = *(const float4*)&Kst[(d4 * 4 + u) * KPAD + tx * 4];
#pragma unroll
                for (int i = 0; i < 4; i++) {
                    acc[i][0] += am[i][u] * bv.x;
                    acc[i][1] += am[i][u] * bv.y;
                    acc[i][2] += am[i][u] * bv.z;
                    acc[i][3] += am[i][u] * bv.w;
                }
            }
        }

        // mask + stage scores
#pragma unroll
        for (int i = 0; i < 4; i++) {
            const int gi = qs0 + ty * 4 + i;
#pragma unroll
            for (int j = 0; j < 4; j++) {
                const int gj = kb * 64 + tx * 4 + j;
                float s = acc[i][j];
                if (gj > gi || gj < gi - WIN) s = -1e30f;
                Ss[(ty * 4 + i) * SPAD + tx * 4 + j] = s;
            }
        }
        __syncthreads();

        // online softmax, 4 threads per row
        float rmax = -1e30f;
#pragma unroll
        for (int c = g; c < 64; c += 4) rmax = fmaxf(rmax, Ss[rg * SPAD + c]);
        rmax = fmaxf(rmax, __shfl_xor_sync(0xffffffffu, rmax, 1));
        rmax = fmaxf(rmax, __shfl_xor_sync(0xffffffffu, rmax, 2));
        const float mnew = fmaxf(m, rmax);
        const float corr = __expf(m - mnew);
        float lsum = 0.f;
#pragma unroll
        for (int c = g; c < 64; c += 4) {
            const float p = __expf(Ss[rg * SPAD + c] - mnew);
            Ss[rg * SPAD + c] = p;
            lsum += p;
        }
        lsum += __shfl_xor_sync(0xffffffffu, lsum, 1);
        lsum += __shfl_xor_sync(0xffffffffu, lsum, 2);
        l = l * corr + lsum;
        m = mnew;
#pragma unroll
        for (int i = 0; i < 32; i++) O[i] *= corr;
        __syncwarp();   // group's P writes visible to group's PV reads

        // O += P @ V  (thread owns row rg, d slice [d0, d0+32))
        for (int c = 0; c < 64; c++) {
            const float p = Ss[rg * SPAD + c];
            const float4* vp = (const float4*)&Vs[c * HD + d0];
#pragma unroll
            for (int q4 = 0; q4 < 8; q4++) {
                const float4 v = vp[q4];
                O[q4 * 4 + 0] += p * v.x;
                O[q4 * 4 + 1] += p * v.y;
                O[q4 * 4 + 2] += p * v.z;
                O[q4 * 4 + 3] += p * v.w;
            }
        }
    }

    const float inv = 1.f / l;
    const size_t ob = (((size_t)b * SS + qs0 + rg) * HH + h) * HD + d0;
#pragma unroll
    for (int q4 = 0; q4 < 8; q4++) {
        const float4 v = make_float4(O[q4 * 4 + 0] * inv, O[q4 * 4 + 1] * inv,
                                     O[q4 * 4 + 2] * inv, O[q4 * 4 + 3] * inv);
        *(float4*)&Og[ob + q4 * 4] = v;
    }
}

// ---------------------------------------------------------------------------
extern "C" void kernel_launch(void* const* d_in, const int* in_sizes, int n_in,
                              void* d_out, int out_size)
{
    const float* hidden = (const float*)d_in[0];
    const float* cosb   = (const float*)d_in[1];
    const float* sinb   = (const float*)d_in[2];
    const float* Wq     = (const float*)d_in[3];
    const float* Wk     = (const float*)d_in[4];
    const float* Wv     = (const float*)d_in[5];
    const float* Wo     = (const float*)d_in[6];
    const float* qscale = (const float*)d_in[7];
    const float* kscale = (const float*)d_in[8];
    float* out = (float*)d_out;

    float *gq, *gk, *gv, *ga;
    cudaGetSymbolAddress((void**)&gq, g_q);
    cudaGetSymbolAddress((void**)&gk, g_k);
    cudaGetSymbolAddress((void**)&gv, g_v);
    cudaGetSymbolAddress((void**)&ga, g_attn);

    cudaFuncSetAttribute(flash_kernel,
                         cudaFuncAttributeMaxDynamicSharedMemorySize, FLASH_SMEM);

    const int M = BB * SS;                 // 4096
    dim3 gemm_grid(DD / 128, M / 128);     // (16, 32)

    sgemm_kernel<<<gemm_grid, 256>>>(hidden, Wq, gq, M, DD, DD);
    sgemm_kernel<<<gemm_grid, 256>>>(hidden, Wk, gk, M, DD, DD);
    sgemm_kernel<<<gemm_grid, 256>>>(hidden, Wv, gv, M, DD, DD);

    rmsrope_kernel<<<M * HH, HD>>>(gq, qscale, cosb, sinb);
    rmsrope_kernel<<<M * HH, HD>>>(gk, kscale, cosb, sinb);

    flash_kernel<<<dim3(SS / 64, HH, BB), 256, FLASH_SMEM>>>(gq, gk, gv, ga);

    sgemm_kernel<<<gemm_grid, 256>>>(ga, Wo, out, M, DD, DD);
}

// round 2
// speedup vs baseline: 1.0002x; 1.0002x over previous
#include <cuda_runtime.h>
#include <math.h>

#define BB 2
#define SS 2048
#define DD 2048
#define HH 16
#define HD 128
#define WIN 1024
#define EPSV 1e-6f
#define SCALEF 0.08838834764831845f   // 128^-0.5

#define NSC (BB * SS * HH * HD)
__device__ float g_q[NSC];
__device__ float g_k[NSC];
__device__ float g_v[NSC];
__device__ float g_attn[NSC];

// ---------------------------------------------------------------------------
// SGEMM: C[M,N] = A[M,K] @ B[K,N], row-major, fp32.
// 128x128 tile, BK=8, 256 threads, 8x8 microtile (split 4+4 to cut smem bank
// conflicts to 2-way), double-buffered smem, float4 everywhere.
// M,N,K assumed multiples of 128/128/8 (true here: 4096/2048/2048).
// ---------------------------------------------------------------------------
__global__ void __launch_bounds__(256) sgemm_kernel(
    const float* __restrict__ A, const float* __restrict__ B,
    float* __restrict__ C, int M, int N, int K)
{
    __shared__ float As[2][8][128];   // transposed: As[k][m]
    __shared__ float Bs[2][8][128];   // Bs[k][n]

    const int tid = threadIdx.x;
    const int ty = tid >> 4, tx = tid & 15;
    const int bm = blockIdx.y * 128, bn = blockIdx.x * 128;
    const int arow = tid >> 1, acol = (tid & 1) * 4;
    const int brow = tid >> 5, bcol = (tid & 31) * 4;

    const float* Ag = A + (size_t)(bm + arow) * K + acol;
    const float* Bg = B + (size_t)brow * N + bn + bcol;

    float acc[8][8];
#pragma unroll
    for (int i = 0; i < 8; i++)
#pragma unroll
        for (int j = 0; j < 8; j++) acc[i][j] = 0.f;

    // prologue: tile 0 -> buffer 0
    {
        const float4 a = *(const float4*)Ag;
        As[0][acol + 0][arow] = a.x; As[0][acol + 1][arow] = a.y;
        As[0][acol + 2][arow] = a.z; As[0][acol + 3][arow] = a.w;
        *(float4*)&Bs[0][brow][bcol] = *(const float4*)Bg;
    }
    __syncthreads();

    const int nk = K >> 3;
    for (int t = 0; t < nk; t++) {
        const int cur = t & 1;
        float4 an, bnv;
        const bool has = (t + 1 < nk);
        if (has) {
            an  = *(const float4*)(Ag + (t + 1) * 8);
            bnv = *(const float4*)(Bg + (size_t)(t + 1) * 8 * N);
        }
#pragma unroll
        for (int k = 0; k < 8; k++) {
            const float4 a0 = *(const float4*)&As[cur][k][ty * 4];
            const float4 a1 = *(const float4*)&As[cur][k][64 + ty * 4];
            const float4 b0 = *(const float4*)&Bs[cur][k][tx * 4];
            const float4 b1 = *(const float4*)&Bs[cur][k][64 + tx * 4];
            const float af[8] = {a0.x, a0.y, a0.z, a0.w, a1.x, a1.y, a1.z, a1.w};
            const float bf[8] = {b0.x, b0.y, b0.z, b0.w, b1.x, b1.y, b1.z, b1.w};
#pragma unroll
            for (int i = 0; i < 8; i++)
#pragma unroll
                for (int j = 0; j < 8; j++)
                    acc[i][j] += af[i] * bf[j];
        }
        if (has) {
            const int nx = cur ^ 1;
            As[nx][acol + 0][arow] = an.x; As[nx][acol + 1][arow] = an.y;
            As[nx][acol + 2][arow] = an.z; As[nx][acol + 3][arow] = an.w;
            *(float4*)&Bs[nx][brow][bcol] = bnv;
        }
        __syncthreads();
    }

#pragma unroll
    for (int i = 0; i < 8; i++) {
        const int r = bm + ((i < 4) ? (ty * 4 + i) : (64 + ty * 4 + i - 4));
        const float4 v0 = make_float4(acc[i][0], acc[i][1], acc[i][2], acc[i][3]);
        const float4 v1 = make_float4(acc[i][4], acc[i][5], acc[i][6], acc[i][7]);
        *(float4*)&C[(size_t)r * N + bn + tx * 4] = v0;
        *(float4*)&C[(size_t)r * N + bn + 64 + tx * 4] = v1;
    }
}

// ---------------------------------------------------------------------------
// Fused per-head RMSNorm + RoPE, in place on x = [B,S,H,HD].
// One block of 128 threads per (b,s,h) row.
// ---------------------------------------------------------------------------
__global__ void __launch_bounds__(128) rmsrope_kernel(
    float* __restrict__ x, const float* __restrict__ scale,
    const float* __restrict__ cosb, const float* __restrict__ sinb)
{
    __shared__ float sh[HD];
    __shared__ float red[4];
    const int row = blockIdx.x;           // (b*S + s)*H + h
    const int d = threadIdx.x;
    const size_t base = (size_t)row * HD;

    const float v = x[base + d];
    float ssum = v * v;
#pragma unroll
    for (int o = 16; o > 0; o >>= 1) ssum += __shfl_xor_sync(0xffffffffu, ssum, o);
    if ((d & 31) == 0) red[d >> 5] = ssum;
    __syncthreads();
    const float tot = red[0] + red[1] + red[2] + red[3];
    const float r = rsqrtf(tot * (1.f / HD) + EPSV);
    const float xn = scale[d] * v * r;
    sh[d] = xn;
    __syncthreads();
    const float rot = (d < 64) ? -sh[d + 64] : sh[d - 64];
    const size_t cbase = (size_t)(row / HH) * HD;   // (b*S + s) * HD
    x[base + d] = xn * cosb[cbase + d] + rot * sinb[cbase + d];
}

// ---------------------------------------------------------------------------
// Sliding-window flash attention. Block = (q-tile of 64 rows, head, batch),
// 256 threads. Q scaled at load. K kept d-major in smem (conflict-free score
// reads). Online softmax: 4 threads per row, O rows in registers (32 f32/thr).
// ---------------------------------------------------------------------------
#define QPAD 132
#define KPAD 68
#define SPAD 68
#define FLASH_SMEM ((64 * QPAD + 128 * KPAD + 64 * 128 + 64 * SPAD) * 4)

__global__ void __launch_bounds__(256) flash_kernel(
    const float* __restrict__ Qg, const float* __restrict__ Kg,
    const float* __restrict__ Vg, float* __restrict__ Og)
{
    extern __shared__ float smf[];
    float* Qs  = smf;                    // [64][QPAD]
    float* Kst = Qs + 64 * QPAD;         // [128][KPAD]   d-major K^T
    float* Vs  = Kst + 128 * KPAD;       // [64][128]
    float* Ss  = Vs + 64 * 128;          // [64][SPAD]

    const int tid = threadIdx.x;
    const int qb = blockIdx.x, h = blockIdx.y, b = blockIdx.z;
    const int qs0 = qb * 64;
    const int ty = tid >> 4, tx = tid & 15;   // score compute mapping (16x16)
    const int rg = tid >> 2, g = tid & 3;     // softmax/PV mapping (64 rows x 4)
    const int d0 = g * 32;

    // load Q tile (pre-scaled)
    for (int i = tid; i < 64 * 32; i += 256) {
        const int r = i >> 5, c = (i & 31) << 2;
        float4 v = *(const float4*)&Qg[(((size_t)b * SS + qs0 + r) * HH + h) * HD + c];
        v.x *= SCALEF; v.y *= SCALEF; v.z *= SCALEF; v.w *= SCALEF;
        *(float4*)&Qs[r * QPAD + c] = v;
    }

    float O[32];
#pragma unroll
    for (int i = 0; i < 32; i++) O[i] = 0.f;
    float m = -1e30f, l = 0.f;

    const int kb_lo = (qs0 >= WIN) ? (qs0 - WIN) / 64 : 0;
    for (int kb = kb_lo; kb <= qb; kb++) {
        __syncthreads();   // prior tile's smem consumers done
        // K tile, stored transposed (d-major); lanes span rows -> conflict-free STS
        for (int i = tid; i < 64 * 32; i += 256) {
            const int r = i & 63, cb = (i >> 6) << 2;
            const float4 kv = *(const float4*)&Kg[(((size_t)b * SS + kb * 64 + r) * HH + h) * HD + cb];
            Kst[(cb + 0) * KPAD + r] = kv.x;
            Kst[(cb + 1) * KPAD + r] = kv.y;
            Kst[(cb + 2) * KPAD + r] = kv.z;
            Kst[(cb + 3) * KPAD + r] = kv.w;
        }
        // V tile (row-major)
        for (int i = tid; i < 64 * 32; i += 256) {
            const int r = i >> 5, c = (i & 31) << 2;
            *(float4*)&Vs[r * HD + c] =
                *(const float4*)&Vg[(((size_t)b * SS + kb * 64 + r) * HH + h) * HD + c];
        }
        __syncthreads();

        // S = Q @ K^T (each thread: 4 rows x 4 cols)
        float acc[4][4];
#pragma unroll
        for (int i = 0; i < 4; i++)
#pragma unroll
            for (int j = 0; j < 4; j++) acc[i][j] = 0.f;

        for (int d4 = 0; d4 < 32; d4++) {
            float am[4][4];
#pragma unroll
            for (int i = 0; i < 4; i++) {
                const float4 aq = *(const float4*)&Qs[(ty * 4 + i) * QPAD + d4 * 4];
                am[i][0] = aq.x; am[i][1] = aq.y; am[i][2] = aq.z; am[i][3] = aq.w;
            }
#pragma unroll
            for (int u = 0; u < 4; u++) {
                const float4 bv = *(const float4*)&Kst[(d4 * 4 + u) * KPAD + tx * 4];
#pragma unroll
                for (int i = 0; i < 4; i++) {
                    acc[i][0] += am[i][u] * bv.x;
                    acc[i][1] += am[i][u] * bv.y;
                    acc[i][2] += am[i][u] * bv.z;
                    acc[i][3] += am[i][u] * bv.w;
                }
            }
        }

        // mask + stage scores
#pragma unroll
        for (int i = 0; i < 4; i++) {
            const int gi = qs0 + ty * 4 + i;
#pragma unroll
            for (int j = 0; j < 4; j++) {
                const int gj = kb * 64 + tx * 4 + j;
                float s = acc[i][j];
                if (gj > gi || gj < gi - WIN) s = -1e30f;
                Ss[(ty * 4 + i) * SPAD + tx * 4 + j] = s;
            }
        }
        __syncthreads();

        // online softmax, 4 threads per row
        float rmax = -1e30f;
#pragma unroll
        for (int c = g; c < 64; c += 4) rmax = fmaxf(rmax, Ss[rg * SPAD + c]);
        rmax = fmaxf(rmax, __shfl_xor_sync(0xffffffffu, rmax, 1));
        rmax = fmaxf(rmax, __shfl_xor_sync(0xffffffffu, rmax, 2));
        const float mnew = fmaxf(m, rmax);
        const float corr = __expf(m - mnew);
        float lsum = 0.f;
#pragma unroll
        for (int c = g; c < 64; c += 4) {
            const float p = __expf(Ss[rg * SPAD + c] - mnew);
            Ss[rg * SPAD + c] = p;
            lsum += p;
        }
        lsum += __shfl_xor_sync(0xffffffffu, lsum, 1);
        lsum += __shfl_xor_sync(0xffffffffu, lsum, 2);
        l = l * corr + lsum;
        m = mnew;
#pragma unroll
        for (int i = 0; i < 32; i++) O[i] *= corr;
        __syncwarp();   // group's P writes visible to group's PV reads

        // O += P @ V  (thread owns row rg, d slice [d0, d0+32))
        for (int c = 0; c < 64; c++) {
            const float p = Ss[rg * SPAD + c];
            const float4* vp = (const float4*)&Vs[c * HD + d0];
#pragma unroll
            for (int q4 = 0; q4 < 8; q4++) {
                const float4 v = vp[q4];
                O[q4 * 4 + 0] += p * v.x;
                O[q4 * 4 + 1] += p * v.y;
                O[q4 * 4 + 2] += p * v.z;
                O[q4 * 4 + 3] += p * v.w;
            }
        }
    }

    const float inv = 1.f / l;
    const size_t ob = (((size_t)b * SS + qs0 + rg) * HH + h) * HD + d0;
#pragma unroll
    for (int q4 = 0; q4 < 8; q4++) {
        const float4 v = make_float4(O[q4 * 4 + 0] * inv, O[q4 * 4 + 1] * inv,
                                     O[q4 * 4 + 2] * inv, O[q4 * 4 + 3] * inv);
        *(float4*)&Og[ob + q4 * 4] = v;
    }
}

// ---------------------------------------------------------------------------
extern "C" void kernel_launch(void* const* d_in, const int* in_sizes, int n_in,
                              void* d_out, int out_size)
{
    const float* hidden = (const float*)d_in[0];
    const float* cosb   = (const float*)d_in[1];
    const float* sinb   = (const float*)d_in[2];
    const float* Wq     = (const float*)d_in[3];
    const float* Wk     = (const float*)d_in[4];
    const float* Wv     = (const float*)d_in[5];
    const float* Wo     = (const float*)d_in[6];
    const float* qscale = (const float*)d_in[7];
    const float* kscale = (const float*)d_in[8];
    float* out = (float*)d_out;

    float *gq, *gk, *gv, *ga;
    cudaGetSymbolAddress((void**)&gq, g_q);
    cudaGetSymbolAddress((void**)&gk, g_k);
    cudaGetSymbolAddress((void**)&gv, g_v);
    cudaGetSymbolAddress((void**)&ga, g_attn);

    cudaFuncSetAttribute(flash_kernel,
                         cudaFuncAttributeMaxDynamicSharedMemorySize, FLASH_SMEM);

    const int M = BB * SS;                 // 4096
    dim3 gemm_grid(DD / 128, M / 128);     // (16, 32)

    sgemm_kernel<<<gemm_grid, 256>>>(hidden, Wq, gq, M, DD, DD);
    sgemm_kernel<<<gemm_grid, 256>>>(hidden, Wk, gk, M, DD, DD);
    sgemm_kernel<<<gemm_grid, 256>>>(hidden, Wv, gv, M, DD, DD);

    rmsrope_kernel<<<M * HH, HD>>>(gq, qscale, cosb, sinb);
    rmsrope_kernel<<<M * HH, HD>>>(gk, kscale, cosb, sinb);

    flash_kernel<<<dim3(SS / 64, HH, BB), 256, FLASH_SMEM>>>(gq, gk, gv, ga);

    sgemm_kernel<<<gemm_grid, 256>>>(ga, Wo, out, M, DD, DD);
}

// round 4
// speedup vs baseline: 1.2221x; 1.2219x over previous
#include <cuda_runtime.h>
#include <cuda_bf16.h>
#include <math.h>
#include <stdint.h>

#define BB 2
#define SS 2048
#define DD 2048
#define HH 16
#define HD 128
#define WIN 1024
#define EPSV 1e-6f
#define SCALEF 0.08838834764831845f   // 128^-0.5

#define NSC (BB * SS * HH * HD)
__device__ float g_q[NSC];
__device__ float g_k[NSC];
__device__ float g_v[NSC];
__device__ float g_attn[NSC];

// bf16 split operand buffers
__device__ __nv_bfloat16 g_hh[BB * SS * DD];   // hidden hi
__device__ __nv_bfloat16 g_hl[BB * SS * DD];   // hidden lo
__device__ __nv_bfloat16 g_ah[BB * SS * DD];   // attn-out hi
__device__ __nv_bfloat16 g_al[BB * SS * DD];   // attn-out lo
__device__ __nv_bfloat16 g_wqh[DD * DD], g_wql[DD * DD];
__device__ __nv_bfloat16 g_wkh[DD * DD], g_wkl[DD * DD];
__device__ __nv_bfloat16 g_wvh[DD * DD], g_wvl[DD * DD];
__device__ __nv_bfloat16 g_woh[DD * DD], g_wol[DD * DD];

// ---------------------------------------------------------------------------
// helpers (baseline PTX only — compute_103-safe: mma.sync / ldmatrix / cp.async)
// ---------------------------------------------------------------------------
__device__ __forceinline__ uint32_t smem_to_u32(const void* p) {
    uint32_t a;
    asm("{ .reg .u64 t; cvta.to.shared.u64 t, %1; cvt.u32.u64 %0, t; }"
        : "=r"(a) : "l"(p));
    return a;
}

#define LDM_X4(r0, r1, r2, r3, a) \
    asm volatile("ldmatrix.sync.aligned.m8n8.x4.shared.b16 {%0,%1,%2,%3}, [%4];" \
        : "=r"(r0), "=r"(r1), "=r"(r2), "=r"(r3) : "r"(a))

__device__ __forceinline__ void mma_bf16(float* d, const uint32_t* a,
                                         uint32_t b0, uint32_t b1) {
    asm volatile(
        "mma.sync.aligned.m16n8k16.row.col.f32.bf16.bf16.f32 "
        "{%0,%1,%2,%3}, {%4,%5,%6,%7}, {%8,%9}, {%0,%1,%2,%3};"
        : "+f"(d[0]), "+f"(d[1]), "+f"(d[2]), "+f"(d[3])
        : "r"(a[0]), "r"(a[1]), "r"(a[2]), "r"(a[3]), "r"(b0), "r"(b1));
}

__device__ __forceinline__ void cp16(uint32_t dst, const void* src) {
    asm volatile("cp.async.cg.shared.global [%0], [%1], 16;" :: "r"(dst), "l"(src));
}
#define CP_COMMIT() asm volatile("cp.async.commit_group;")

// ---------------------------------------------------------------------------
// fp32 -> bf16 hi/lo split (elementwise, float4 granularity)
// ---------------------------------------------------------------------------
__global__ void __launch_bounds__(256) convert_split_kernel(
    const float* __restrict__ x, __nv_bfloat16* __restrict__ hi,
    __nv_bfloat16* __restrict__ lo, int n4)
{
    int i = blockIdx.x * blockDim.x + threadIdx.x;
    if (i >= n4) return;
    float4 v = ((const float4*)x)[i];
    __nv_bfloat16 h0 = __float2bfloat16(v.x), h1 = __float2bfloat16(v.y);
    __nv_bfloat16 h2 = __float2bfloat16(v.z), h3 = __float2bfloat16(v.w);
    __nv_bfloat16 l0 = __float2bfloat16(v.x - __bfloat162float(h0));
    __nv_bfloat16 l1 = __float2bfloat16(v.y - __bfloat162float(h1));
    __nv_bfloat16 l2 = __float2bfloat16(v.z - __bfloat162float(h2));
    __nv_bfloat16 l3 = __float2bfloat16(v.w - __bfloat162float(h3));
    __nv_bfloat162* hp = (__nv_bfloat162*)(hi + 4 * (size_t)i);
    __nv_bfloat162* lp = (__nv_bfloat162*)(lo + 4 * (size_t)i);
    hp[0] = __halves2bfloat162(h0, h1); hp[1] = __halves2bfloat162(h2, h3);
    lp[0] = __halves2bfloat162(l0, l1); lp[1] = __halves2bfloat162(l2, l3);
}

// ---------------------------------------------------------------------------
// W[K][N] fp32 -> transposed bf16 hi/lo [N][K]
// ---------------------------------------------------------------------------
__global__ void __launch_bounds__(256) transpose_split_kernel(
    const float* __restrict__ W, __nv_bfloat16* __restrict__ Thi,
    __nv_bfloat16* __restrict__ Tlo)
{
    __shared__ float t[32][33];
    const int k0 = blockIdx.y * 32, n0 = blockIdx.x * 32;
    const int tx = threadIdx.x, ty = threadIdx.y;
#pragma unroll
    for (int r = 0; r < 32; r += 8)
        t[ty + r][tx] = W[(size_t)(k0 + ty + r) * DD + n0 + tx];
    __syncthreads();
#pragma unroll
    for (int r = 0; r < 32; r += 8) {
        const float v = t[tx][ty + r];
        __nv_bfloat16 h = __float2bfloat16(v);
        __nv_bfloat16 l = __float2bfloat16(v - __bfloat162float(h));
        const size_t o = (size_t)(n0 + ty + r) * DD + k0 + tx;
        Thi[o] = h; Tlo[o] = l;
    }
}

// ---------------------------------------------------------------------------
// bf16 split-precision GEMM on HMMA (mma.sync m16n8k16):
//   C[M,N] = A[M,K] @ W[K,N],  A as (Ahi,Alo)[M][K], W pre-transposed to
//   (Bhi,Blo)[N][K].  D += Ahi*Bhi + Ahi*Blo + Alo*Bhi.
// CTA tile 128x128, BK=32, 8 warps (warp tile 64x32), 3-stage cp.async.
// Smem rows padded to 80 B (stride 5 mod 8 groups -> ldmatrix conflict-free).
// ---------------------------------------------------------------------------
#define ROWB 80                 // 32 bf16 = 64 B data + 16 B pad
#define MATB (128 * ROWB)       // 10240 B per matrix section
#define STAGEB (4 * MATB)       // Ahi,Alo,Bhi,Blo
#define NSTAGE 3
#define GSMEM (NSTAGE * STAGEB) // 122880 B

__global__ void __launch_bounds__(256) gemm_mma_kernel(
    const __nv_bfloat16* __restrict__ Ahi, const __nv_bfloat16* __restrict__ Alo,
    const __nv_bfloat16* __restrict__ Bhi, const __nv_bfloat16* __restrict__ Blo,
    float* __restrict__ C, int M, int N, int K)
{
    extern __shared__ char smc[];
    const uint32_t sb = smem_to_u32(smc);
    const int tid = threadIdx.x, lane = tid & 31, wid = tid >> 5;
    const int bm = blockIdx.y * 128, bn = blockIdx.x * 128;
    const int m0 = (wid & 1) * 64, n0 = (wid >> 1) * 32;

    float acc[4][4][4];
#pragma unroll
    for (int i = 0; i < 4; i++)
#pragma unroll
        for (int j = 0; j < 4; j++)
#pragma unroll
            for (int c = 0; c < 4; c++) acc[i][j][c] = 0.f;

    // per-thread cp.async mapping: 8 chunks of 16 B per stage
    const __nv_bfloat16* gsrc[8];
    uint32_t sdst[8];
#pragma unroll
    for (int j = 0; j < 8; j++) {
        const int idx = j * 256 + tid;       // 0..2047
        const int mat = idx >> 9;            // 0..3: Ahi,Alo,Bhi,Blo
        const int w = idx & 511;
        const int row = w >> 2, cc = w & 3;
        const __nv_bfloat16* base = (mat == 0) ? Ahi : (mat == 1) ? Alo
                                  : (mat == 2) ? Bhi : Blo;
        const int r = ((mat < 2) ? bm : bn) + row;
        gsrc[j] = base + (size_t)r * K + cc * 8;
        sdst[j] = sb + mat * MATB + row * ROWB + cc * 16;
    }

    const int nk = K >> 5;   // 64

    // prologue: stages 0,1
#pragma unroll
    for (int s = 0; s < 2; s++) {
        const uint32_t so = s * STAGEB;
        const int kc = s * 32;
#pragma unroll
        for (int j = 0; j < 8; j++) cp16(sdst[j] + so, gsrc[j] + kc);
        CP_COMMIT();
    }

    for (int c = 0; c < nk; c++) {
        if (c + 2 < nk) {
            const uint32_t so = ((c + 2) % NSTAGE) * STAGEB;
            const int kc = (c + 2) * 32;
#pragma unroll
            for (int j = 0; j < 8; j++) cp16(sdst[j] + so, gsrc[j] + kc);
        }
        CP_COMMIT();
        asm volatile("cp.async.wait_group 2;");
        __syncthreads();

        const uint32_t st = sb + (c % NSTAGE) * STAGEB;
#pragma unroll
        for (int ks = 0; ks < 2; ks++) {
            const uint32_t kb = ks * 32;    // byte offset of k16 chunk
            uint32_t ah[4][4], al[4][4];
#pragma unroll
            for (int mi = 0; mi < 4; mi++) {
                const uint32_t ra = st + (m0 + mi * 16 + (lane & 15)) * ROWB
                                  + kb + ((lane >> 4) << 4);
                LDM_X4(ah[mi][0], ah[mi][1], ah[mi][2], ah[mi][3], ra);
                LDM_X4(al[mi][0], al[mi][1], al[mi][2], al[mi][3], ra + MATB);
            }
            uint32_t bh0[4], bh1[4], bl0[4], bl1[4];
            {
                const uint32_t rb = st + 2 * MATB + (n0 + lane) * ROWB + kb;
                LDM_X4(bh0[0], bh0[1], bh0[2], bh0[3], rb);
                LDM_X4(bh1[0], bh1[1], bh1[2], bh1[3], rb + 16);
                LDM_X4(bl0[0], bl0[1], bl0[2], bl0[3], rb + MATB);
                LDM_X4(bl1[0], bl1[1], bl1[2], bl1[3], rb + MATB + 16);
            }
#pragma unroll
            for (int mi = 0; mi < 4; mi++)
#pragma unroll
                for (int ni = 0; ni < 4; ni++)
                    mma_bf16(acc[mi][ni], ah[mi], bh0[ni], bh1[ni]);
#pragma unroll
            for (int mi = 0; mi < 4; mi++)
#pragma unroll
                for (int ni = 0; ni < 4; ni++)
                    mma_bf16(acc[mi][ni], ah[mi], bl0[ni], bl1[ni]);
#pragma unroll
            for (int mi = 0; mi < 4; mi++)
#pragma unroll
                for (int ni = 0; ni < 4; ni++)
                    mma_bf16(acc[mi][ni], al[mi], bh0[ni], bh1[ni]);
        }
        __syncthreads();
    }

    // epilogue
#pragma unroll
    for (int mi = 0; mi < 4; mi++) {
        const int r0 = bm + m0 + mi * 16 + (lane >> 2);
#pragma unroll
        for (int ni = 0; ni < 4; ni++) {
            const int c0 = bn + n0 + ni * 8 + (lane & 3) * 2;
            *(float2*)&C[(size_t)r0 * N + c0] =
                make_float2(acc[mi][ni][0], acc[mi][ni][1]);
            *(float2*)&C[(size_t)(r0 + 8) * N + c0] =
                make_float2(acc[mi][ni][2], acc[mi][ni][3]);
        }
    }
}

// ---------------------------------------------------------------------------
// Fused per-head RMSNorm + RoPE, in place on x = [B,S,H,HD].
// ---------------------------------------------------------------------------
__global__ void __launch_bounds__(128) rmsrope_kernel(
    float* __restrict__ x, const float* __restrict__ scale,
    const float* __restrict__ cosb, const float* __restrict__ sinb)
{
    __shared__ float sh[HD];
    __shared__ float red[4];
    const int row = blockIdx.x;
    const int d = threadIdx.x;
    const size_t base = (size_t)row * HD;

    const float v = x[base + d];
    float ssum = v * v;
#pragma unroll
    for (int o = 16; o > 0; o >>= 1) ssum += __shfl_xor_sync(0xffffffffu, ssum, o);
    if ((d & 31) == 0) red[d >> 5] = ssum;
    __syncthreads();
    const float tot = red[0] + red[1] + red[2] + red[3];
    const float r = rsqrtf(tot * (1.f / HD) + EPSV);
    const float xn = scale[d] * v * r;
    sh[d] = xn;
    __syncthreads();
    const float rot = (d < 64) ? -sh[d + 64] : sh[d - 64];
    const size_t cbase = (size_t)(row / HH) * HD;
    x[base + d] = xn * cosb[cbase + d] + rot * sinb[cbase + d];
}

// ---------------------------------------------------------------------------
// Sliding-window flash attention (fp32 FFMA), unchanged.
// ---------------------------------------------------------------------------
#define QPAD 132
#define KPAD 68
#define SPAD 68
#define FLASH_SMEM ((64 * QPAD + 128 * KPAD + 64 * 128 + 64 * SPAD) * 4)

__global__ void __launch_bounds__(256) flash_kernel(
    const float* __restrict__ Qg, const float* __restrict__ Kg,
    const float* __restrict__ Vg, float* __restrict__ Og)
{
    extern __shared__ float smf[];
    float* Qs  = smf;
    float* Kst = Qs + 64 * QPAD;
    float* Vs  = Kst + 128 * KPAD;
    float* Ss  = Vs + 64 * 128;

    const int tid = threadIdx.x;
    const int qb = blockIdx.x, h = blockIdx.y, b = blockIdx.z;
    const int qs0 = qb * 64;
    const int ty = tid >> 4, tx = tid & 15;
    const int rg = tid >> 2, g = tid & 3;
    const int d0 = g * 32;

    for (int i = tid; i < 64 * 32; i += 256) {
        const int r = i >> 5, c = (i & 31) << 2;
        float4 v = *(const float4*)&Qg[(((size_t)b * SS + qs0 + r) * HH + h) * HD + c];
        v.x *= SCALEF; v.y *= SCALEF; v.z *= SCALEF; v.w *= SCALEF;
        *(float4*)&Qs[r * QPAD + c] = v;
    }

    float O[32];
#pragma unroll
    for (int i = 0; i < 32; i++) O[i] = 0.f;
    float m = -1e30f, l = 0.f;

    const int kb_lo = (qs0 >= WIN) ? (qs0 - WIN) / 64 : 0;
    for (int kb = kb_lo; kb <= qb; kb++) {
        __syncthreads();
        for (int i = tid; i < 64 * 32; i += 256) {
            const int r = i & 63, cb = (i >> 6) << 2;
            const float4 kv = *(const float4*)&Kg[(((size_t)b * SS + kb * 64 + r) * HH + h) * HD + cb];
            Kst[(cb + 0) * KPAD + r] = kv.x;
            Kst[(cb + 1) * KPAD + r] = kv.y;
            Kst[(cb + 2) * KPAD + r] = kv.z;
            Kst[(cb + 3) * KPAD + r] = kv.w;
        }
        for (int i = tid; i < 64 * 32; i += 256) {
            const int r = i >> 5, c = (i & 31) << 2;
            *(float4*)&Vs[r * HD + c] =
                *(const float4*)&Vg[(((size_t)b * SS + kb * 64 + r) * HH + h) * HD + c];
        }
        __syncthreads();

        float acc[4][4];
#pragma unroll
        for (int i = 0; i < 4; i++)
#pragma unroll
            for (int j = 0; j < 4; j++) acc[i][j] = 0.f;

        for (int d4 = 0; d4 < 32; d4++) {
            float am[4][4];
#pragma unroll
            for (int i = 0; i < 4; i++) {
                const float4 aq = *(const float4*)&Qs[(ty * 4 + i) * QPAD + d4 * 4];
                am[i][0] = aq.x; am[i][1] = aq.y; am[i][2] = aq.z; am[i][3] = aq.w;
            }
#pragma unroll
            for (int u = 0; u < 4; u++) {
                const float4 bv = *(const float4*)&Kst[(d4 * 4 + u) * KPAD + tx * 4];
#pragma unroll
                for (int i = 0; i < 4; i++) {
                    acc[i][0] += am[i][u] * bv.x;
                    acc[i][1] += am[i][u] * bv.y;
                    acc[i][2] += am[i][u] * bv.z;
                    acc[i][3] += am[i][u] * bv.w;
                }
            }
        }

#pragma unroll
        for (int i = 0; i < 4; i++) {
            const int gi = qs0 + ty * 4 + i;
#pragma unroll
            for (int j = 0; j < 4; j++) {
                const int gj = kb * 64 + tx * 4 + j;
                float s = acc[i][j];
                if (gj > gi || gj < gi - WIN) s = -1e30f;
                Ss[(ty * 4 + i) * SPAD + tx * 4 + j] = s;
            }
        }
        __syncthreads();

        float rmax = -1e30f;
#pragma unroll
        for (int c = g; c < 64; c += 4) rmax = fmaxf(rmax, Ss[rg * SPAD + c]);
        rmax = fmaxf(rmax, __shfl_xor_sync(0xffffffffu, rmax, 1));
        rmax = fmaxf(rmax, __shfl_xor_sync(0xffffffffu, rmax, 2));
        const float mnew = fmaxf(m, rmax);
        const float corr = __expf(m - mnew);
        float lsum = 0.f;
#pragma unroll
        for (int c = g; c < 64; c += 4) {
            const float p = __expf(Ss[rg * SPAD + c] - mnew);
            Ss[rg * SPAD + c] = p;
            lsum += p;
        }
        lsum += __shfl_xor_sync(0xffffffffu, lsum, 1);
        lsum += __shfl_xor_sync(0xffffffffu, lsum, 2);
        l = l * corr + lsum;
        m = mnew;
#pragma unroll
        for (int i = 0; i < 32; i++) O[i] *= corr;
        __syncwarp();

        for (int c = 0; c < 64; c++) {
            const float p = Ss[rg * SPAD + c];
            const float4* vp = (const float4*)&Vs[c * HD + d0];
#pragma unroll
            for (int q4 = 0; q4 < 8; q4++) {
                const float4 v = vp[q4];
                O[q4 * 4 + 0] += p * v.x;
                O[q4 * 4 + 1] += p * v.y;
                O[q4 * 4 + 2] += p * v.z;
                O[q4 * 4 + 3] += p * v.w;
            }
        }
    }

    const float inv = 1.f / l;
    const size_t ob = (((size_t)b * SS + qs0 + rg) * HH + h) * HD + d0;
#pragma unroll
    for (int q4 = 0; q4 < 8; q4++) {
        const float4 v = make_float4(O[q4 * 4 + 0] * inv, O[q4 * 4 + 1] * inv,
                                     O[q4 * 4 + 2] * inv, O[q4 * 4 + 3] * inv);
        *(float4*)&Og[ob + q4 * 4] = v;
    }
}

// ---------------------------------------------------------------------------
extern "C" void kernel_launch(void* const* d_in, const int* in_sizes, int n_in,
                              void* d_out, int out_size)
{
    const float* hidden = (const float*)d_in[0];
    const float* cosb   = (const float*)d_in[1];
    const float* sinb   = (const float*)d_in[2];
    const float* Wq     = (const float*)d_in[3];
    const float* Wk     = (const float*)d_in[4];
    const float* Wv     = (const float*)d_in[5];
    const float* Wo     = (const float*)d_in[6];
    const float* qscale = (const float*)d_in[7];
    const float* kscale = (const float*)d_in[8];
    float* out = (float*)d_out;

    float *gq, *gk, *gv, *ga;
    cudaGetSymbolAddress((void**)&gq, g_q);
    cudaGetSymbolAddress((void**)&gk, g_k);
    cudaGetSymbolAddress((void**)&gv, g_v);
    cudaGetSymbolAddress((void**)&ga, g_attn);

    __nv_bfloat16 *hh, *hl, *ah, *al;
    __nv_bfloat16 *wqh, *wql, *wkh, *wkl, *wvh, *wvl, *woh, *wol;
    cudaGetSymbolAddress((void**)&hh, g_hh);   cudaGetSymbolAddress((void**)&hl, g_hl);
    cudaGetSymbolAddress((void**)&ah, g_ah);   cudaGetSymbolAddress((void**)&al, g_al);
    cudaGetSymbolAddress((void**)&wqh, g_wqh); cudaGetSymbolAddress((void**)&wql, g_wql);
    cudaGetSymbolAddress((void**)&wkh, g_wkh); cudaGetSymbolAddress((void**)&wkl, g_wkl);
    cudaGetSymbolAddress((void**)&wvh, g_wvh); cudaGetSymbolAddress((void**)&wvl, g_wvl);
    cudaGetSymbolAddress((void**)&woh, g_woh); cudaGetSymbolAddress((void**)&wol, g_wol);

    cudaFuncSetAttribute(flash_kernel,
                         cudaFuncAttributeMaxDynamicSharedMemorySize, FLASH_SMEM);
    cudaFuncSetAttribute(gemm_mma_kernel,
                         cudaFuncAttributeMaxDynamicSharedMemorySize, GSMEM);

    const int M = BB * SS;                 // 4096
    const int n4 = M * DD / 4;
    dim3 tgrid(DD / 32, DD / 32);
    dim3 tblk(32, 8);
    dim3 ggrid(DD / 128, M / 128);         // (16, 32)

    // operand prep
    convert_split_kernel<<<(n4 + 255) / 256, 256>>>(hidden, hh, hl, n4);
    transpose_split_kernel<<<tgrid, tblk>>>(Wq, wqh, wql);
    transpose_split_kernel<<<tgrid, tblk>>>(Wk, wkh, wkl);
    transpose_split_kernel<<<tgrid, tblk>>>(Wv, wvh, wvl);
    transpose_split_kernel<<<tgrid, tblk>>>(Wo, woh, wol);

    // QKV projections on tensor cores (HMMA)
    gemm_mma_kernel<<<ggrid, 256, GSMEM>>>(hh, hl, wqh, wql, gq, M, DD, DD);
    gemm_mma_kernel<<<ggrid, 256, GSMEM>>>(hh, hl, wkh, wkl, gk, M, DD, DD);
    gemm_mma_kernel<<<ggrid, 256, GSMEM>>>(hh, hl, wvh, wvl, gv, M, DD, DD);

    rmsrope_kernel<<<M * HH, HD>>>(gq, qscale, cosb, sinb);
    rmsrope_kernel<<<M * HH, HD>>>(gk, kscale, cosb, sinb);

    flash_kernel<<<dim3(SS / 64, HH, BB), 256, FLASH_SMEM>>>(gq, gk, gv, ga);

    // output projection
    convert_split_kernel<<<(n4 + 255) / 256, 256>>>(ga, ah, al, n4);
    gemm_mma_kernel<<<ggrid, 256, GSMEM>>>(ah, al, woh, wol, out, M, DD, DD);
}

// round 5
// speedup vs baseline: 3.1088x; 2.5438x over previous
#include <cuda_runtime.h>
#include <cuda_bf16.h>
#include <math.h>
#include <stdint.h>

#define BB 2
#define SS 2048
#define DD 2048
#define HH 16
#define HD 128
#define WIN 1024
#define EPSV 1e-6f
#define SCALEF 0.08838834764831845f   // 128^-0.5

#define NSC (BB * SS * HH * HD)
__device__ float g_q[NSC];
__device__ float g_k[NSC];
__device__ float g_v[NSC];
__device__ float g_attn[NSC];

// bf16 split operand buffers
__device__ __nv_bfloat16 g_hh[BB * SS * DD];
__device__ __nv_bfloat16 g_hl[BB * SS * DD];
__device__ __nv_bfloat16 g_ah[BB * SS * DD];
__device__ __nv_bfloat16 g_al[BB * SS * DD];
__device__ __nv_bfloat16 g_wqh[DD * DD], g_wql[DD * DD];
__device__ __nv_bfloat16 g_wkh[DD * DD], g_wkl[DD * DD];
__device__ __nv_bfloat16 g_wvh[DD * DD], g_wvl[DD * DD];
__device__ __nv_bfloat16 g_woh[DD * DD], g_wol[DD * DD];

// ---------------------------------------------------------------------------
// helpers (compute_103-safe baseline PTX: mma.sync / ldmatrix / cp.async)
// ---------------------------------------------------------------------------
__device__ __forceinline__ uint32_t smem_to_u32(const void* p) {
    uint32_t a;
    asm("{ .reg .u64 t; cvta.to.shared.u64 t, %1; cvt.u32.u64 %0, t; }"
        : "=r"(a) : "l"(p));
    return a;
}

#define LDM_X4(r0, r1, r2, r3, a) \
    asm volatile("ldmatrix.sync.aligned.m8n8.x4.shared.b16 {%0,%1,%2,%3}, [%4];" \
        : "=r"(r0), "=r"(r1), "=r"(r2), "=r"(r3) : "r"(a))

#define LDM_X4_T(r0, r1, r2, r3, a) \
    asm volatile("ldmatrix.sync.aligned.m8n8.x4.trans.shared.b16 {%0,%1,%2,%3}, [%4];" \
        : "=r"(r0), "=r"(r1), "=r"(r2), "=r"(r3) : "r"(a))

__device__ __forceinline__ void mma_bf16(float* d, const uint32_t* a,
                                         uint32_t b0, uint32_t b1) {
    asm volatile(
        "mma.sync.aligned.m16n8k16.row.col.f32.bf16.bf16.f32 "
        "{%0,%1,%2,%3}, {%4,%5,%6,%7}, {%8,%9}, {%0,%1,%2,%3};"
        : "+f"(d[0]), "+f"(d[1]), "+f"(d[2]), "+f"(d[3])
        : "r"(a[0]), "r"(a[1]), "r"(a[2]), "r"(a[3]), "r"(b0), "r"(b1));
}

__device__ __forceinline__ void cp16(uint32_t dst, const void* src) {
    asm volatile("cp.async.cg.shared.global [%0], [%1], 16;" :: "r"(dst), "l"(src));
}
#define CP_COMMIT() asm volatile("cp.async.commit_group;")

// pack fp32 pair -> bf16x2 (hi) and residual bf16x2 (lo)
__device__ __forceinline__ void split2(float x, float y, uint32_t& hi, uint32_t& lo) {
    __nv_bfloat162 h = __floats2bfloat162_rn(x, y);
    __nv_bfloat162 l = __floats2bfloat162_rn(x - __bfloat162float(h.x),
                                             y - __bfloat162float(h.y));
    hi = *(uint32_t*)&h;
    lo = *(uint32_t*)&l;
}

// ---------------------------------------------------------------------------
// fp32 -> bf16 hi/lo split (elementwise)
// ---------------------------------------------------------------------------
__global__ void __launch_bounds__(256) convert_split_kernel(
    const float* __restrict__ x, __nv_bfloat16* __restrict__ hi,
    __nv_bfloat16* __restrict__ lo, int n4)
{
    int i = blockIdx.x * blockDim.x + threadIdx.x;
    if (i >= n4) return;
    float4 v = ((const float4*)x)[i];
    uint32_t h0, l0, h1, l1;
    split2(v.x, v.y, h0, l0);
    split2(v.z, v.w, h1, l1);
    uint32_t* hp = (uint32_t*)(hi + 4 * (size_t)i);
    uint32_t* lp = (uint32_t*)(lo + 4 * (size_t)i);
    hp[0] = h0; hp[1] = h1;
    lp[0] = l0; lp[1] = l1;
}

// ---------------------------------------------------------------------------
// W[K][N] fp32 -> transposed bf16 hi/lo [N][K]
// ---------------------------------------------------------------------------
__global__ void __launch_bounds__(256) transpose_split_kernel(
    const float* __restrict__ W, __nv_bfloat16* __restrict__ Thi,
    __nv_bfloat16* __restrict__ Tlo)
{
    __shared__ float t[32][33];
    const int k0 = blockIdx.y * 32, n0 = blockIdx.x * 32;
    const int tx = threadIdx.x, ty = threadIdx.y;
#pragma unroll
    for (int r = 0; r < 32; r += 8)
        t[ty + r][tx] = W[(size_t)(k0 + ty + r) * DD + n0 + tx];
    __syncthreads();
#pragma unroll
    for (int r = 0; r < 32; r += 8) {
        const float v = t[tx][ty + r];
        __nv_bfloat16 h = __float2bfloat16(v);
        __nv_bfloat16 l = __float2bfloat16(v - __bfloat162float(h));
        const size_t o = (size_t)(n0 + ty + r) * DD + k0 + tx;
        Thi[o] = h; Tlo[o] = l;
    }
}

// ---------------------------------------------------------------------------
// bf16 split-precision GEMM on HMMA (unchanged from round 4 — passing).
// ---------------------------------------------------------------------------
#define ROWB 80
#define MATB (128 * ROWB)
#define STAGEB (4 * MATB)
#define NSTAGE 3
#define GSMEM (NSTAGE * STAGEB)

__global__ void __launch_bounds__(256) gemm_mma_kernel(
    const __nv_bfloat16* __restrict__ Ahi, const __nv_bfloat16* __restrict__ Alo,
    const __nv_bfloat16* __restrict__ Bhi, const __nv_bfloat16* __restrict__ Blo,
    float* __restrict__ C, int M, int N, int K)
{
    extern __shared__ char smc[];
    const uint32_t sb = smem_to_u32(smc);
    const int tid = threadIdx.x, lane = tid & 31, wid = tid >> 5;
    const int bm = blockIdx.y * 128, bn = blockIdx.x * 128;
    const int m0 = (wid & 1) * 64, n0 = (wid >> 1) * 32;

    float acc[4][4][4];
#pragma unroll
    for (int i = 0; i < 4; i++)
#pragma unroll
        for (int j = 0; j < 4; j++)
#pragma unroll
            for (int c = 0; c < 4; c++) acc[i][j][c] = 0.f;

    const __nv_bfloat16* gsrc[8];
    uint32_t sdst[8];
#pragma unroll
    for (int j = 0; j < 8; j++) {
        const int idx = j * 256 + tid;
        const int mat = idx >> 9;
        const int w = idx & 511;
        const int row = w >> 2, cc = w & 3;
        const __nv_bfloat16* base = (mat == 0) ? Ahi : (mat == 1) ? Alo
                                  : (mat == 2) ? Bhi : Blo;
        const int r = ((mat < 2) ? bm : bn) + row;
        gsrc[j] = base + (size_t)r * K + cc * 8;
        sdst[j] = sb + mat * MATB + row * ROWB + cc * 16;
    }

    const int nk = K >> 5;

#pragma unroll
    for (int s = 0; s < 2; s++) {
        const uint32_t so = s * STAGEB;
        const int kc = s * 32;
#pragma unroll
        for (int j = 0; j < 8; j++) cp16(sdst[j] + so, gsrc[j] + kc);
        CP_COMMIT();
    }

    for (int c = 0; c < nk; c++) {
        if (c + 2 < nk) {
            const uint32_t so = ((c + 2) % NSTAGE) * STAGEB;
            const int kc = (c + 2) * 32;
#pragma unroll
            for (int j = 0; j < 8; j++) cp16(sdst[j] + so, gsrc[j] + kc);
        }
        CP_COMMIT();
        asm volatile("cp.async.wait_group 2;");
        __syncthreads();

        const uint32_t st = sb + (c % NSTAGE) * STAGEB;
#pragma unroll
        for (int ks = 0; ks < 2; ks++) {
            const uint32_t kb = ks * 32;
            uint32_t ah[4][4], al[4][4];
#pragma unroll
            for (int mi = 0; mi < 4; mi++) {
                const uint32_t ra = st + (m0 + mi * 16 + (lane & 15)) * ROWB
                                  + kb + ((lane >> 4) << 4);
                LDM_X4(ah[mi][0], ah[mi][1], ah[mi][2], ah[mi][3], ra);
                LDM_X4(al[mi][0], al[mi][1], al[mi][2], al[mi][3], ra + MATB);
            }
            uint32_t bh0[4], bh1[4], bl0[4], bl1[4];
            {
                const uint32_t rb = st + 2 * MATB + (n0 + lane) * ROWB + kb;
                LDM_X4(bh0[0], bh0[1], bh0[2], bh0[3], rb);
                LDM_X4(bh1[0], bh1[1], bh1[2], bh1[3], rb + 16);
                LDM_X4(bl0[0], bl0[1], bl0[2], bl0[3], rb + MATB);
                LDM_X4(bl1[0], bl1[1], bl1[2], bl1[3], rb + MATB + 16);
            }
#pragma unroll
            for (int mi = 0; mi < 4; mi++)
#pragma unroll
                for (int ni = 0; ni < 4; ni++)
                    mma_bf16(acc[mi][ni], ah[mi], bh0[ni], bh1[ni]);
#pragma unroll
            for (int mi = 0; mi < 4; mi++)
#pragma unroll
                for (int ni = 0; ni < 4; ni++)
                    mma_bf16(acc[mi][ni], ah[mi], bl0[ni], bl1[ni]);
#pragma unroll
            for (int mi = 0; mi < 4; mi++)
#pragma unroll
                for (int ni = 0; ni < 4; ni++)
                    mma_bf16(acc[mi][ni], al[mi], bh0[ni], bh1[ni]);
        }
        __syncthreads();
    }

#pragma unroll
    for (int mi = 0; mi < 4; mi++) {
        const int r0 = bm + m0 + mi * 16 + (lane >> 2);
#pragma unroll
        for (int ni = 0; ni < 4; ni++) {
            const int c0 = bn + n0 + ni * 8 + (lane & 3) * 2;
            *(float2*)&C[(size_t)r0 * N + c0] =
                make_float2(acc[mi][ni][0], acc[mi][ni][1]);
            *(float2*)&C[(size_t)(r0 + 8) * N + c0] =
                make_float2(acc[mi][ni][2], acc[mi][ni][3]);
        }
    }
}

// ---------------------------------------------------------------------------
// Fused per-head RMSNorm + RoPE (unchanged).
// ---------------------------------------------------------------------------
__global__ void __launch_bounds__(128) rmsrope_kernel(
    float* __restrict__ x, const float* __restrict__ scale,
    const float* __restrict__ cosb, const float* __restrict__ sinb)
{
    __shared__ float sh[HD];
    __shared__ float red[4];
    const int row = blockIdx.x;
    const int d = threadIdx.x;
    const size_t base = (size_t)row * HD;

    const float v = x[base + d];
    float ssum = v * v;
#pragma unroll
    for (int o = 16; o > 0; o >>= 1) ssum += __shfl_xor_sync(0xffffffffu, ssum, o);
    if ((d & 31) == 0) red[d >> 5] = ssum;
    __syncthreads();
    const float tot = red[0] + red[1] + red[2] + red[3];
    const float r = rsqrtf(tot * (1.f / HD) + EPSV);
    const float xn = scale[d] * v * r;
    sh[d] = xn;
    __syncthreads();
    const float rot = (d < 64) ? -sh[d + 64] : sh[d - 64];
    const size_t cbase = (size_t)(row / HH) * HD;
    x[base + d] = xn * cosb[cbase + d] + rot * sinb[cbase + d];
}

// ---------------------------------------------------------------------------
// HMMA sliding-window flash attention with bf16 hi/lo split.
// Block: 256 threads (8 warps), q-tile 128 (16 rows/warp), k-tile 64.
// S = Qh*Kh + Qh*Kl + Ql*Kh ; O = Ph*Vh + Ph*Vl + Pl*Vh (fp32 accum).
// Smem: bf16 tiles with 272-byte rows (conflict-free ldmatrix).
// ---------------------------------------------------------------------------
#define FQ 128
#define FKT 64
#define QROWB 272
#define FSM_QH 0
#define FSM_QL (FQ * QROWB)              // 34816
#define FSM_KH (2 * FQ * QROWB)          // 69632
#define FSM_KL (FSM_KH + FKT * QROWB)
#define FSM_VH (FSM_KH + 2 * FKT * QROWB)
#define FSM_VL (FSM_KH + 3 * FKT * QROWB)
#define FLASH2_SMEM (FSM_KH + 4 * FKT * QROWB)   // 139264

__global__ void __launch_bounds__(256) flash_hmma_kernel(
    const float* __restrict__ Qg, const float* __restrict__ Kg,
    const float* __restrict__ Vg, float* __restrict__ Og)
{
    extern __shared__ char sm[];
    const uint32_t sb = smem_to_u32(sm);
    const int tid = threadIdx.x, lane = tid & 31, wid = tid >> 5;
    const int qb = blockIdx.x, h = blockIdx.y, b = blockIdx.z;
    const int qs0 = qb * FQ;
    const int mr = wid * 16;

    // load Q tile: fp32 -> scaled -> bf16 hi/lo
    for (int i = tid; i < FQ * 32; i += 256) {
        const int r = i >> 5, c = i & 31;
        float4 q = *(const float4*)&Qg[(((size_t)b * SS + qs0 + r) * HH + h) * HD + c * 4];
        q.x *= SCALEF; q.y *= SCALEF; q.z *= SCALEF; q.w *= SCALEF;
        uint32_t h0, l0, h1, l1;
        split2(q.x, q.y, h0, l0);
        split2(q.z, q.w, h1, l1);
        char* ph = sm + FSM_QH + r * QROWB + c * 8;
        char* pl = sm + FSM_QL + r * QROWB + c * 8;
        *(uint2*)ph = make_uint2(h0, h1);
        *(uint2*)pl = make_uint2(l0, l1);
    }

    float oacc[16][4];
#pragma unroll
    for (int j = 0; j < 16; j++)
#pragma unroll
        for (int c = 0; c < 4; c++) oacc[j][c] = 0.f;
    float m0 = 0.f, m1 = 0.f, l0s = 0.f, l1s = 0.f;   // m init 0: masked->exp(-1e30)=0

    // ldmatrix address components
    const uint32_t g8 = (lane >> 3) & 1, g16 = (lane >> 4) & 1, l7 = lane & 7;
    const uint32_t a_addr0 = sb + FSM_QH + (mr + g8 * 8 + l7) * QROWB + g16 * 16;

    const int kb_lo = (qs0 >= WIN) ? (qs0 - WIN) / 64 : 0;
    const int kb_hi = (qs0 + FQ - 1) / 64;

    for (int kb = kb_lo; kb <= kb_hi; kb++) {
        __syncthreads();
        // load K,V tile: fp32 -> bf16 hi/lo
        for (int i = tid; i < FKT * 32; i += 256) {
            const int r = i >> 5, c = i & 31;
            const size_t gsrc = (((size_t)b * SS + kb * 64 + r) * HH + h) * HD + c * 4;
            float4 kv = *(const float4*)&Kg[gsrc];
            float4 vv = *(const float4*)&Vg[gsrc];
            uint32_t h0, l0, h1, l1;
            split2(kv.x, kv.y, h0, l0);
            split2(kv.z, kv.w, h1, l1);
            *(uint2*)(sm + FSM_KH + r * QROWB + c * 8) = make_uint2(h0, h1);
            *(uint2*)(sm + FSM_KL + r * QROWB + c * 8) = make_uint2(l0, l1);
            split2(vv.x, vv.y, h0, l0);
            split2(vv.z, vv.w, h1, l1);
            *(uint2*)(sm + FSM_VH + r * QROWB + c * 8) = make_uint2(h0, h1);
            *(uint2*)(sm + FSM_VL + r * QROWB + c * 8) = make_uint2(l0, l1);
        }
        __syncthreads();

        // ---- S = Q @ K^T ----
        float sacc[8][4];
#pragma unroll
        for (int j = 0; j < 8; j++)
#pragma unroll
            for (int c = 0; c < 4; c++) sacc[j][c] = 0.f;

#pragma unroll
        for (int kt = 0; kt < 8; kt++) {
            uint32_t ah[4], al[4];
            const uint32_t aa = a_addr0 + kt * 32;
            LDM_X4(ah[0], ah[1], ah[2], ah[3], aa);
            LDM_X4(al[0], al[1], al[2], al[3], aa + (FSM_QL - FSM_QH));
#pragma unroll
            for (int nt = 0; nt < 4; nt++) {
                const uint32_t ba = sb + FSM_KH
                    + (nt * 16 + g16 * 8 + l7) * QROWB + kt * 32 + g8 * 16;
                uint32_t bh[4], bl[4];
                LDM_X4(bh[0], bh[1], bh[2], bh[3], ba);
                LDM_X4(bl[0], bl[1], bl[2], bl[3], ba + (FSM_KL - FSM_KH));
                mma_bf16(sacc[2 * nt],     ah, bh[0], bh[1]);
                mma_bf16(sacc[2 * nt + 1], ah, bh[2], bh[3]);
                mma_bf16(sacc[2 * nt],     ah, bl[0], bl[1]);
                mma_bf16(sacc[2 * nt + 1], ah, bl[2], bl[3]);
                mma_bf16(sacc[2 * nt],     al, bh[0], bh[1]);
                mma_bf16(sacc[2 * nt + 1], al, bh[2], bh[3]);
            }
        }

        // ---- mask ----
        const int gi0 = qs0 + mr + (lane >> 2);
        const int gi1 = gi0 + 8;
        const bool interior = (kb * 64 + 63 <= qs0) && (kb * 64 >= qs0 + FQ - 1 - WIN);
        if (!interior) {
#pragma unroll
            for (int j = 0; j < 8; j++) {
                const int gj = kb * 64 + j * 8 + (lane & 3) * 2;
                if (gj > gi0 || gj < gi0 - WIN)         sacc[j][0] = -1e30f;
                if (gj + 1 > gi0 || gj + 1 < gi0 - WIN) sacc[j][1] = -1e30f;
                if (gj > gi1 || gj < gi1 - WIN)         sacc[j][2] = -1e30f;
                if (gj + 1 > gi1 || gj + 1 < gi1 - WIN) sacc[j][3] = -1e30f;
            }
        }

        // ---- online softmax ----
        float rmax0 = -1e30f, rmax1 = -1e30f;
#pragma unroll
        for (int j = 0; j < 8; j++) {
            rmax0 = fmaxf(rmax0, fmaxf(sacc[j][0], sacc[j][1]));
            rmax1 = fmaxf(rmax1, fmaxf(sacc[j][2], sacc[j][3]));
        }
        rmax0 = fmaxf(rmax0, __shfl_xor_sync(0xffffffffu, rmax0, 1));
        rmax0 = fmaxf(rmax0, __shfl_xor_sync(0xffffffffu, rmax0, 2));
        rmax1 = fmaxf(rmax1, __shfl_xor_sync(0xffffffffu, rmax1, 1));
        rmax1 = fmaxf(rmax1, __shfl_xor_sync(0xffffffffu, rmax1, 2));
        const float m0n = fmaxf(m0, rmax0), m1n = fmaxf(m1, rmax1);
        const float c0 = __expf(m0 - m0n), c1 = __expf(m1 - m1n);

        uint32_t pah[4][4], pal[4][4];
        float ls0 = 0.f, ls1 = 0.f;
#pragma unroll
        for (int t = 0; t < 4; t++) {
#pragma unroll
            for (int q = 0; q < 2; q++) {
                const int j = 2 * t + q;
                const float p0 = __expf(sacc[j][0] - m0n);
                const float p1 = __expf(sacc[j][1] - m0n);
                const float p2 = __expf(sacc[j][2] - m1n);
                const float p3 = __expf(sacc[j][3] - m1n);
                ls0 += p0 + p1; ls1 += p2 + p3;
                split2(p0, p1, pah[t][2 * q],     pal[t][2 * q]);
                split2(p2, p3, pah[t][2 * q + 1], pal[t][2 * q + 1]);
            }
        }
        ls0 += __shfl_xor_sync(0xffffffffu, ls0, 1);
        ls0 += __shfl_xor_sync(0xffffffffu, ls0, 2);
        ls1 += __shfl_xor_sync(0xffffffffu, ls1, 1);
        ls1 += __shfl_xor_sync(0xffffffffu, ls1, 2);
        l0s = l0s * c0 + ls0;
        l1s = l1s * c1 + ls1;
        m0 = m0n; m1 = m1n;
#pragma unroll
        for (int j = 0; j < 16; j++) {
            oacc[j][0] *= c0; oacc[j][1] *= c0;
            oacc[j][2] *= c1; oacc[j][3] *= c1;
        }

        // ---- O += P @ V ----
#pragma unroll
        for (int t = 0; t < 4; t++) {
#pragma unroll
            for (int dn = 0; dn < 8; dn++) {
                const uint32_t va = sb + FSM_VH
                    + (t * 16 + g8 * 8 + l7) * QROWB + dn * 32 + g16 * 16;
                uint32_t vh[4], vl[4];
                LDM_X4_T(vh[0], vh[1], vh[2], vh[3], va);
                LDM_X4_T(vl[0], vl[1], vl[2], vl[3], va + (FSM_VL - FSM_VH));
                mma_bf16(oacc[2 * dn],     pah[t], vh[0], vh[1]);
                mma_bf16(oacc[2 * dn + 1], pah[t], vh[2], vh[3]);
                mma_bf16(oacc[2 * dn],     pah[t], vl[0], vl[1]);
                mma_bf16(oacc[2 * dn + 1], pah[t], vl[2], vl[3]);
                mma_bf16(oacc[2 * dn],     pal[t], vh[0], vh[1]);
                mma_bf16(oacc[2 * dn + 1], pal[t], vh[2], vh[3]);
            }
        }
    }

    // ---- epilogue ----
    const float inv0 = 1.f / l0s, inv1 = 1.f / l1s;
    const int r0 = qs0 + mr + (lane >> 2);
    const size_t ob0 = (((size_t)b * SS + r0) * HH + h) * HD;
    const size_t ob1 = (((size_t)b * SS + r0 + 8) * HH + h) * HD;
#pragma unroll
    for (int j = 0; j < 16; j++) {
        const int col = j * 8 + (lane & 3) * 2;
        *(float2*)&Og[ob0 + col] = make_float2(oacc[j][0] * inv0, oacc[j][1] * inv0);
        *(float2*)&Og[ob1 + col] = make_float2(oacc[j][2] * inv1, oacc[j][3] * inv1);
    }
}

// ---------------------------------------------------------------------------
extern "C" void kernel_launch(void* const* d_in, const int* in_sizes, int n_in,
                              void* d_out, int out_size)
{
    const float* hidden = (const float*)d_in[0];
    const float* cosb   = (const float*)d_in[1];
    const float* sinb   = (const float*)d_in[2];
    const float* Wq     = (const float*)d_in[3];
    const float* Wk     = (const float*)d_in[4];
    const float* Wv     = (const float*)d_in[5];
    const float* Wo     = (const float*)d_in[6];
    const float* qscale = (const float*)d_in[7];
    const float* kscale = (const float*)d_in[8];
    float* out = (float*)d_out;

    float *gq, *gk, *gv, *ga;
    cudaGetSymbolAddress((void**)&gq, g_q);
    cudaGetSymbolAddress((void**)&gk, g_k);
    cudaGetSymbolAddress((void**)&gv, g_v);
    cudaGetSymbolAddress((void**)&ga, g_attn);

    __nv_bfloat16 *hh, *hl, *ah, *al;
    __nv_bfloat16 *wqh, *wql, *wkh, *wkl, *wvh, *wvl, *woh, *wol;
    cudaGetSymbolAddress((void**)&hh, g_hh);   cudaGetSymbolAddress((void**)&hl, g_hl);
    cudaGetSymbolAddress((void**)&ah, g_ah);   cudaGetSymbolAddress((void**)&al, g_al);
    cudaGetSymbolAddress((void**)&wqh, g_wqh); cudaGetSymbolAddress((void**)&wql, g_wql);
    cudaGetSymbolAddress((void**)&wkh, g_wkh); cudaGetSymbolAddress((void**)&wkl, g_wkl);
    cudaGetSymbolAddress((void**)&wvh, g_wvh); cudaGetSymbolAddress((void**)&wvl, g_wvl);
    cudaGetSymbolAddress((void**)&woh, g_woh); cudaGetSymbolAddress((void**)&wol, g_wol);

    cudaFuncSetAttribute(flash_hmma_kernel,
                         cudaFuncAttributeMaxDynamicSharedMemorySize, FLASH2_SMEM);
    cudaFuncSetAttribute(gemm_mma_kernel,
                         cudaFuncAttributeMaxDynamicSharedMemorySize, GSMEM);

    const int M = BB * SS;                 // 4096
    const int n4 = M * DD / 4;
    dim3 tgrid(DD / 32, DD / 32);
    dim3 tblk(32, 8);
    dim3 ggrid(DD / 128, M / 128);         // (16, 32)

    convert_split_kernel<<<(n4 + 255) / 256, 256>>>(hidden, hh, hl, n4);
    transpose_split_kernel<<<tgrid, tblk>>>(Wq, wqh, wql);
    transpose_split_kernel<<<tgrid, tblk>>>(Wk, wkh, wkl);
    transpose_split_kernel<<<tgrid, tblk>>>(Wv, wvh, wvl);
    transpose_split_kernel<<<tgrid, tblk>>>(Wo, woh, wol);

    gemm_mma_kernel<<<ggrid, 256, GSMEM>>>(hh, hl, wqh, wql, gq, M, DD, DD);
    gemm_mma_kernel<<<ggrid, 256, GSMEM>>>(hh, hl, wkh, wkl, gk, M, DD, DD);
    gemm_mma_kernel<<<ggrid, 256, GSMEM>>>(hh, hl, wvh, wvl, gv, M, DD, DD);

    rmsrope_kernel<<<M * HH, HD>>>(gq, qscale, cosb, sinb);
    rmsrope_kernel<<<M * HH, HD>>>(gk, kscale, cosb, sinb);

    flash_hmma_kernel<<<dim3(SS / FQ, HH, BB), 256, FLASH2_SMEM>>>(gq, gk, gv, ga);

    convert_split_kernel<<<(n4 + 255) / 256, 256>>>(ga, ah, al, n4);
    gemm_mma_kernel<<<ggrid, 256, GSMEM>>>(ah, al, woh, wol, out, M, DD, DD);
}

// round 6
// speedup vs baseline: 3.3962x; 1.0925x over previous
#include <cuda_runtime.h>
#include <cuda_bf16.h>
#include <math.h>
#include <stdint.h>

#define BB 2
#define SS 2048
#define DD 2048
#define HH 16
#define HD 128
#define WIN 1024
#define EPSV 1e-6f
#define SCALEF 0.08838834764831845f   // 128^-0.5

#define NSC (BB * SS * HH * HD)
__device__ float g_q[NSC];
__device__ float g_k[NSC];
__device__ float g_v[NSC];
__device__ float g_attn[NSC];

// bf16 split operand buffers
__device__ __nv_bfloat16 g_hh[BB * SS * DD];
__device__ __nv_bfloat16 g_hl[BB * SS * DD];
__device__ __nv_bfloat16 g_ah[BB * SS * DD];
__device__ __nv_bfloat16 g_al[BB * SS * DD];
__device__ __nv_bfloat16 g_wqh[DD * DD], g_wql[DD * DD];
__device__ __nv_bfloat16 g_wkh[DD * DD], g_wkl[DD * DD];
__device__ __nv_bfloat16 g_wvh[DD * DD], g_wvl[DD * DD];
__device__ __nv_bfloat16 g_woh[DD * DD], g_wol[DD * DD];

// ---------------------------------------------------------------------------
// helpers (compute_103-safe baseline PTX: mma.sync / ldmatrix / cp.async)
// ---------------------------------------------------------------------------
__device__ __forceinline__ uint32_t smem_to_u32(const void* p) {
    uint32_t a;
    asm("{ .reg .u64 t; cvta.to.shared.u64 t, %1; cvt.u32.u64 %0, t; }"
        : "=r"(a) : "l"(p));
    return a;
}

#define LDM_X4(r0, r1, r2, r3, a) \
    asm volatile("ldmatrix.sync.aligned.m8n8.x4.shared.b16 {%0,%1,%2,%3}, [%4];" \
        : "=r"(r0), "=r"(r1), "=r"(r2), "=r"(r3) : "r"(a))

#define LDM_X4_T(r0, r1, r2, r3, a) \
    asm volatile("ldmatrix.sync.aligned.m8n8.x4.trans.shared.b16 {%0,%1,%2,%3}, [%4];" \
        : "=r"(r0), "=r"(r1), "=r"(r2), "=r"(r3) : "r"(a))

__device__ __forceinline__ void mma_bf16(float* d, const uint32_t* a,
                                         uint32_t b0, uint32_t b1) {
    asm volatile(
        "mma.sync.aligned.m16n8k16.row.col.f32.bf16.bf16.f32 "
        "{%0,%1,%2,%3}, {%4,%5,%6,%7}, {%8,%9}, {%0,%1,%2,%3};"
        : "+f"(d[0]), "+f"(d[1]), "+f"(d[2]), "+f"(d[3])
        : "r"(a[0]), "r"(a[1]), "r"(a[2]), "r"(a[3]), "r"(b0), "r"(b1));
}

__device__ __forceinline__ void cp16(uint32_t dst, const void* src) {
    asm volatile("cp.async.cg.shared.global [%0], [%1], 16;" :: "r"(dst), "l"(src));
}
#define CP_COMMIT() asm volatile("cp.async.commit_group;")

__device__ __forceinline__ void split2(float x, float y, uint32_t& hi, uint32_t& lo) {
    __nv_bfloat162 h = __floats2bfloat162_rn(x, y);
    __nv_bfloat162 l = __floats2bfloat162_rn(x - __bfloat162float(h.x),
                                             y - __bfloat162float(h.y));
    hi = *(uint32_t*)&h;
    lo = *(uint32_t*)&l;
}

// ---------------------------------------------------------------------------
// fp32 -> bf16 hi/lo split (elementwise)
// ---------------------------------------------------------------------------
__global__ void __launch_bounds__(256) convert_split_kernel(
    const float* __restrict__ x, __nv_bfloat16* __restrict__ hi,
    __nv_bfloat16* __restrict__ lo, int n4)
{
    int i = blockIdx.x * blockDim.x + threadIdx.x;
    if (i >= n4) return;
    float4 v = ((const float4*)x)[i];
    uint32_t h0, l0, h1, l1;
    split2(v.x, v.y, h0, l0);
    split2(v.z, v.w, h1, l1);
    uint32_t* hp = (uint32_t*)(hi + 4 * (size_t)i);
    uint32_t* lp = (uint32_t*)(lo + 4 * (size_t)i);
    hp[0] = h0; hp[1] = h1;
    lp[0] = l0; lp[1] = l1;
}

// ---------------------------------------------------------------------------
// W[K][N] fp32 -> transposed bf16 hi/lo [N][K]
// ---------------------------------------------------------------------------
__global__ void __launch_bounds__(256) transpose_split_kernel(
    const float* __restrict__ W, __nv_bfloat16* __restrict__ Thi,
    __nv_bfloat16* __restrict__ Tlo)
{
    __shared__ float t[32][33];
    const int k0 = blockIdx.y * 32, n0 = blockIdx.x * 32;
    const int tx = threadIdx.x, ty = threadIdx.y;
#pragma unroll
    for (int r = 0; r < 32; r += 8)
        t[ty + r][tx] = W[(size_t)(k0 + ty + r) * DD + n0 + tx];
    __syncthreads();
#pragma unroll
    for (int r = 0; r < 32; r += 8) {
        const float v = t[tx][ty + r];
        __nv_bfloat16 h = __float2bfloat16(v);
        __nv_bfloat16 l = __float2bfloat16(v - __bfloat162float(h));
        const size_t o = (size_t)(n0 + ty + r) * DD + k0 + tx;
        Thi[o] = h; Tlo[o] = l;
    }
}

// ---------------------------------------------------------------------------
// Fused bf16 split-precision GEMM on HMMA, up to 3 weight matrices sharing A.
//   C_z[M,N] = A[M,K] @ W_z[K,N] ; W pre-transposed [N][K] hi/lo.
// CTA tile 256x128, BK=32, 512 threads (16 warps, warp tile 64x32),
// 3-stage cp.async pipeline. z selects (B, C).
// ---------------------------------------------------------------------------
#define GBM 256
#define GBN 128
#define ROWB 80                       // 32 bf16 = 64 B + 16 B pad
#define AHI_OFF 0
#define ALO_OFF (GBM * ROWB)          // 20480
#define BHI_OFF (2 * GBM * ROWB)      // 40960
#define BLO_OFF (BHI_OFF + GBN * ROWB)
#define STAGEB (BHI_OFF + 2 * GBN * ROWB)   // 61440
#define NSTAGE 3
#define GSMEM (NSTAGE * STAGEB)       // 184320

__global__ void __launch_bounds__(512) gemm_mma_kernel(
    const __nv_bfloat16* __restrict__ Ahi, const __nv_bfloat16* __restrict__ Alo,
    const __nv_bfloat16* __restrict__ B0h, const __nv_bfloat16* __restrict__ B0l,
    float* __restrict__ C0,
    const __nv_bfloat16* __restrict__ B1h, const __nv_bfloat16* __restrict__ B1l,
    float* __restrict__ C1,
    const __nv_bfloat16* __restrict__ B2h, const __nv_bfloat16* __restrict__ B2l,
    float* __restrict__ C2,
    int M, int N, int K)
{
    extern __shared__ char smc[];
    const uint32_t sb = smem_to_u32(smc);
    const int tid = threadIdx.x, lane = tid & 31, wid = tid >> 5;
    const int bm = blockIdx.y * GBM, bn = blockIdx.x * GBN;
    const int z = blockIdx.z;
    const __nv_bfloat16* Bhi = (z == 0) ? B0h : (z == 1) ? B1h : B2h;
    const __nv_bfloat16* Blo = (z == 0) ? B0l : (z == 1) ? B1l : B2l;
    float* C = (z == 0) ? C0 : (z == 1) ? C1 : C2;

    const int m0 = (wid & 3) * 64, n0 = (wid >> 2) * 32;

    float acc[4][4][4];
#pragma unroll
    for (int i = 0; i < 4; i++)
#pragma unroll
        for (int j = 0; j < 4; j++)
#pragma unroll
            for (int c = 0; c < 4; c++) acc[i][j][c] = 0.f;

    // cp.async mapping: 3072 16B data chunks / 512 threads = 6 per thread
    const __nv_bfloat16* gsrc[6];
    uint32_t sdst[6];
#pragma unroll
    for (int j = 0; j < 6; j++) {
        const int idx = j * 512 + tid;
        int mat, row;
        if (idx < 1024)      { mat = 0; row = idx >> 2; }
        else if (idx < 2048) { mat = 1; row = (idx - 1024) >> 2; }
        else if (idx < 2560) { mat = 2; row = (idx - 2048) >> 2; }
        else                 { mat = 3; row = (idx - 2560) >> 2; }
        const int cc = idx & 3;
        const __nv_bfloat16* base = (mat == 0) ? Ahi : (mat == 1) ? Alo
                                  : (mat == 2) ? Bhi : Blo;
        const int r = ((mat < 2) ? bm : bn) + row;
        const uint32_t moff = (mat == 0) ? AHI_OFF : (mat == 1) ? ALO_OFF
                            : (mat == 2) ? BHI_OFF : BLO_OFF;
        gsrc[j] = base + (size_t)r * K + cc * 8;
        sdst[j] = sb + moff + row * ROWB + cc * 16;
    }

    const int nk = K >> 5;   // 64

#pragma unroll
    for (int s = 0; s < 2; s++) {
        const uint32_t so = s * STAGEB;
        const int kc = s * 32;
#pragma unroll
        for (int j = 0; j < 6; j++) cp16(sdst[j] + so, gsrc[j] + kc);
        CP_COMMIT();
    }

    for (int c = 0; c < nk; c++) {
        if (c + 2 < nk) {
            const uint32_t so = ((c + 2) % NSTAGE) * STAGEB;
            const int kc = (c + 2) * 32;
#pragma unroll
            for (int j = 0; j < 6; j++) cp16(sdst[j] + so, gsrc[j] + kc);
        }
        CP_COMMIT();
        asm volatile("cp.async.wait_group 2;");
        __syncthreads();

        const uint32_t st = sb + (c % NSTAGE) * STAGEB;
#pragma unroll
        for (int ks = 0; ks < 2; ks++) {
            const uint32_t kb = ks * 32;
            // B fragments for this k16 (16 regs), reused across all mi
            uint32_t bh0[4], bh1[4], bl0[4], bl1[4];
            {
                const uint32_t rb = st + BHI_OFF + (n0 + lane) * ROWB + kb;
                LDM_X4(bh0[0], bh0[1], bh0[2], bh0[3], rb);
                LDM_X4(bh1[0], bh1[1], bh1[2], bh1[3], rb + 16);
                LDM_X4(bl0[0], bl0[1], bl0[2], bl0[3], rb + (BLO_OFF - BHI_OFF));
                LDM_X4(bl1[0], bl1[1], bl1[2], bl1[3], rb + (BLO_OFF - BHI_OFF) + 16);
            }
#pragma unroll
            for (int mi = 0; mi < 4; mi++) {
                uint32_t ah[4], al[4];
                const uint32_t ra = st + AHI_OFF
                    + (m0 + mi * 16 + (lane & 15)) * ROWB + kb + ((lane >> 4) << 4);
                LDM_X4(ah[0], ah[1], ah[2], ah[3], ra);
                LDM_X4(al[0], al[1], al[2], al[3], ra + (ALO_OFF - AHI_OFF));
#pragma unroll
                for (int ni = 0; ni < 4; ni++) {
                    mma_bf16(acc[mi][ni], ah, bh0[ni], bh1[ni]);
                    mma_bf16(acc[mi][ni], ah, bl0[ni], bl1[ni]);
                    mma_bf16(acc[mi][ni], al, bh0[ni], bh1[ni]);
                }
            }
        }
        __syncthreads();
    }

#pragma unroll
    for (int mi = 0; mi < 4; mi++) {
        const int r0 = bm + m0 + mi * 16 + (lane >> 2);
#pragma unroll
        for (int ni = 0; ni < 4; ni++) {
            const int c0 = bn + n0 + ni * 8 + (lane & 3) * 2;
            *(float2*)&C[(size_t)r0 * N + c0] =
                make_float2(acc[mi][ni][0], acc[mi][ni][1]);
            *(float2*)&C[(size_t)(r0 + 8) * N + c0] =
                make_float2(acc[mi][ni][2], acc[mi][ni][3]);
        }
    }
}

// ---------------------------------------------------------------------------
// Fused per-head RMSNorm + RoPE (unchanged).
// ---------------------------------------------------------------------------
__global__ void __launch_bounds__(128) rmsrope_kernel(
    float* __restrict__ x, const float* __restrict__ scale,
    const float* __restrict__ cosb, const float* __restrict__ sinb)
{
    __shared__ float sh[HD];
    __shared__ float red[4];
    const int row = blockIdx.x;
    const int d = threadIdx.x;
    const size_t base = (size_t)row * HD;

    const float v = x[base + d];
    float ssum = v * v;
#pragma unroll
    for (int o = 16; o > 0; o >>= 1) ssum += __shfl_xor_sync(0xffffffffu, ssum, o);
    if ((d & 31) == 0) red[d >> 5] = ssum;
    __syncthreads();
    const float tot = red[0] + red[1] + red[2] + red[3];
    const float r = rsqrtf(tot * (1.f / HD) + EPSV);
    const float xn = scale[d] * v * r;
    sh[d] = xn;
    __syncthreads();
    const float rot = (d < 64) ? -sh[d + 64] : sh[d - 64];
    const size_t cbase = (size_t)(row / HH) * HD;
    x[base + d] = xn * cosb[cbase + d] + rot * sinb[cbase + d];
}

// ---------------------------------------------------------------------------
// HMMA sliding-window flash attention with bf16 hi/lo split (unchanged).
// ---------------------------------------------------------------------------
#define FQ 128
#define FKT 64
#define QROWB 272
#define FSM_QH 0
#define FSM_QL (FQ * QROWB)
#define FSM_KH (2 * FQ * QROWB)
#define FSM_KL (FSM_KH + FKT * QROWB)
#define FSM_VH (FSM_KH + 2 * FKT * QROWB)
#define FSM_VL (FSM_KH + 3 * FKT * QROWB)
#define FLASH2_SMEM (FSM_KH + 4 * FKT * QROWB)

__global__ void __launch_bounds__(256) flash_hmma_kernel(
    const float* __restrict__ Qg, const float* __restrict__ Kg,
    const float* __restrict__ Vg, float* __restrict__ Og)
{
    extern __shared__ char sm[];
    const uint32_t sb = smem_to_u32(sm);
    const int tid = threadIdx.x, lane = tid & 31, wid = tid >> 5;
    const int qb = blockIdx.x, h = blockIdx.y, b = blockIdx.z;
    const int qs0 = qb * FQ;
    const int mr = wid * 16;

    for (int i = tid; i < FQ * 32; i += 256) {
        const int r = i >> 5, c = i & 31;
        float4 q = *(const float4*)&Qg[(((size_t)b * SS + qs0 + r) * HH + h) * HD + c * 4];
        q.x *= SCALEF; q.y *= SCALEF; q.z *= SCALEF; q.w *= SCALEF;
        uint32_t h0, l0, h1, l1;
        split2(q.x, q.y, h0, l0);
        split2(q.z, q.w, h1, l1);
        *(uint2*)(sm + FSM_QH + r * QROWB + c * 8) = make_uint2(h0, h1);
        *(uint2*)(sm + FSM_QL + r * QROWB + c * 8) = make_uint2(l0, l1);
    }

    float oacc[16][4];
#pragma unroll
    for (int j = 0; j < 16; j++)
#pragma unroll
        for (int c = 0; c < 4; c++) oacc[j][c] = 0.f;
    float m0 = 0.f, m1 = 0.f, l0s = 0.f, l1s = 0.f;

    const uint32_t g8 = (lane >> 3) & 1, g16 = (lane >> 4) & 1, l7 = lane & 7;
    const uint32_t a_addr0 = sb + FSM_QH + (mr + g8 * 8 + l7) * QROWB + g16 * 16;

    const int kb_lo = (qs0 >= WIN) ? (qs0 - WIN) / 64 : 0;
    const int kb_hi = (qs0 + FQ - 1) / 64;

    for (int kb = kb_lo; kb <= kb_hi; kb++) {
        __syncthreads();
        for (int i = tid; i < FKT * 32; i += 256) {
            const int r = i >> 5, c = i & 31;
            const size_t gsrc = (((size_t)b * SS + kb * 64 + r) * HH + h) * HD + c * 4;
            float4 kv = *(const float4*)&Kg[gsrc];
            float4 vv = *(const float4*)&Vg[gsrc];
            uint32_t h0, l0, h1, l1;
            split2(kv.x, kv.y, h0, l0);
            split2(kv.z, kv.w, h1, l1);
            *(uint2*)(sm + FSM_KH + r * QROWB + c * 8) = make_uint2(h0, h1);
            *(uint2*)(sm + FSM_KL + r * QROWB + c * 8) = make_uint2(l0, l1);
            split2(vv.x, vv.y, h0, l0);
            split2(vv.z, vv.w, h1, l1);
            *(uint2*)(sm + FSM_VH + r * QROWB + c * 8) = make_uint2(h0, h1);
            *(uint2*)(sm + FSM_VL + r * QROWB + c * 8) = make_uint2(l0, l1);
        }
        __syncthreads();

        float sacc[8][4];
#pragma unroll
        for (int j = 0; j < 8; j++)
#pragma unroll
            for (int c = 0; c < 4; c++) sacc[j][c] = 0.f;

#pragma unroll
        for (int kt = 0; kt < 8; kt++) {
            uint32_t ah[4], al[4];
            const uint32_t aa = a_addr0 + kt * 32;
            LDM_X4(ah[0], ah[1], ah[2], ah[3], aa);
            LDM_X4(al[0], al[1], al[2], al[3], aa + (FSM_QL - FSM_QH));
#pragma unroll
            for (int nt = 0; nt < 4; nt++) {
                const uint32_t ba = sb + FSM_KH
                    + (nt * 16 + g16 * 8 + l7) * QROWB + kt * 32 + g8 * 16;
                uint32_t bh[4], bl[4];
                LDM_X4(bh[0], bh[1], bh[2], bh[3], ba);
                LDM_X4(bl[0], bl[1], bl[2], bl[3], ba + (FSM_KL - FSM_KH));
                mma_bf16(sacc[2 * nt],     ah, bh[0], bh[1]);
                mma_bf16(sacc[2 * nt + 1], ah, bh[2], bh[3]);
                mma_bf16(sacc[2 * nt],     ah, bl[0], bl[1]);
                mma_bf16(sacc[2 * nt + 1], ah, bl[2], bl[3]);
                mma_bf16(sacc[2 * nt],     al, bh[0], bh[1]);
                mma_bf16(sacc[2 * nt + 1], al, bh[2], bh[3]);
            }
        }

        const int gi0 = qs0 + mr + (lane >> 2);
        const int gi1 = gi0 + 8;
        const bool interior = (kb * 64 + 63 <= qs0) && (kb * 64 >= qs0 + FQ - 1 - WIN);
        if (!interior) {
#pragma unroll
            for (int j = 0; j < 8; j++) {
                const int gj = kb * 64 + j * 8 + (lane & 3) * 2;
                if (gj > gi0 || gj < gi0 - WIN)         sacc[j][0] = -1e30f;
                if (gj + 1 > gi0 || gj + 1 < gi0 - WIN) sacc[j][1] = -1e30f;
                if (gj > gi1 || gj < gi1 - WIN)         sacc[j][2] = -1e30f;
                if (gj + 1 > gi1 || gj + 1 < gi1 - WIN) sacc[j][3] = -1e30f;
            }
        }

        float rmax0 = -1e30f, rmax1 = -1e30f;
#pragma unroll
        for (int j = 0; j < 8; j++) {
            rmax0 = fmaxf(rmax0, fmaxf(sacc[j][0], sacc[j][1]));
            rmax1 = fmaxf(rmax1, fmaxf(sacc[j][2], sacc[j][3]));
        }
        rmax0 = fmaxf(rmax0, __shfl_xor_sync(0xffffffffu, rmax0, 1));
        rmax0 = fmaxf(rmax0, __shfl_xor_sync(0xffffffffu, rmax0, 2));
        rmax1 = fmaxf(rmax1, __shfl_xor_sync(0xffffffffu, rmax1, 1));
        rmax1 = fmaxf(rmax1, __shfl_xor_sync(0xffffffffu, rmax1, 2));
        const float m0n = fmaxf(m0, rmax0), m1n = fmaxf(m1, rmax1);
        const float c0 = __expf(m0 - m0n), c1 = __expf(m1 - m1n);

        uint32_t pah[4][4], pal[4][4];
        float ls0 = 0.f, ls1 = 0.f;
#pragma unroll
        for (int t = 0; t < 4; t++) {
#pragma unroll
            for (int q = 0; q < 2; q++) {
                const int j = 2 * t + q;
                const float p0 = __expf(sacc[j][0] - m0n);
                const float p1 = __expf(sacc[j][1] - m0n);
                const float p2 = __expf(sacc[j][2] - m1n);
                const float p3 = __expf(sacc[j][3] - m1n);
                ls0 += p0 + p1; ls1 += p2 + p3;
                split2(p0, p1, pah[t][2 * q],     pal[t][2 * q]);
                split2(p2, p3, pah[t][2 * q + 1], pal[t][2 * q + 1]);
            }
        }
        ls0 += __shfl_xor_sync(0xffffffffu, ls0, 1);
        ls0 += __shfl_xor_sync(0xffffffffu, ls0, 2);
        ls1 += __shfl_xor_sync(0xffffffffu, ls1, 1);
        ls1 += __shfl_xor_sync(0xffffffffu, ls1, 2);
        l0s = l0s * c0 + ls0;
        l1s = l1s * c1 + ls1;
        m0 = m0n; m1 = m1n;
#pragma unroll
        for (int j = 0; j < 16; j++) {
            oacc[j][0] *= c0; oacc[j][1] *= c0;
            oacc[j][2] *= c1; oacc[j][3] *= c1;
        }

#pragma unroll
        for (int t = 0; t < 4; t++) {
#pragma unroll
            for (int dn = 0; dn < 8; dn++) {
                const uint32_t va = sb + FSM_VH
                    + (t * 16 + g8 * 8 + l7) * QROWB + dn * 32 + g16 * 16;
                uint32_t vh[4], vl[4];
                LDM_X4_T(vh[0], vh[1], vh[2], vh[3], va);
                LDM_X4_T(vl[0], vl[1], vl[2], vl[3], va + (FSM_VL - FSM_VH));
                mma_bf16(oacc[2 * dn],     pah[t], vh[0], vh[1]);
                mma_bf16(oacc[2 * dn + 1], pah[t], vh[2], vh[3]);
                mma_bf16(oacc[2 * dn],     pah[t], vl[0], vl[1]);
                mma_bf16(oacc[2 * dn + 1], pah[t], vl[2], vl[3]);
                mma_bf16(oacc[2 * dn],     pal[t], vh[0], vh[1]);
                mma_bf16(oacc[2 * dn + 1], pal[t], vh[2], vh[3]);
            }
        }
    }

    const float inv0 = 1.f / l0s, inv1 = 1.f / l1s;
    const int r0 = qs0 + mr + (lane >> 2);
    const size_t ob0 = (((size_t)b * SS + r0) * HH + h) * HD;
    const size_t ob1 = (((size_t)b * SS + r0 + 8) * HH + h) * HD;
#pragma unroll
    for (int j = 0; j < 16; j++) {
        const int col = j * 8 + (lane & 3) * 2;
        *(float2*)&Og[ob0 + col] = make_float2(oacc[j][0] * inv0, oacc[j][1] * inv0);
        *(float2*)&Og[ob1 + col] = make_float2(oacc[j][2] * inv1, oacc[j][3] * inv1);
    }
}

// ---------------------------------------------------------------------------
extern "C" void kernel_launch(void* const* d_in, const int* in_sizes, int n_in,
                              void* d_out, int out_size)
{
    const float* hidden = (const float*)d_in[0];
    const float* cosb   = (const float*)d_in[1];
    const float* sinb   = (const float*)d_in[2];
    const float* Wq     = (const float*)d_in[3];
    const float* Wk     = (const float*)d_in[4];
    const float* Wv     = (const float*)d_in[5];
    const float* Wo     = (const float*)d_in[6];
    const float* qscale = (const float*)d_in[7];
    const float* kscale = (const float*)d_in[8];
    float* out = (float*)d_out;

    float *gq, *gk, *gv, *ga;
    cudaGetSymbolAddress((void**)&gq, g_q);
    cudaGetSymbolAddress((void**)&gk, g_k);
    cudaGetSymbolAddress((void**)&gv, g_v);
    cudaGetSymbolAddress((void**)&ga, g_attn);

    __nv_bfloat16 *hh, *hl, *ah, *al;
    __nv_bfloat16 *wqh, *wql, *wkh, *wkl, *wvh, *wvl, *woh, *wol;
    cudaGetSymbolAddress((void**)&hh, g_hh);   cudaGetSymbolAddress((void**)&hl, g_hl);
    cudaGetSymbolAddress((void**)&ah, g_ah);   cudaGetSymbolAddress((void**)&al, g_al);
    cudaGetSymbolAddress((void**)&wqh, g_wqh); cudaGetSymbolAddress((void**)&wql, g_wql);
    cudaGetSymbolAddress((void**)&wkh, g_wkh); cudaGetSymbolAddress((void**)&wkl, g_wkl);
    cudaGetSymbolAddress((void**)&wvh, g_wvh); cudaGetSymbolAddress((void**)&wvl, g_wvl);
    cudaGetSymbolAddress((void**)&woh, g_woh); cudaGetSymbolAddress((void**)&wol, g_wol);

    cudaFuncSetAttribute(flash_hmma_kernel,
                         cudaFuncAttributeMaxDynamicSharedMemorySize, FLASH2_SMEM);
    cudaFuncSetAttribute(gemm_mma_kernel,
                         cudaFuncAttributeMaxDynamicSharedMemorySize, GSMEM);

    const int M = BB * SS;                 // 4096
    const int n4 = M * DD / 4;
    dim3 tgrid(DD / 32, DD / 32);
    dim3 tblk(32, 8);
    dim3 qkv_grid(DD / GBN, M / GBM, 3);   // (16, 16, 3)
    dim3 wo_grid(DD / GBN, M / GBM, 1);

    // prep (ordered so the ncu sample lands on the fused GEMM)
    transpose_split_kernel<<<tgrid, tblk>>>(Wq, wqh, wql);
    transpose_split_kernel<<<tgrid, tblk>>>(Wk, wkh, wkl);
    transpose_split_kernel<<<tgrid, tblk>>>(Wv, wvh, wvl);
    convert_split_kernel<<<(n4 + 255) / 256, 256>>>(hidden, hh, hl, n4);

    // fused QKV projection
    gemm_mma_kernel<<<qkv_grid, 512, GSMEM>>>(hh, hl,
        wqh, wql, gq, wkh, wkl, gk, wvh, wvl, gv, M, DD, DD);

    transpose_split_kernel<<<tgrid, tblk>>>(Wo, woh, wol);

    rmsrope_kernel<<<M * HH, HD>>>(gq, qscale, cosb, sinb);
    rmsrope_kernel<<<M * HH, HD>>>(gk, kscale, cosb, sinb);

    flash_hmma_kernel<<<dim3(SS / FQ, HH, BB), 256, FLASH2_SMEM>>>(gq, gk, gv, ga);

    convert_split_kernel<<<(n4 + 255) / 256, 256>>>(ga, ah, al, n4);
    gemm_mma_kernel<<<wo_grid, 512, GSMEM>>>(ah, al,
        woh, wol, out, woh, wol, out, woh, wol, out, M, DD, DD);
}

// round 7
// speedup vs baseline: 4.9416x; 1.4550x over previous
#include <cuda_runtime.h>
#include <cuda_fp16.h>
#include <math.h>
#include <stdint.h>

#define BB 2
#define SS 2048
#define DD 2048
#define HH 16
#define HD 128
#define WIN 1024
#define EPSV 1e-6f
#define SCALEF 0.08838834764831845f   // 128^-0.5

#define NSC (BB * SS * HH * HD)
__device__ float g_q[NSC];
__device__ float g_k[NSC];
__device__ float g_v[NSC];
__device__ float g_attn[NSC];

// fp16 operand buffers
__device__ __half g_hf[BB * SS * DD];          // hidden, single fp16
__device__ __half g_af[BB * SS * DD];          // attn-out, single fp16
__device__ __half g_wqh[DD * DD], g_wql[DD * DD];
__device__ __half g_wkh[DD * DD], g_wkl[DD * DD];
__device__ __half g_wvh[DD * DD], g_wvl[DD * DD];
__device__ __half g_woh[DD * DD], g_wol[DD * DD];

// ---------------------------------------------------------------------------
// helpers (compute_103-safe baseline PTX: mma.sync / ldmatrix / cp.async)
// ---------------------------------------------------------------------------
__device__ __forceinline__ uint32_t smem_to_u32(const void* p) {
    uint32_t a;
    asm("{ .reg .u64 t; cvta.to.shared.u64 t, %1; cvt.u32.u64 %0, t; }"
        : "=r"(a) : "l"(p));
    return a;
}

#define LDM_X4(r0, r1, r2, r3, a) \
    asm volatile("ldmatrix.sync.aligned.m8n8.x4.shared.b16 {%0,%1,%2,%3}, [%4];" \
        : "=r"(r0), "=r"(r1), "=r"(r2), "=r"(r3) : "r"(a))

#define LDM_X4_T(r0, r1, r2, r3, a) \
    asm volatile("ldmatrix.sync.aligned.m8n8.x4.trans.shared.b16 {%0,%1,%2,%3}, [%4];" \
        : "=r"(r0), "=r"(r1), "=r"(r2), "=r"(r3) : "r"(a))

__device__ __forceinline__ void mma_f16(float* d, const uint32_t* a,
                                        uint32_t b0, uint32_t b1) {
    asm volatile(
        "mma.sync.aligned.m16n8k16.row.col.f32.f16.f16.f32 "
        "{%0,%1,%2,%3}, {%4,%5,%6,%7}, {%8,%9}, {%0,%1,%2,%3};"
        : "+f"(d[0]), "+f"(d[1]), "+f"(d[2]), "+f"(d[3])
        : "r"(a[0]), "r"(a[1]), "r"(a[2]), "r"(a[3]), "r"(b0), "r"(b1));
}

__device__ __forceinline__ void cp16(uint32_t dst, const void* src) {
    asm volatile("cp.async.cg.shared.global [%0], [%1], 16;" :: "r"(dst), "l"(src));
}
#define CP_COMMIT() asm volatile("cp.async.commit_group;")

__device__ __forceinline__ uint32_t packh2(float x, float y) {
    __half2 h = __floats2half2_rn(x, y);
    return *(uint32_t*)&h;
}
__device__ __forceinline__ void splith2(float x, float y, uint32_t& hi, uint32_t& lo) {
    __half2 h = __floats2half2_rn(x, y);
    __half2 l = __floats2half2_rn(x - __half2float(h.x), y - __half2float(h.y));
    hi = *(uint32_t*)&h;
    lo = *(uint32_t*)&l;
}

// ---------------------------------------------------------------------------
// fp32 -> fp16 (single, elementwise)
// ---------------------------------------------------------------------------
__global__ void __launch_bounds__(256) convert_half_kernel(
    const float* __restrict__ x, __half* __restrict__ y, int n4)
{
    int i = blockIdx.x * blockDim.x + threadIdx.x;
    if (i >= n4) return;
    float4 v = ((const float4*)x)[i];
    uint2 o = make_uint2(packh2(v.x, v.y), packh2(v.z, v.w));
    *(uint2*)(y + 4 * (size_t)i) = o;
}

// ---------------------------------------------------------------------------
// W[K][N] fp32 -> transposed fp16 hi/lo [N][K]
// ---------------------------------------------------------------------------
__global__ void __launch_bounds__(256) transpose_split_kernel(
    const float* __restrict__ W, __half* __restrict__ Thi,
    __half* __restrict__ Tlo)
{
    __shared__ float t[32][33];
    const int k0 = blockIdx.y * 32, n0 = blockIdx.x * 32;
    const int tx = threadIdx.x, ty = threadIdx.y;
#pragma unroll
    for (int r = 0; r < 32; r += 8)
        t[ty + r][tx] = W[(size_t)(k0 + ty + r) * DD + n0 + tx];
    __syncthreads();
#pragma unroll
    for (int r = 0; r < 32; r += 8) {
        const float v = t[tx][ty + r];
        const __half h = __float2half_rn(v);
        const __half l = __float2half_rn(v - __half2float(h));
        const size_t o = (size_t)(n0 + ty + r) * DD + k0 + tx;
        Thi[o] = h; Tlo[o] = l;
    }
}

// ---------------------------------------------------------------------------
// fp16 2-product GEMM on HMMA: C_z[M,N] = A[M,K] @ W_z[K,N].
//   A single fp16 [M][K]; W pre-transposed fp16 hi/lo [N][K].
//   C = Ah*Bh + Ah*Bl  (= A_rounded * B_exact).
// CTA tile 256x128, BK=32, 512 threads (16 warps, warp tile 64x32),
// 4-stage cp.async pipeline. grid.z selects (B, C) for fused QKV.
// ---------------------------------------------------------------------------
#define GBM 256
#define GBN 128
#define ROWB 80                          // 32 fp16 = 64 B + 16 B pad
#define A_OFF 0
#define BHI_OFF (GBM * ROWB)             // 20480
#define BLO_OFF (BHI_OFF + GBN * ROWB)   // 30720
#define STAGEB (BHI_OFF + 2 * GBN * ROWB)   // 40960
#define NSTAGE 4
#define GSMEM (NSTAGE * STAGEB)          // 163840

__global__ void __launch_bounds__(512) gemm_mma_kernel(
    const __half* __restrict__ A,
    const __half* __restrict__ B0h, const __half* __restrict__ B0l,
    float* __restrict__ C0,
    const __half* __restrict__ B1h, const __half* __restrict__ B1l,
    float* __restrict__ C1,
    const __half* __restrict__ B2h, const __half* __restrict__ B2l,
    float* __restrict__ C2,
    int M, int N, int K)
{
    extern __shared__ char smc[];
    const uint32_t sb = smem_to_u32(smc);
    const int tid = threadIdx.x, lane = tid & 31, wid = tid >> 5;
    const int bm = blockIdx.y * GBM, bn = blockIdx.x * GBN;
    const int z = blockIdx.z;
    const __half* Bhi = (z == 0) ? B0h : (z == 1) ? B1h : B2h;
    const __half* Blo = (z == 0) ? B0l : (z == 1) ? B1l : B2l;
    float* C = (z == 0) ? C0 : (z == 1) ? C1 : C2;

    const int m0 = (wid & 3) * 64, n0 = (wid >> 2) * 32;

    float acc[4][4][4];
#pragma unroll
    for (int i = 0; i < 4; i++)
#pragma unroll
        for (int j = 0; j < 4; j++)
#pragma unroll
            for (int c = 0; c < 4; c++) acc[i][j][c] = 0.f;

    // cp.async mapping: 2048 16B chunks / 512 threads = 4 per thread
    const __half* gsrc[4];
    uint32_t sdst[4];
#pragma unroll
    for (int j = 0; j < 4; j++) {
        const int idx = j * 512 + tid;
        int mat, row;
        if (idx < 1024)      { mat = 0; row = idx >> 2; }
        else if (idx < 1536) { mat = 1; row = (idx - 1024) >> 2; }
        else                 { mat = 2; row = (idx - 1536) >> 2; }
        const int cc = idx & 3;
        const __half* base = (mat == 0) ? A : (mat == 1) ? Bhi : Blo;
        const int r = ((mat == 0) ? bm : bn) + row;
        const uint32_t moff = (mat == 0) ? A_OFF : (mat == 1) ? BHI_OFF : BLO_OFF;
        gsrc[j] = base + (size_t)r * K + cc * 8;
        sdst[j] = sb + moff + row * ROWB + cc * 16;
    }

    const int nk = K >> 5;   // 64

#pragma unroll
    for (int s = 0; s < 3; s++) {
        const uint32_t so = s * STAGEB;
        const int kc = s * 32;
#pragma unroll
        for (int j = 0; j < 4; j++) cp16(sdst[j] + so, gsrc[j] + kc);
        CP_COMMIT();
    }

    for (int c = 0; c < nk; c++) {
        if (c + 3 < nk) {
            const uint32_t so = ((c + 3) % NSTAGE) * STAGEB;
            const int kc = (c + 3) * 32;
#pragma unroll
            for (int j = 0; j < 4; j++) cp16(sdst[j] + so, gsrc[j] + kc);
        }
        CP_COMMIT();
        asm volatile("cp.async.wait_group 3;");
        __syncthreads();

        const uint32_t st = sb + (c % NSTAGE) * STAGEB;
#pragma unroll
        for (int ks = 0; ks < 2; ks++) {
            const uint32_t kb = ks * 32;
            uint32_t bh0[4], bh1[4], bl0[4], bl1[4];
            {
                const uint32_t rb = st + BHI_OFF + (n0 + lane) * ROWB + kb;
                LDM_X4(bh0[0], bh0[1], bh0[2], bh0[3], rb);
                LDM_X4(bh1[0], bh1[1], bh1[2], bh1[3], rb + 16);
                LDM_X4(bl0[0], bl0[1], bl0[2], bl0[3], rb + (BLO_OFF - BHI_OFF));
                LDM_X4(bl1[0], bl1[1], bl1[2], bl1[3], rb + (BLO_OFF - BHI_OFF) + 16);
            }
#pragma unroll
            for (int mi = 0; mi < 4; mi++) {
                uint32_t ah[4];
                const uint32_t ra = st + A_OFF
                    + (m0 + mi * 16 + (lane & 15)) * ROWB + kb + ((lane >> 4) << 4);
                LDM_X4(ah[0], ah[1], ah[2], ah[3], ra);
#pragma unroll
                for (int ni = 0; ni < 4; ni++) {
                    mma_f16(acc[mi][ni], ah, bh0[ni], bh1[ni]);
                    mma_f16(acc[mi][ni], ah, bl0[ni], bl1[ni]);
                }
            }
        }
        __syncthreads();
    }

#pragma unroll
    for (int mi = 0; mi < 4; mi++) {
        const int r0 = bm + m0 + mi * 16 + (lane >> 2);
#pragma unroll
        for (int ni = 0; ni < 4; ni++) {
            const int c0 = bn + n0 + ni * 8 + (lane & 3) * 2;
            *(float2*)&C[(size_t)r0 * N + c0] =
                make_float2(acc[mi][ni][0], acc[mi][ni][1]);
            *(float2*)&C[(size_t)(r0 + 8) * N + c0] =
                make_float2(acc[mi][ni][2], acc[mi][ni][3]);
        }
    }
}

// ---------------------------------------------------------------------------
// Fused per-head RMSNorm + RoPE (unchanged).
// ---------------------------------------------------------------------------
__global__ void __launch_bounds__(128) rmsrope_kernel(
    float* __restrict__ x, const float* __restrict__ scale,
    const float* __restrict__ cosb, const float* __restrict__ sinb)
{
    __shared__ float sh[HD];
    __shared__ float red[4];
    const int row = blockIdx.x;
    const int d = threadIdx.x;
    const size_t base = (size_t)row * HD;

    const float v = x[base + d];
    float ssum = v * v;
#pragma unroll
    for (int o = 16; o > 0; o >>= 1) ssum += __shfl_xor_sync(0xffffffffu, ssum, o);
    if ((d & 31) == 0) red[d >> 5] = ssum;
    __syncthreads();
    const float tot = red[0] + red[1] + red[2] + red[3];
    const float r = rsqrtf(tot * (1.f / HD) + EPSV);
    const float xn = scale[d] * v * r;
    sh[d] = xn;
    __syncthreads();
    const float rot = (d < 64) ? -sh[d + 64] : sh[d - 64];
    const size_t cbase = (size_t)(row / HH) * HD;
    x[base + d] = xn * cosb[cbase + d] + rot * sinb[cbase + d];
}

// ---------------------------------------------------------------------------
// HMMA sliding-window flash attention, fp16 2-product:
//   S = Qh*(Kh+Kl)  (Q single fp16, pre-scaled; K split hi/lo)
//   O = Ph*(Vh+Vl)  (P single fp16; V split hi/lo)
// Block: 256 threads (8 warps), q-tile 128, k-tile 64.
// ---------------------------------------------------------------------------
#define FQ 128
#define FKT 64
#define QROWB 272
#define FSM_Q 0
#define FSM_KH (FQ * QROWB)
#define FSM_KL (FSM_KH + FKT * QROWB)
#define FSM_VH (FSM_KH + 2 * FKT * QROWB)
#define FSM_VL (FSM_KH + 3 * FKT * QROWB)
#define FLASH2_SMEM (FSM_KH + 4 * FKT * QROWB)   // 104448

__global__ void __launch_bounds__(256) flash_hmma_kernel(
    const float* __restrict__ Qg, const float* __restrict__ Kg,
    const float* __restrict__ Vg, float* __restrict__ Og)
{
    extern __shared__ char sm[];
    const uint32_t sb = smem_to_u32(sm);
    const int tid = threadIdx.x, lane = tid & 31, wid = tid >> 5;
    const int qb = blockIdx.x, h = blockIdx.y, b = blockIdx.z;
    const int qs0 = qb * FQ;
    const int mr = wid * 16;

    // Q tile: fp32 -> scaled -> single fp16
    for (int i = tid; i < FQ * 32; i += 256) {
        const int r = i >> 5, c = i & 31;
        float4 q = *(const float4*)&Qg[(((size_t)b * SS + qs0 + r) * HH + h) * HD + c * 4];
        q.x *= SCALEF; q.y *= SCALEF; q.z *= SCALEF; q.w *= SCALEF;
        *(uint2*)(sm + FSM_Q + r * QROWB + c * 8) =
            make_uint2(packh2(q.x, q.y), packh2(q.z, q.w));
    }

    float oacc[16][4];
#pragma unroll
    for (int j = 0; j < 16; j++)
#pragma unroll
        for (int c = 0; c < 4; c++) oacc[j][c] = 0.f;
    float m0 = 0.f, m1 = 0.f, l0s = 0.f, l1s = 0.f;   // m init 0: masked->exp(-1e30)=0

    const uint32_t g8 = (lane >> 3) & 1, g16 = (lane >> 4) & 1, l7 = lane & 7;
    const uint32_t a_addr0 = sb + FSM_Q + (mr + g8 * 8 + l7) * QROWB + g16 * 16;

    const int kb_lo = (qs0 >= WIN) ? (qs0 - WIN) / 64 : 0;
    const int kb_hi = (qs0 + FQ - 1) / 64;

    for (int kb = kb_lo; kb <= kb_hi; kb++) {
        __syncthreads();
        // K,V tile: fp32 -> fp16 hi/lo
        for (int i = tid; i < FKT * 32; i += 256) {
            const int r = i >> 5, c = i & 31;
            const size_t gsrc = (((size_t)b * SS + kb * 64 + r) * HH + h) * HD + c * 4;
            float4 kv = *(const float4*)&Kg[gsrc];
            float4 vv = *(const float4*)&Vg[gsrc];
            uint32_t h0, l0, h1, l1;
            splith2(kv.x, kv.y, h0, l0);
            splith2(kv.z, kv.w, h1, l1);
            *(uint2*)(sm + FSM_KH + r * QROWB + c * 8) = make_uint2(h0, h1);
            *(uint2*)(sm + FSM_KL + r * QROWB + c * 8) = make_uint2(l0, l1);
            splith2(vv.x, vv.y, h0, l0);
            splith2(vv.z, vv.w, h1, l1);
            *(uint2*)(sm + FSM_VH + r * QROWB + c * 8) = make_uint2(h0, h1);
            *(uint2*)(sm + FSM_VL + r * QROWB + c * 8) = make_uint2(l0, l1);
        }
        __syncthreads();

        // ---- S = Q @ K^T ----
        float sacc[8][4];
#pragma unroll
        for (int j = 0; j < 8; j++)
#pragma unroll
            for (int c = 0; c < 4; c++) sacc[j][c] = 0.f;

#pragma unroll
        for (int kt = 0; kt < 8; kt++) {
            uint32_t aq[4];
            LDM_X4(aq[0], aq[1], aq[2], aq[3], a_addr0 + kt * 32);
#pragma unroll
            for (int nt = 0; nt < 4; nt++) {
                const uint32_t ba = sb + FSM_KH
                    + (nt * 16 + g16 * 8 + l7) * QROWB + kt * 32 + g8 * 16;
                uint32_t bh[4], bl[4];
                LDM_X4(bh[0], bh[1], bh[2], bh[3], ba);
                LDM_X4(bl[0], bl[1], bl[2], bl[3], ba + (FSM_KL - FSM_KH));
                mma_f16(sacc[2 * nt],     aq, bh[0], bh[1]);
                mma_f16(sacc[2 * nt + 1], aq, bh[2], bh[3]);
                mma_f16(sacc[2 * nt],     aq, bl[0], bl[1]);
                mma_f16(sacc[2 * nt + 1], aq, bl[2], bl[3]);
            }
        }

        // ---- mask ----
        const int gi0 = qs0 + mr + (lane >> 2);
        const int gi1 = gi0 + 8;
        const bool interior = (kb * 64 + 63 <= qs0) && (kb * 64 >= qs0 + FQ - 1 - WIN);
        if (!interior) {
#pragma unroll
            for (int j = 0; j < 8; j++) {
                const int gj = kb * 64 + j * 8 + (lane & 3) * 2;
                if (gj > gi0 || gj < gi0 - WIN)         sacc[j][0] = -1e30f;
                if (gj + 1 > gi0 || gj + 1 < gi0 - WIN) sacc[j][1] = -1e30f;
                if (gj > gi1 || gj < gi1 - WIN)         sacc[j][2] = -1e30f;
                if (gj + 1 > gi1 || gj + 1 < gi1 - WIN) sacc[j][3] = -1e30f;
            }
        }

        // ---- online softmax ----
        float rmax0 = -1e30f, rmax1 = -1e30f;
#pragma unroll
        for (int j = 0; j < 8; j++) {
            rmax0 = fmaxf(rmax0, fmaxf(sacc[j][0], sacc[j][1]));
            rmax1 = fmaxf(rmax1, fmaxf(sacc[j][2], sacc[j][3]));
        }
        rmax0 = fmaxf(rmax0, __shfl_xor_sync(0xffffffffu, rmax0, 1));
        rmax0 = fmaxf(rmax0, __shfl_xor_sync(0xffffffffu, rmax0, 2));
        rmax1 = fmaxf(rmax1, __shfl_xor_sync(0xffffffffu, rmax1, 1));
        rmax1 = fmaxf(rmax1, __shfl_xor_sync(0xffffffffu, rmax1, 2));
        const float m0n = fmaxf(m0, rmax0), m1n = fmaxf(m1, rmax1);
        const float c0 = __expf(m0 - m0n), c1 = __expf(m1 - m1n);

        uint32_t pa[4][4];
        float ls0 = 0.f, ls1 = 0.f;
#pragma unroll
        for (int t = 0; t < 4; t++) {
#pragma unroll
            for (int q = 0; q < 2; q++) {
                const int j = 2 * t + q;
                const float p0 = __expf(sacc[j][0] - m0n);
                const float p1 = __expf(sacc[j][1] - m0n);
                const float p2 = __expf(sacc[j][2] - m1n);
                const float p3 = __expf(sacc[j][3] - m1n);
                ls0 += p0 + p1; ls1 += p2 + p3;
                pa[t][2 * q]     = packh2(p0, p1);
                pa[t][2 * q + 1] = packh2(p2, p3);
            }
        }
        ls0 += __shfl_xor_sync(0xffffffffu, ls0, 1);
        ls0 += __shfl_xor_sync(0xffffffffu, ls0, 2);
        ls1 += __shfl_xor_sync(0xffffffffu, ls1, 1);
        ls1 += __shfl_xor_sync(0xffffffffu, ls1, 2);
        l0s = l0s * c0 + ls0;
        l1s = l1s * c1 + ls1;
        m0 = m0n; m1 = m1n;
#pragma unroll
        for (int j = 0; j < 16; j++) {
            oacc[j][0] *= c0; oacc[j][1] *= c0;
            oacc[j][2] *= c1; oacc[j][3] *= c1;
        }

        // ---- O += P @ V ----
#pragma unroll
        for (int t = 0; t < 4; t++) {
#pragma unroll
            for (int dn = 0; dn < 8; dn++) {
                const uint32_t va = sb + FSM_VH
                    + (t * 16 + g8 * 8 + l7) * QROWB + dn * 32 + g16 * 16;
                uint32_t vh[4], vl[4];
                LDM_X4_T(vh[0], vh[1], vh[2], vh[3], va);
                LDM_X4_T(vl[0], vl[1], vl[2], vl[3], va + (FSM_VL - FSM_VH));
                mma_f16(oacc[2 * dn],     pa[t], vh[0], vh[1]);
                mma_f16(oacc[2 * dn + 1], pa[t], vh[2], vh[3]);
                mma_f16(oacc[2 * dn],     pa[t], vl[0], vl[1]);
                mma_f16(oacc[2 * dn + 1], pa[t], vl[2], vl[3]);
            }
        }
    }

    const float inv0 = 1.f / l0s, inv1 = 1.f / l1s;
    const int r0 = qs0 + mr + (lane >> 2);
    const size_t ob0 = (((size_t)b * SS + r0) * HH + h) * HD;
    const size_t ob1 = (((size_t)b * SS + r0 + 8) * HH + h) * HD;
#pragma unroll
    for (int j = 0; j < 16; j++) {
        const int col = j * 8 + (lane & 3) * 2;
        *(float2*)&Og[ob0 + col] = make_float2(oacc[j][0] * inv0, oacc[j][1] * inv0);
        *(float2*)&Og[ob1 + col] = make_float2(oacc[j][2] * inv1, oacc[j][3] * inv1);
    }
}

// ---------------------------------------------------------------------------
extern "C" void kernel_launch(void* const* d_in, const int* in_sizes, int n_in,
                              void* d_out, int out_size)
{
    const float* hidden = (const float*)d_in[0];
    const float* cosb   = (const float*)d_in[1];
    const float* sinb   = (const float*)d_in[2];
    const float* Wq     = (const float*)d_in[3];
    const float* Wk     = (const float*)d_in[4];
    const float* Wv     = (const float*)d_in[5];
    const float* Wo     = (const float*)d_in[6];
    const float* qscale = (const float*)d_in[7];
    const float* kscale = (const float*)d_in[8];
    float* out = (float*)d_out;

    float *gq, *gk, *gv, *ga;
    cudaGetSymbolAddress((void**)&gq, g_q);
    cudaGetSymbolAddress((void**)&gk, g_k);
    cudaGetSymbolAddress((void**)&gv, g_v);
    cudaGetSymbolAddress((void**)&ga, g_attn);

    __half *hf, *af;
    __half *wqh, *wql, *wkh, *wkl, *wvh, *wvl, *woh, *wol;
    cudaGetSymbolAddress((void**)&hf, g_hf);
    cudaGetSymbolAddress((void**)&af, g_af);
    cudaGetSymbolAddress((void**)&wqh, g_wqh); cudaGetSymbolAddress((void**)&wql, g_wql);
    cudaGetSymbolAddress((void**)&wkh, g_wkh); cudaGetSymbolAddress((void**)&wkl, g_wkl);
    cudaGetSymbolAddress((void**)&wvh, g_wvh); cudaGetSymbolAddress((void**)&wvl, g_wvl);
    cudaGetSymbolAddress((void**)&woh, g_woh); cudaGetSymbolAddress((void**)&wol, g_wol);

    cudaFuncSetAttribute(flash_hmma_kernel,
                         cudaFuncAttributeMaxDynamicSharedMemorySize, FLASH2_SMEM);
    cudaFuncSetAttribute(gemm_mma_kernel,
                         cudaFuncAttributeMaxDynamicSharedMemorySize, GSMEM);

    const int M = BB * SS;                 // 4096
    const int n4 = M * DD / 4;
    dim3 tgrid(DD / 32, DD / 32);
    dim3 tblk(32, 8);
    dim3 qkv_grid(DD / GBN, M / GBM, 3);   // (16, 16, 3)
    dim3 wo_grid(DD / GBN, M / GBM, 1);

    transpose_split_kernel<<<tgrid, tblk>>>(Wq, wqh, wql);
    transpose_split_kernel<<<tgrid, tblk>>>(Wk, wkh, wkl);
    transpose_split_kernel<<<tgrid, tblk>>>(Wv, wvh, wvl);
    convert_half_kernel<<<(n4 + 255) / 256, 256>>>(hidden, hf, n4);

    gemm_mma_kernel<<<qkv_grid, 512, GSMEM>>>(hf,
        wqh, wql, gq, wkh, wkl, gk, wvh, wvl, gv, M, DD, DD);

    transpose_split_kernel<<<tgrid, tblk>>>(Wo, woh, wol);

    rmsrope_kernel<<<M * HH, HD>>>(gq, qscale, cosb, sinb);
    rmsrope_kernel<<<M * HH, HD>>>(gk, kscale, cosb, sinb);

    flash_hmma_kernel<<<dim3(SS / FQ, HH, BB), 256, FLASH2_SMEM>>>(gq, gk, gv, ga);

    convert_half_kernel<<<(n4 + 255) / 256, 256>>>(ga, af, n4);
    gemm_mma_kernel<<<wo_grid, 512, GSMEM>>>(af,
        woh, wol, out, woh, wol, out, woh, wol, out, M, DD, DD);
}

// round 8
// speedup vs baseline: 5.4634x; 1.1056x over previous
#include <cuda_runtime.h>
#include <cuda_fp16.h>
#include <math.h>
#include <stdint.h>

#define BB 2
#define SS 2048
#define DD 2048
#define HH 16
#define HD 128
#define WIN 1024
#define EPSV 1e-6f
#define SCALEF 0.08838834764831845f   // 128^-0.5

// fp16 operand buffers
__device__ __half g_hf[BB * SS * DD];          // hidden, single fp16
__device__ __half g_af[BB * SS * DD];          // attn-out, single fp16
__device__ __half g_qf[BB * SS * DD];          // Q (normed+roped+scaled), single
__device__ __half g_kh[BB * SS * DD], g_kl[BB * SS * DD];   // K hi/lo
__device__ __half g_vh[BB * SS * DD], g_vl[BB * SS * DD];   // V hi/lo
__device__ __half g_wqh[DD * DD], g_wql[DD * DD];
__device__ __half g_wkh[DD * DD], g_wkl[DD * DD];
__device__ __half g_wvh[DD * DD], g_wvl[DD * DD];
__device__ __half g_woh[DD * DD], g_wol[DD * DD];

// ---------------------------------------------------------------------------
// helpers (compute_103-safe baseline PTX: mma.sync / ldmatrix / cp.async)
// ---------------------------------------------------------------------------
__device__ __forceinline__ uint32_t smem_to_u32(const void* p) {
    uint32_t a;
    asm("{ .reg .u64 t; cvta.to.shared.u64 t, %1; cvt.u32.u64 %0, t; }"
        : "=r"(a) : "l"(p));
    return a;
}

#define LDM_X4(r0, r1, r2, r3, a) \
    asm volatile("ldmatrix.sync.aligned.m8n8.x4.shared.b16 {%0,%1,%2,%3}, [%4];" \
        : "=r"(r0), "=r"(r1), "=r"(r2), "=r"(r3) : "r"(a))

#define LDM_X4_T(r0, r1, r2, r3, a) \
    asm volatile("ldmatrix.sync.aligned.m8n8.x4.trans.shared.b16 {%0,%1,%2,%3}, [%4];" \
        : "=r"(r0), "=r"(r1), "=r"(r2), "=r"(r3) : "r"(a))

__device__ __forceinline__ void mma_f16(float* d, const uint32_t* a,
                                        uint32_t b0, uint32_t b1) {
    asm volatile(
        "mma.sync.aligned.m16n8k16.row.col.f32.f16.f16.f32 "
        "{%0,%1,%2,%3}, {%4,%5,%6,%7}, {%8,%9}, {%0,%1,%2,%3};"
        : "+f"(d[0]), "+f"(d[1]), "+f"(d[2]), "+f"(d[3])
        : "r"(a[0]), "r"(a[1]), "r"(a[2]), "r"(a[3]), "r"(b0), "r"(b1));
}

__device__ __forceinline__ void cp16(uint32_t dst, const void* src) {
    asm volatile("cp.async.cg.shared.global [%0], [%1], 16;" :: "r"(dst), "l"(src));
}
#define CP_COMMIT() asm volatile("cp.async.commit_group;")

__device__ __forceinline__ uint32_t packh2(float x, float y) {
    __half2 h = __floats2half2_rn(x, y);
    return *(uint32_t*)&h;
}
__device__ __forceinline__ void splith2(float x, float y, uint32_t& hi, uint32_t& lo) {
    __half2 h = __floats2half2_rn(x, y);
    __half2 l = __floats2half2_rn(x - __half2float(h.x), y - __half2float(h.y));
    hi = *(uint32_t*)&h;
    lo = *(uint32_t*)&l;
}

// ---------------------------------------------------------------------------
// fp32 -> fp16 (single, elementwise)
// ---------------------------------------------------------------------------
__global__ void __launch_bounds__(256) convert_half_kernel(
    const float* __restrict__ x, __half* __restrict__ y, int n4)
{
    int i = blockIdx.x * blockDim.x + threadIdx.x;
    if (i >= n4) return;
    float4 v = ((const float4*)x)[i];
    *(uint2*)(y + 4 * (size_t)i) = make_uint2(packh2(v.x, v.y), packh2(v.z, v.w));
}

// ---------------------------------------------------------------------------
// W[K][N] fp32 -> transposed fp16 hi/lo [N][K]
// ---------------------------------------------------------------------------
__global__ void __launch_bounds__(256) transpose_split_kernel(
    const float* __restrict__ W, __half* __restrict__ Thi, __half* __restrict__ Tlo)
{
    __shared__ float t[32][33];
    const int k0 = blockIdx.y * 32, n0 = blockIdx.x * 32;
    const int tx = threadIdx.x, ty = threadIdx.y;
#pragma unroll
    for (int r = 0; r < 32; r += 8)
        t[ty + r][tx] = W[(size_t)(k0 + ty + r) * DD + n0 + tx];
    __syncthreads();
#pragma unroll
    for (int r = 0; r < 32; r += 8) {
        const float v = t[tx][ty + r];
        const __half h = __float2half_rn(v);
        const __half l = __float2half_rn(v - __half2float(h));
        const size_t o = (size_t)(n0 + ty + r) * DD + k0 + tx;
        Thi[o] = h; Tlo[o] = l;
    }
}

// ---------------------------------------------------------------------------
// fp16 2-product GEMM on HMMA. CTA tile 256x128, BK=32, 512 threads, 4-stage.
// MODE 0: fused QKV — grid.z in {0,1,2}; epilogue does RMSNorm+RoPE (z<2) and
//         writes fp16 (Q single pre-scaled; K,V hi/lo).
// MODE 1: plain fp32 store to C (Wo projection).
// ---------------------------------------------------------------------------
#define GBM 256
#define GBN 128
#define ROWB 80
#define A_OFF 0
#define BHI_OFF (GBM * ROWB)             // 20480
#define BLO_OFF (BHI_OFF + GBN * ROWB)   // 30720
#define STAGEB (BHI_OFF + 2 * GBN * ROWB)   // 40960
#define NSTAGE 4
#define GSMEM (NSTAGE * STAGEB)          // 163840
// epilogue staging (reuses pipeline smem): xs[256][132] + sums[4][256] + rsq[256]
#define XSROW 132
#define SUMS_OFF 135168
#define RSQ_OFF  139264

template <int MODE>
__global__ void __launch_bounds__(512) gemm_mma_kernel(
    const __half* __restrict__ A,
    const __half* __restrict__ B0h, const __half* __restrict__ B0l,
    const __half* __restrict__ B1h, const __half* __restrict__ B1l,
    const __half* __restrict__ B2h, const __half* __restrict__ B2l,
    __half* __restrict__ qf, __half* __restrict__ khp, __half* __restrict__ klp,
    __half* __restrict__ vhp, __half* __restrict__ vlp,
    const float* __restrict__ cosb, const float* __restrict__ sinb,
    const float* __restrict__ qsc, const float* __restrict__ ksc,
    float* __restrict__ C, int M, int N, int K)
{
    extern __shared__ char smc[];
    const uint32_t sb = smem_to_u32(smc);
    const int tid = threadIdx.x, lane = tid & 31, wid = tid >> 5;
    const int bm = blockIdx.y * GBM, bn = blockIdx.x * GBN;
    const int z = blockIdx.z;
    const __half* Bhi = (z == 0) ? B0h : (z == 1) ? B1h : B2h;
    const __half* Blo = (z == 0) ? B0l : (z == 1) ? B1l : B2l;

    const int m0 = (wid & 3) * 64, n0 = (wid >> 2) * 32;

    float acc[4][4][4];
#pragma unroll
    for (int i = 0; i < 4; i++)
#pragma unroll
        for (int j = 0; j < 4; j++)
#pragma unroll
            for (int c = 0; c < 4; c++) acc[i][j][c] = 0.f;

    const __half* gsrc[4];
    uint32_t sdst[4];
#pragma unroll
    for (int j = 0; j < 4; j++) {
        const int idx = j * 512 + tid;
        int mat, row;
        if (idx < 1024)      { mat = 0; row = idx >> 2; }
        else if (idx < 1536) { mat = 1; row = (idx - 1024) >> 2; }
        else                 { mat = 2; row = (idx - 1536) >> 2; }
        const int cc = idx & 3;
        const __half* base = (mat == 0) ? A : (mat == 1) ? Bhi : Blo;
        const int r = ((mat == 0) ? bm : bn) + row;
        const uint32_t moff = (mat == 0) ? A_OFF : (mat == 1) ? BHI_OFF : BLO_OFF;
        gsrc[j] = base + (size_t)r * K + cc * 8;
        sdst[j] = sb + moff + row * ROWB + cc * 16;
    }

    const int nk = K >> 5;

#pragma unroll
    for (int s = 0; s < 3; s++) {
        const uint32_t so = s * STAGEB;
        const int kc = s * 32;
#pragma unroll
        for (int j = 0; j < 4; j++) cp16(sdst[j] + so, gsrc[j] + kc);
        CP_COMMIT();
    }

    for (int c = 0; c < nk; c++) {
        if (c + 3 < nk) {
            const uint32_t so = ((c + 3) % NSTAGE) * STAGEB;
            const int kc = (c + 3) * 32;
#pragma unroll
            for (int j = 0; j < 4; j++) cp16(sdst[j] + so, gsrc[j] + kc);
        }
        CP_COMMIT();
        asm volatile("cp.async.wait_group 3;");
        __syncthreads();

        const uint32_t st = sb + (c % NSTAGE) * STAGEB;
#pragma unroll
        for (int ks = 0; ks < 2; ks++) {
            const uint32_t kb = ks * 32;
            uint32_t bh0[4], bh1[4], bl0[4], bl1[4];
            {
                const uint32_t rb = st + BHI_OFF + (n0 + lane) * ROWB + kb;
                LDM_X4(bh0[0], bh0[1], bh0[2], bh0[3], rb);
                LDM_X4(bh1[0], bh1[1], bh1[2], bh1[3], rb + 16);
                LDM_X4(bl0[0], bl0[1], bl0[2], bl0[3], rb + (BLO_OFF - BHI_OFF));
                LDM_X4(bl1[0], bl1[1], bl1[2], bl1[3], rb + (BLO_OFF - BHI_OFF) + 16);
            }
#pragma unroll
            for (int mi = 0; mi < 4; mi++) {
                uint32_t ah[4];
                const uint32_t ra = st + A_OFF
                    + (m0 + mi * 16 + (lane & 15)) * ROWB + kb + ((lane >> 4) << 4);
                LDM_X4(ah[0], ah[1], ah[2], ah[3], ra);
#pragma unroll
                for (int ni = 0; ni < 4; ni++) {
                    mma_f16(acc[mi][ni], ah, bh0[ni], bh1[ni]);
                    mma_f16(acc[mi][ni], ah, bl0[ni], bl1[ni]);
                }
            }
        }
        __syncthreads();
    }

    if (MODE == 1) {
        // plain fp32 epilogue (Wo)
#pragma unroll
        for (int mi = 0; mi < 4; mi++) {
            const int r0 = bm + m0 + mi * 16 + (lane >> 2);
#pragma unroll
            for (int ni = 0; ni < 4; ni++) {
                const int c0 = bn + n0 + ni * 8 + (lane & 3) * 2;
                *(float2*)&C[(size_t)r0 * N + c0] =
                    make_float2(acc[mi][ni][0], acc[mi][ni][1]);
                *(float2*)&C[(size_t)(r0 + 8) * N + c0] =
                    make_float2(acc[mi][ni][2], acc[mi][ni][3]);
            }
        }
        return;
    }

    // ---- fused QKV epilogue ----
    const int wg = wid >> 2;     // N-chunk 0..3
    const int rq = lane >> 2;    // 0..7

    if (z == 2) {
        // V: plain hi/lo fp16 convert
#pragma unroll
        for (int mi = 0; mi < 4; mi++) {
            const int rg = bm + m0 + mi * 16 + rq;
#pragma unroll
            for (int ni = 0; ni < 4; ni++) {
                const int d0 = n0 + ni * 8 + (lane & 3) * 2;
                size_t o = (size_t)rg * DD + bn + d0;
                uint32_t hi, lo;
                splith2(acc[mi][ni][0], acc[mi][ni][1], hi, lo);
                *(uint32_t*)&vhp[o] = hi; *(uint32_t*)&vlp[o] = lo;
                o += (size_t)8 * DD;
                splith2(acc[mi][ni][2], acc[mi][ni][3], hi, lo);
                *(uint32_t*)&vhp[o] = hi; *(uint32_t*)&vlp[o] = lo;
            }
        }
        return;
    }

    float* xs   = (float*)smc;
    float* sums = (float*)(smc + SUMS_OFF);
    float* rsq  = (float*)(smc + RSQ_OFF);

    // per-row sum of squares (CTA holds the full HD=128 per row)
#pragma unroll
    for (int mi = 0; mi < 4; mi++) {
        float s0 = 0.f, s1 = 0.f;
#pragma unroll
        for (int ni = 0; ni < 4; ni++) {
            s0 += acc[mi][ni][0] * acc[mi][ni][0] + acc[mi][ni][1] * acc[mi][ni][1];
            s1 += acc[mi][ni][2] * acc[mi][ni][2] + acc[mi][ni][3] * acc[mi][ni][3];
        }
        s0 += __shfl_xor_sync(0xffffffffu, s0, 1);
        s0 += __shfl_xor_sync(0xffffffffu, s0, 2);
        s1 += __shfl_xor_sync(0xffffffffu, s1, 1);
        s1 += __shfl_xor_sync(0xffffffffu, s1, 2);
        if ((lane & 3) == 0) {
            sums[wg * 256 + m0 + mi * 16 + rq]     = s0;
            sums[wg * 256 + m0 + mi * 16 + rq + 8] = s1;
        }
    }
    __syncthreads();
    if (tid < 256)
        rsq[tid] = rsqrtf((sums[tid] + sums[256 + tid] + sums[512 + tid]
                           + sums[768 + tid]) * (1.f / HD) + EPSV);
    __syncthreads();

    const float* svec = (z == 0) ? qsc : ksc;
#pragma unroll
    for (int mi = 0; mi < 4; mi++) {
        const int ra = m0 + mi * 16 + rq, rb2 = ra + 8;
#pragma unroll
        for (int ni = 0; ni < 4; ni++) {
            const int d0 = n0 + ni * 8 + (lane & 3) * 2;
            const float sc0 = svec[d0], sc1 = svec[d0 + 1];
            xs[ra * XSROW + d0]      = acc[mi][ni][0] * rsq[ra] * sc0;
            xs[ra * XSROW + d0 + 1]  = acc[mi][ni][1] * rsq[ra] * sc1;
            xs[rb2 * XSROW + d0]     = acc[mi][ni][2] * rsq[rb2] * sc0;
            xs[rb2 * XSROW + d0 + 1] = acc[mi][ni][3] * rsq[rb2] * sc1;
        }
    }
    __syncthreads();

    // RoPE + convert + store
#pragma unroll
    for (int mi = 0; mi < 4; mi++) {
#pragma unroll
        for (int hh2 = 0; hh2 < 2; hh2++) {
            const int rloc = m0 + mi * 16 + rq + hh2 * 8;
            const int rg = bm + rloc;
#pragma unroll
            for (int ni = 0; ni < 4; ni++) {
                const int d0 = n0 + ni * 8 + (lane & 3) * 2;
                const float x0 = xs[rloc * XSROW + d0];
                const float x1 = xs[rloc * XSROW + d0 + 1];
                float rot0, rot1;
                if (d0 < 64) { rot0 = -xs[rloc * XSROW + d0 + 64];
                               rot1 = -xs[rloc * XSROW + d0 + 65]; }
                else         { rot0 =  xs[rloc * XSROW + d0 - 64];
                               rot1 =  xs[rloc * XSROW + d0 - 63]; }
                const size_t cb = (size_t)rg * HD + d0;
                const float y0 = x0 * cosb[cb]     + rot0 * sinb[cb];
                const float y1 = x1 * cosb[cb + 1] + rot1 * sinb[cb + 1];
                const size_t o = (size_t)rg * DD + bn + d0;
                if (z == 0) {
                    *(uint32_t*)&qf[o] = packh2(y0 * SCALEF, y1 * SCALEF);
                } else {
                    uint32_t hi, lo;
                    splith2(y0, y1, hi, lo);
                    *(uint32_t*)&khp[o] = hi; *(uint32_t*)&klp[o] = lo;
                }
            }
        }
    }
}

// ---------------------------------------------------------------------------
// HMMA sliding-window flash attention, fp16 2-product, cp.async inputs.
//   S = Q*(Kh+Kl) ; O = P*(Vh+Vl). Q pre-scaled/normed/roped (from GEMM epi).
// Block 256 threads (8 warps), q-tile 128, k-tile 64, double-buffered KV.
// Writes attn output as single fp16 (operand of Wo GEMM).
// ---------------------------------------------------------------------------
#define FQ 128
#define ROWB2 272
#define Q_BYTES (FQ * ROWB2)           // 34816
#define KVTILE (64 * ROWB2)            // 17408
#define KVBUF (4 * KVTILE)             // 69632
#define FLASH_SMEM (Q_BYTES + 2 * KVBUF)   // 174080

__global__ void __launch_bounds__(256) flash_hmma_kernel(
    const __half* __restrict__ Qf,
    const __half* __restrict__ Kh, const __half* __restrict__ Kl,
    const __half* __restrict__ Vh, const __half* __restrict__ Vl,
    __half* __restrict__ Oa)
{
    extern __shared__ char sm[];
    const uint32_t sb = smem_to_u32(sm);
    const int tid = threadIdx.x, lane = tid & 31, wid = tid >> 5;
    const int qb = blockIdx.x, h = blockIdx.y, b = blockIdx.z;
    const int qs0 = qb * FQ;
    const int mr = wid * 16;

    const int kb_lo = (qs0 >= WIN) ? (qs0 - WIN) / 64 : 0;
    const int kb_hi = (qs0 + FQ - 1) / 64;

    // Q tile via cp.async: 128 rows x 16 chunks
    {
        const size_t qbase = ((size_t)(b * SS + qs0) * HH + h) * HD;
#pragma unroll
        for (int i = 0; i < 8; i++) {
            const int idx = tid + i * 256;
            const int r = idx >> 4, cc = idx & 15;
            cp16(sb + r * ROWB2 + cc * 16, Qf + qbase + (size_t)r * (HH * HD) + cc * 8);
        }
        CP_COMMIT();
    }
    // prologue: KV tile kb_lo -> buf 0
    {
        const uint32_t kvb = sb + Q_BYTES;
        const size_t base = ((size_t)(b * SS + kb_lo * 64) * HH + h) * HD;
#pragma unroll
        for (int i = 0; i < 16; i++) {
            const int idx = tid + i * 256;
            const int mat = idx >> 10, w = idx & 1023, r = w >> 4, cc = w & 15;
            const __half* src = (mat == 0) ? Kh : (mat == 1) ? Kl
                              : (mat == 2) ? Vh : Vl;
            cp16(kvb + mat * KVTILE + r * ROWB2 + cc * 16,
                 src + base + (size_t)r * (HH * HD) + cc * 8);
        }
        CP_COMMIT();
    }

    float oacc[16][4];
#pragma unroll
    for (int j = 0; j < 16; j++)
#pragma unroll
        for (int c = 0; c < 4; c++) oacc[j][c] = 0.f;
    float m0 = 0.f, m1 = 0.f, l0s = 0.f, l1s = 0.f;

    const uint32_t g8 = (lane >> 3) & 1, g16 = (lane >> 4) & 1, l7 = lane & 7;
    const uint32_t a_addr0 = sb + (mr + g8 * 8 + l7) * ROWB2 + g16 * 16;

    for (int kb = kb_lo; kb <= kb_hi; kb++) {
        const int buf = (kb - kb_lo) & 1;
        const uint32_t kvb = sb + Q_BYTES + buf * KVBUF;

        asm volatile("cp.async.wait_group 0;");
        __syncthreads();

        // prefetch next KV tile into the other buffer (overlaps compute)
        if (kb + 1 <= kb_hi) {
            const uint32_t nb = sb + Q_BYTES + (buf ^ 1) * KVBUF;
            const size_t base = ((size_t)(b * SS + (kb + 1) * 64) * HH + h) * HD;
#pragma unroll
            for (int i = 0; i < 16; i++) {
                const int idx = tid + i * 256;
                const int mat = idx >> 10, w = idx & 1023, r = w >> 4, cc = w & 15;
                const __half* src = (mat == 0) ? Kh : (mat == 1) ? Kl
                                  : (mat == 2) ? Vh : Vl;
                cp16(nb + mat * KVTILE + r * ROWB2 + cc * 16,
                     src + base + (size_t)r * (HH * HD) + cc * 8);
            }
        }
        CP_COMMIT();

        // ---- S = Q @ K^T ----
        float sacc[8][4];
#pragma unroll
        for (int j = 0; j < 8; j++)
#pragma unroll
            for (int c = 0; c < 4; c++) sacc[j][c] = 0.f;

#pragma unroll
        for (int kt = 0; kt < 8; kt++) {
            uint32_t aq[4];
            LDM_X4(aq[0], aq[1], aq[2], aq[3], a_addr0 + kt * 32);
#pragma unroll
            for (int nt = 0; nt < 4; nt++) {
                const uint32_t ba = kvb + (nt * 16 + g16 * 8 + l7) * ROWB2
                                  + kt * 32 + g8 * 16;
                uint32_t bh[4], bl[4];
                LDM_X4(bh[0], bh[1], bh[2], bh[3], ba);
                LDM_X4(bl[0], bl[1], bl[2], bl[3], ba + KVTILE);
                mma_f16(sacc[2 * nt],     aq, bh[0], bh[1]);
                mma_f16(sacc[2 * nt + 1], aq, bh[2], bh[3]);
                mma_f16(sacc[2 * nt],     aq, bl[0], bl[1]);
                mma_f16(sacc[2 * nt + 1], aq, bl[2], bl[3]);
            }
        }

        // ---- mask ----
        const int gi0 = qs0 + mr + (lane >> 2);
        const int gi1 = gi0 + 8;
        const bool interior = (kb * 64 + 63 <= qs0) && (kb * 64 >= qs0 + FQ - 1 - WIN);
        if (!interior) {
#pragma unroll
            for (int j = 0; j < 8; j++) {
                const int gj = kb * 64 + j * 8 + (lane & 3) * 2;
                if (gj > gi0 || gj < gi0 - WIN)         sacc[j][0] = -1e30f;
                if (gj + 1 > gi0 || gj + 1 < gi0 - WIN) sacc[j][1] = -1e30f;
                if (gj > gi1 || gj < gi1 - WIN)         sacc[j][2] = -1e30f;
                if (gj + 1 > gi1 || gj + 1 < gi1 - WIN) sacc[j][3] = -1e30f;
            }
        }

        // ---- online softmax ----
        float rmax0 = -1e30f, rmax1 = -1e30f;
#pragma unroll
        for (int j = 0; j < 8; j++) {
            rmax0 = fmaxf(rmax0, fmaxf(sacc[j][0], sacc[j][1]));
            rmax1 = fmaxf(rmax1, fmaxf(sacc[j][2], sacc[j][3]));
        }
        rmax0 = fmaxf(rmax0, __shfl_xor_sync(0xffffffffu, rmax0, 1));
        rmax0 = fmaxf(rmax0, __shfl_xor_sync(0xffffffffu, rmax0, 2));
        rmax1 = fmaxf(rmax1, __shfl_xor_sync(0xffffffffu, rmax1, 1));
        rmax1 = fmaxf(rmax1, __shfl_xor_sync(0xffffffffu, rmax1, 2));
        const float m0n = fmaxf(m0, rmax0), m1n = fmaxf(m1, rmax1);
        const float c0 = __expf(m0 - m0n), c1 = __expf(m1 - m1n);

        uint32_t pa[4][4];
        float ls0 = 0.f, ls1 = 0.f;
#pragma unroll
        for (int t = 0; t < 4; t++) {
#pragma unroll
            for (int q = 0; q < 2; q++) {
                const int j = 2 * t + q;
                const float p0 = __expf(sacc[j][0] - m0n);
                const float p1 = __expf(sacc[j][1] - m0n);
                const float p2 = __expf(sacc[j][2] - m1n);
                const float p3 = __expf(sacc[j][3] - m1n);
                ls0 += p0 + p1; ls1 += p2 + p3;
                pa[t][2 * q]     = packh2(p0, p1);
                pa[t][2 * q + 1] = packh2(p2, p3);
            }
        }
        ls0 += __shfl_xor_sync(0xffffffffu, ls0, 1);
        ls0 += __shfl_xor_sync(0xffffffffu, ls0, 2);
        ls1 += __shfl_xor_sync(0xffffffffu, ls1, 1);
        ls1 += __shfl_xor_sync(0xffffffffu, ls1, 2);
        l0s = l0s * c0 + ls0;
        l1s = l1s * c1 + ls1;
        m0 = m0n; m1 = m1n;
#pragma unroll
        for (int j = 0; j < 16; j++) {
            oacc[j][0] *= c0; oacc[j][1] *= c0;
            oacc[j][2] *= c1; oacc[j][3] *= c1;
        }

        // ---- O += P @ V ----
#pragma unroll
        for (int t = 0; t < 4; t++) {
#pragma unroll
            for (int dn = 0; dn < 8; dn++) {
                const uint32_t va = kvb + 2 * KVTILE
                    + (t * 16 + g8 * 8 + l7) * ROWB2 + dn * 32 + g16 * 16;
                uint32_t vh[4], vl[4];
                LDM_X4_T(vh[0], vh[1], vh[2], vh[3], va);
                LDM_X4_T(vl[0], vl[1], vl[2], vl[3], va + KVTILE);
                mma_f16(oacc[2 * dn],     pa[t], vh[0], vh[1]);
                mma_f16(oacc[2 * dn + 1], pa[t], vh[2], vh[3]);
                mma_f16(oacc[2 * dn],     pa[t], vl[0], vl[1]);
                mma_f16(oacc[2 * dn + 1], pa[t], vl[2], vl[3]);
            }
        }
        __syncthreads();   // all warps done with this buf before next overwrite
    }

    // ---- epilogue: write fp16 attn output (Wo GEMM A operand) ----
    const float inv0 = 1.f / l0s, inv1 = 1.f / l1s;
    const int r0 = qs0 + mr + (lane >> 2);
    const size_t ob0 = (((size_t)b * SS + r0) * HH + h) * HD;
    const size_t ob1 = (((size_t)b * SS + r0 + 8) * HH + h) * HD;
#pragma unroll
    for (int j = 0; j < 16; j++) {
        const int col = j * 8 + (lane & 3) * 2;
        *(uint32_t*)&Oa[ob0 + col] = packh2(oacc[j][0] * inv0, oacc[j][1] * inv0);
        *(uint32_t*)&Oa[ob1 + col] = packh2(oacc[j][2] * inv1, oacc[j][3] * inv1);
    }
}

// ---------------------------------------------------------------------------
extern "C" void kernel_launch(void* const* d_in, const int* in_sizes, int n_in,
                              void* d_out, int out_size)
{
    const float* hidden = (const float*)d_in[0];
    const float* cosb   = (const float*)d_in[1];
    const float* sinb   = (const float*)d_in[2];
    const float* Wq     = (const float*)d_in[3];
    const float* Wk     = (const float*)d_in[4];
    const float* Wv     = (const float*)d_in[5];
    const float* Wo     = (const float*)d_in[6];
    const float* qscale = (const float*)d_in[7];
    const float* kscale = (const float*)d_in[8];
    float* out = (float*)d_out;

    __half *hf, *af, *qf, *kh, *kl, *vh, *vl;
    __half *wqh, *wql, *wkh, *wkl, *wvh, *wvl, *woh, *wol;
    cudaGetSymbolAddress((void**)&hf, g_hf);
    cudaGetSymbolAddress((void**)&af, g_af);
    cudaGetSymbolAddress((void**)&qf, g_qf);
    cudaGetSymbolAddress((void**)&kh, g_kh); cudaGetSymbolAddress((void**)&kl, g_kl);
    cudaGetSymbolAddress((void**)&vh, g_vh); cudaGetSymbolAddress((void**)&vl, g_vl);
    cudaGetSymbolAddress((void**)&wqh, g_wqh); cudaGetSymbolAddress((void**)&wql, g_wql);
    cudaGetSymbolAddress((void**)&wkh, g_wkh); cudaGetSymbolAddress((void**)&wkl, g_wkl);
    cudaGetSymbolAddress((void**)&wvh, g_wvh); cudaGetSymbolAddress((void**)&wvl, g_wvl);
    cudaGetSymbolAddress((void**)&woh, g_woh); cudaGetSymbolAddress((void**)&wol, g_wol);

    cudaFuncSetAttribute(flash_hmma_kernel,
                         cudaFuncAttributeMaxDynamicSharedMemorySize, FLASH_SMEM);
    cudaFuncSetAttribute(gemm_mma_kernel<0>,
                         cudaFuncAttributeMaxDynamicSharedMemorySize, GSMEM);
    cudaFuncSetAttribute(gemm_mma_kernel<1>,
                         cudaFuncAttributeMaxDynamicSharedMemorySize, GSMEM);

    const int M = BB * SS;                 // 4096
    const int n4 = M * DD / 4;
    dim3 tgrid(DD / 32, DD / 32);
    dim3 tblk(32, 8);
    dim3 qkv_grid(DD / GBN, M / GBM, 3);   // (16, 16, 3)
    dim3 wo_grid(DD / GBN, M / GBM, 1);

    transpose_split_kernel<<<tgrid, tblk>>>(Wq, wqh, wql);
    transpose_split_kernel<<<tgrid, tblk>>>(Wk, wkh, wkl);
    transpose_split_kernel<<<tgrid, tblk>>>(Wv, wvh, wvl);
    convert_half_kernel<<<(n4 + 255) / 256, 256>>>(hidden, hf, n4);

    // fused QKV projection + RMSNorm + RoPE + fp16 conversion
    gemm_mma_kernel<0><<<qkv_grid, 512, GSMEM>>>(hf,
        wqh, wql, wkh, wkl, wvh, wvl,
        qf, kh, kl, vh, vl, cosb, sinb, qscale, kscale,
        nullptr, M, DD, DD);

    transpose_split_kernel<<<tgrid, tblk>>>(Wo, woh, wol);

    flash_hmma_kernel<<<dim3(SS / FQ, HH, BB), 256, FLASH_SMEM>>>(
        qf, kh, kl, vh, vl, af);

    // output projection
    gemm_mma_kernel<1><<<wo_grid, 512, GSMEM>>>(af,
        woh, wol, woh, wol, woh, wol,
        nullptr, nullptr, nullptr, nullptr, nullptr,
        nullptr, nullptr, nullptr, nullptr,
        out, M, DD, DD);
}

// round 9
// speedup vs baseline: 8.4907x; 1.5541x over previous
#include <cuda_runtime.h>
#include <cuda_fp16.h>
#include <math.h>
#include <stdint.h>

#define BB 2
#define SS 2048
#define DD 2048
#define HH 16
#define HD 128
#define WIN 1024
#define EPSV 1e-6f
#define SCALEF 0.08838834764831845f   // 128^-0.5

// fp16 operand buffers (all single precision fp16 now)
__device__ __half g_hf[BB * SS * DD];          // hidden
__device__ __half g_af[BB * SS * DD];          // attn-out
__device__ __half g_qf[BB * SS * DD];          // Q (normed+roped+scaled)
__device__ __half g_kf[BB * SS * DD];          // K (normed+roped)
__device__ __half g_vf[BB * SS * DD];          // V
__device__ __half g_wq[DD * DD], g_wk[DD * DD], g_wv[DD * DD], g_wo[DD * DD];

// ---------------------------------------------------------------------------
// helpers (compute_103-safe baseline PTX: mma.sync / ldmatrix / cp.async)
// ---------------------------------------------------------------------------
__device__ __forceinline__ uint32_t smem_to_u32(const void* p) {
    uint32_t a;
    asm("{ .reg .u64 t; cvta.to.shared.u64 t, %1; cvt.u32.u64 %0, t; }"
        : "=r"(a) : "l"(p));
    return a;
}

#define LDM_X4(r0, r1, r2, r3, a) \
    asm volatile("ldmatrix.sync.aligned.m8n8.x4.shared.b16 {%0,%1,%2,%3}, [%4];" \
        : "=r"(r0), "=r"(r1), "=r"(r2), "=r"(r3) : "r"(a))

#define LDM_X4_T(r0, r1, r2, r3, a) \
    asm volatile("ldmatrix.sync.aligned.m8n8.x4.trans.shared.b16 {%0,%1,%2,%3}, [%4];" \
        : "=r"(r0), "=r"(r1), "=r"(r2), "=r"(r3) : "r"(a))

__device__ __forceinline__ void mma_f16(float* d, const uint32_t* a,
                                        uint32_t b0, uint32_t b1) {
    asm volatile(
        "mma.sync.aligned.m16n8k16.row.col.f32.f16.f16.f32 "
        "{%0,%1,%2,%3}, {%4,%5,%6,%7}, {%8,%9}, {%0,%1,%2,%3};"
        : "+f"(d[0]), "+f"(d[1]), "+f"(d[2]), "+f"(d[3])
        : "r"(a[0]), "r"(a[1]), "r"(a[2]), "r"(a[3]), "r"(b0), "r"(b1));
}

__device__ __forceinline__ void cp16(uint32_t dst, const void* src) {
    asm volatile("cp.async.cg.shared.global [%0], [%1], 16;" :: "r"(dst), "l"(src));
}
#define CP_COMMIT() asm volatile("cp.async.commit_group;")

__device__ __forceinline__ uint32_t packh2(float x, float y) {
    __half2 h = __floats2half2_rn(x, y);
    return *(uint32_t*)&h;
}

// ---------------------------------------------------------------------------
// fp32 -> fp16 (elementwise)
// ---------------------------------------------------------------------------
__global__ void __launch_bounds__(256) convert_half_kernel(
    const float* __restrict__ x, __half* __restrict__ y, int n4)
{
    int i = blockIdx.x * blockDim.x + threadIdx.x;
    if (i >= n4) return;
    float4 v = ((const float4*)x)[i];
    *(uint2*)(y + 4 * (size_t)i) = make_uint2(packh2(v.x, v.y), packh2(v.z, v.w));
}

// ---------------------------------------------------------------------------
// W[K][N] fp32 -> transposed fp16 [N][K]
// ---------------------------------------------------------------------------
__global__ void __launch_bounds__(256) transpose_half_kernel(
    const float* __restrict__ W, __half* __restrict__ T)
{
    __shared__ float t[32][33];
    const int k0 = blockIdx.y * 32, n0 = blockIdx.x * 32;
    const int tx = threadIdx.x, ty = threadIdx.y;
#pragma unroll
    for (int r = 0; r < 32; r += 8)
        t[ty + r][tx] = W[(size_t)(k0 + ty + r) * DD + n0 + tx];
    __syncthreads();
#pragma unroll
    for (int r = 0; r < 32; r += 8)
        T[(size_t)(n0 + ty + r) * DD + k0 + tx] = __float2half_rn(t[tx][ty + r]);
}

// ---------------------------------------------------------------------------
// fp16 single-product GEMM on HMMA. CTA tile 256x128, BK=32, 512 threads,
// 4-stage cp.async pipeline.
// MODE 0: fused QKV — grid.z in {0,1,2}; epilogue does RMSNorm+RoPE (z<2),
//         writes fp16 (Q pre-scaled by 1/sqrt(HD)).
// MODE 1: plain fp32 store to C (Wo projection).
// ---------------------------------------------------------------------------
#define GBM 256
#define GBN 128
#define ROWB 80
#define A_OFF 0
#define B_OFF (GBM * ROWB)               // 20480
#define STAGEB (B_OFF + GBN * ROWB)      // 30720
#define NSTAGE 4
// epilogue staging: xs[256][132] f32 + sums[4][256] + rsq[256]
#define XSROW 132
#define SUMS_OFF 135168
#define RSQ_OFF  139264
#define GSMEM 140288                     // >= max(NSTAGE*STAGEB, epilogue)

template <int MODE>
__global__ void __launch_bounds__(512) gemm_mma_kernel(
    const __half* __restrict__ A,
    const __half* __restrict__ B0, const __half* __restrict__ B1,
    const __half* __restrict__ B2,
    __half* __restrict__ qf, __half* __restrict__ kfp, __half* __restrict__ vfp,
    const float* __restrict__ cosb, const float* __restrict__ sinb,
    const float* __restrict__ qsc, const float* __restrict__ ksc,
    float* __restrict__ C, int M, int N, int K)
{
    extern __shared__ char smc[];
    const uint32_t sb = smem_to_u32(smc);
    const int tid = threadIdx.x, lane = tid & 31, wid = tid >> 5;
    const int bm = blockIdx.y * GBM, bn = blockIdx.x * GBN;
    const int z = blockIdx.z;
    const __half* B = (z == 0) ? B0 : (z == 1) ? B1 : B2;

    const int m0 = (wid & 3) * 64, n0 = (wid >> 2) * 32;

    float acc[4][4][4];
#pragma unroll
    for (int i = 0; i < 4; i++)
#pragma unroll
        for (int j = 0; j < 4; j++)
#pragma unroll
            for (int c = 0; c < 4; c++) acc[i][j][c] = 0.f;

    // cp.async mapping: 1536 16B chunks / 512 threads = 3 per thread
    const __half* gsrc[3];
    uint32_t sdst[3];
#pragma unroll
    for (int j = 0; j < 3; j++) {
        const int idx = j * 512 + tid;
        const int mat = (idx < 1024) ? 0 : 1;
        const int row = (mat == 0) ? (idx >> 2) : ((idx - 1024) >> 2);
        const int cc = idx & 3;
        const __half* base = (mat == 0) ? A : B;
        const int r = ((mat == 0) ? bm : bn) + row;
        gsrc[j] = base + (size_t)r * K + cc * 8;
        sdst[j] = sb + ((mat == 0) ? A_OFF : B_OFF) + row * ROWB + cc * 16;
    }

    const int nk = K >> 5;

#pragma unroll
    for (int s = 0; s < 3; s++) {
        const uint32_t so = s * STAGEB;
        const int kc = s * 32;
#pragma unroll
        for (int j = 0; j < 3; j++) cp16(sdst[j] + so, gsrc[j] + kc);
        CP_COMMIT();
    }

    for (int c = 0; c < nk; c++) {
        if (c + 3 < nk) {
            const uint32_t so = ((c + 3) % NSTAGE) * STAGEB;
            const int kc = (c + 3) * 32;
#pragma unroll
            for (int j = 0; j < 3; j++) cp16(sdst[j] + so, gsrc[j] + kc);
        }
        CP_COMMIT();
        asm volatile("cp.async.wait_group 3;");
        __syncthreads();

        const uint32_t st = sb + (c % NSTAGE) * STAGEB;
#pragma unroll
        for (int ks = 0; ks < 2; ks++) {
            const uint32_t kb = ks * 32;
            uint32_t b0[4], b1[4];
            {
                const uint32_t rb = st + B_OFF + (n0 + lane) * ROWB + kb;
                LDM_X4(b0[0], b0[1], b0[2], b0[3], rb);
                LDM_X4(b1[0], b1[1], b1[2], b1[3], rb + 16);
            }
#pragma unroll
            for (int mi = 0; mi < 4; mi++) {
                uint32_t ah[4];
                const uint32_t ra = st + A_OFF
                    + (m0 + mi * 16 + (lane & 15)) * ROWB + kb + ((lane >> 4) << 4);
                LDM_X4(ah[0], ah[1], ah[2], ah[3], ra);
#pragma unroll
                for (int ni = 0; ni < 4; ni++)
                    mma_f16(acc[mi][ni], ah, b0[ni], b1[ni]);
            }
        }
        __syncthreads();
    }

    if (MODE == 1) {
#pragma unroll
        for (int mi = 0; mi < 4; mi++) {
            const int r0 = bm + m0 + mi * 16 + (lane >> 2);
#pragma unroll
            for (int ni = 0; ni < 4; ni++) {
                const int c0 = bn + n0 + ni * 8 + (lane & 3) * 2;
                *(float2*)&C[(size_t)r0 * N + c0] =
                    make_float2(acc[mi][ni][0], acc[mi][ni][1]);
                *(float2*)&C[(size_t)(r0 + 8) * N + c0] =
                    make_float2(acc[mi][ni][2], acc[mi][ni][3]);
            }
        }
        return;
    }

    // ---- fused QKV epilogue ----
    const int wg = wid >> 2;
    const int rq = lane >> 2;

    if (z == 2) {
        // V: plain fp16 convert
#pragma unroll
        for (int mi = 0; mi < 4; mi++) {
            const int rg = bm + m0 + mi * 16 + rq;
#pragma unroll
            for (int ni = 0; ni < 4; ni++) {
                const int d0 = n0 + ni * 8 + (lane & 3) * 2;
                size_t o = (size_t)rg * DD + bn + d0;
                *(uint32_t*)&vfp[o] = packh2(acc[mi][ni][0], acc[mi][ni][1]);
                o += (size_t)8 * DD;
                *(uint32_t*)&vfp[o] = packh2(acc[mi][ni][2], acc[mi][ni][3]);
            }
        }
        return;
    }

    float* xs   = (float*)smc;
    float* sums = (float*)(smc + SUMS_OFF);
    float* rsq  = (float*)(smc + RSQ_OFF);

#pragma unroll
    for (int mi = 0; mi < 4; mi++) {
        float s0 = 0.f, s1 = 0.f;
#pragma unroll
        for (int ni = 0; ni < 4; ni++) {
            s0 += acc[mi][ni][0] * acc[mi][ni][0] + acc[mi][ni][1] * acc[mi][ni][1];
            s1 += acc[mi][ni][2] * acc[mi][ni][2] + acc[mi][ni][3] * acc[mi][ni][3];
        }
        s0 += __shfl_xor_sync(0xffffffffu, s0, 1);
        s0 += __shfl_xor_sync(0xffffffffu, s0, 2);
        s1 += __shfl_xor_sync(0xffffffffu, s1, 1);
        s1 += __shfl_xor_sync(0xffffffffu, s1, 2);
        if ((lane & 3) == 0) {
            sums[wg * 256 + m0 + mi * 16 + rq]     = s0;
            sums[wg * 256 + m0 + mi * 16 + rq + 8] = s1;
        }
    }
    __syncthreads();
    if (tid < 256)
        rsq[tid] = rsqrtf((sums[tid] + sums[256 + tid] + sums[512 + tid]
                           + sums[768 + tid]) * (1.f / HD) + EPSV);
    __syncthreads();

    const float* svec = (z == 0) ? qsc : ksc;
#pragma unroll
    for (int mi = 0; mi < 4; mi++) {
        const int ra = m0 + mi * 16 + rq, rb2 = ra + 8;
#pragma unroll
        for (int ni = 0; ni < 4; ni++) {
            const int d0 = n0 + ni * 8 + (lane & 3) * 2;
            const float sc0 = svec[d0], sc1 = svec[d0 + 1];
            xs[ra * XSROW + d0]      = acc[mi][ni][0] * rsq[ra] * sc0;
            xs[ra * XSROW + d0 + 1]  = acc[mi][ni][1] * rsq[ra] * sc1;
            xs[rb2 * XSROW + d0]     = acc[mi][ni][2] * rsq[rb2] * sc0;
            xs[rb2 * XSROW + d0 + 1] = acc[mi][ni][3] * rsq[rb2] * sc1;
        }
    }
    __syncthreads();

#pragma unroll
    for (int mi = 0; mi < 4; mi++) {
#pragma unroll
        for (int hh2 = 0; hh2 < 2; hh2++) {
            const int rloc = m0 + mi * 16 + rq + hh2 * 8;
            const int rg = bm + rloc;
#pragma unroll
            for (int ni = 0; ni < 4; ni++) {
                const int d0 = n0 + ni * 8 + (lane & 3) * 2;
                const float x0 = xs[rloc * XSROW + d0];
                const float x1 = xs[rloc * XSROW + d0 + 1];
                float rot0, rot1;
                if (d0 < 64) { rot0 = -xs[rloc * XSROW + d0 + 64];
                               rot1 = -xs[rloc * XSROW + d0 + 65]; }
                else         { rot0 =  xs[rloc * XSROW + d0 - 64];
                               rot1 =  xs[rloc * XSROW + d0 - 63]; }
                const size_t cb = (size_t)rg * HD + d0;
                const float y0 = x0 * cosb[cb]     + rot0 * sinb[cb];
                const float y1 = x1 * cosb[cb + 1] + rot1 * sinb[cb + 1];
                const size_t o = (size_t)rg * DD + bn + d0;
                if (z == 0)
                    *(uint32_t*)&qf[o] = packh2(y0 * SCALEF, y1 * SCALEF);
                else
                    *(uint32_t*)&kfp[o] = packh2(y0, y1);
            }
        }
    }
}

// ---------------------------------------------------------------------------
// HMMA sliding-window flash attention, single fp16 operands.
//   S = Q*K ; O = P*V. Q pre-scaled/normed/roped.
// Block 256 threads (8 warps), q-tile 128, k-tile 64, double-buffered KV.
// ---------------------------------------------------------------------------
#define FQ 128
#define ROWB2 272
#define Q_BYTES (FQ * ROWB2)           // 34816
#define KVTILE (64 * ROWB2)            // 17408
#define KVBUF (2 * KVTILE)             // 34816  (K,V)
#define FLASH_SMEM (Q_BYTES + 2 * KVBUF)   // 104448

__global__ void __launch_bounds__(256) flash_hmma_kernel(
    const __half* __restrict__ Qf, const __half* __restrict__ Kf,
    const __half* __restrict__ Vf, __half* __restrict__ Oa)
{
    extern __shared__ char sm[];
    const uint32_t sb = smem_to_u32(sm);
    const int tid = threadIdx.x, lane = tid & 31, wid = tid >> 5;
    const int qb = blockIdx.x, h = blockIdx.y, b = blockIdx.z;
    const int qs0 = qb * FQ;
    const int mr = wid * 16;

    const int kb_lo = (qs0 >= WIN) ? (qs0 - WIN) / 64 : 0;
    const int kb_hi = (qs0 + FQ - 1) / 64;

    // Q tile via cp.async
    {
        const size_t qbase = ((size_t)(b * SS + qs0) * HH + h) * HD;
#pragma unroll
        for (int i = 0; i < 8; i++) {
            const int idx = tid + i * 256;
            const int r = idx >> 4, cc = idx & 15;
            cp16(sb + r * ROWB2 + cc * 16, Qf + qbase + (size_t)r * (HH * HD) + cc * 8);
        }
        CP_COMMIT();
    }
    // prologue: KV tile kb_lo -> buf 0  (1024 chunks K + 1024 V = 8/thread)
    {
        const uint32_t kvb = sb + Q_BYTES;
        const size_t base = ((size_t)(b * SS + kb_lo * 64) * HH + h) * HD;
#pragma unroll
        for (int i = 0; i < 8; i++) {
            const int idx = tid + i * 256;
            const int mat = idx >> 10, w = idx & 1023, r = w >> 4, cc = w & 15;
            const __half* src = (mat == 0) ? Kf : Vf;
            cp16(kvb + mat * KVTILE + r * ROWB2 + cc * 16,
                 src + base + (size_t)r * (HH * HD) + cc * 8);
        }
        CP_COMMIT();
    }

    float oacc[16][4];
#pragma unroll
    for (int j = 0; j < 16; j++)
#pragma unroll
        for (int c = 0; c < 4; c++) oacc[j][c] = 0.f;
    float m0 = 0.f, m1 = 0.f, l0s = 0.f, l1s = 0.f;

    const uint32_t g8 = (lane >> 3) & 1, g16 = (lane >> 4) & 1, l7 = lane & 7;
    const uint32_t a_addr0 = sb + (mr + g8 * 8 + l7) * ROWB2 + g16 * 16;

    for (int kb = kb_lo; kb <= kb_hi; kb++) {
        const int buf = (kb - kb_lo) & 1;
        const uint32_t kvb = sb + Q_BYTES + buf * KVBUF;

        asm volatile("cp.async.wait_group 0;");
        __syncthreads();

        if (kb + 1 <= kb_hi) {
            const uint32_t nb = sb + Q_BYTES + (buf ^ 1) * KVBUF;
            const size_t base = ((size_t)(b * SS + (kb + 1) * 64) * HH + h) * HD;
#pragma unroll
            for (int i = 0; i < 8; i++) {
                const int idx = tid + i * 256;
                const int mat = idx >> 10, w = idx & 1023, r = w >> 4, cc = w & 15;
                const __half* src = (mat == 0) ? Kf : Vf;
                cp16(nb + mat * KVTILE + r * ROWB2 + cc * 16,
                     src + base + (size_t)r * (HH * HD) + cc * 8);
            }
        }
        CP_COMMIT();

        // ---- S = Q @ K^T ----
        float sacc[8][4];
#pragma unroll
        for (int j = 0; j < 8; j++)
#pragma unroll
            for (int c = 0; c < 4; c++) sacc[j][c] = 0.f;

#pragma unroll
        for (int kt = 0; kt < 8; kt++) {
            uint32_t aq[4];
            LDM_X4(aq[0], aq[1], aq[2], aq[3], a_addr0 + kt * 32);
#pragma unroll
            for (int nt = 0; nt < 4; nt++) {
                const uint32_t ba = kvb + (nt * 16 + g16 * 8 + l7) * ROWB2
                                  + kt * 32 + g8 * 16;
                uint32_t bh[4];
                LDM_X4(bh[0], bh[1], bh[2], bh[3], ba);
                mma_f16(sacc[2 * nt],     aq, bh[0], bh[1]);
                mma_f16(sacc[2 * nt + 1], aq, bh[2], bh[3]);
            }
        }

        // ---- mask ----
        const int gi0 = qs0 + mr + (lane >> 2);
        const int gi1 = gi0 + 8;
        const bool interior = (kb * 64 + 63 <= qs0) && (kb * 64 >= qs0 + FQ - 1 - WIN);
        if (!interior) {
#pragma unroll
            for (int j = 0; j < 8; j++) {
                const int gj = kb * 64 + j * 8 + (lane & 3) * 2;
                if (gj > gi0 || gj < gi0 - WIN)         sacc[j][0] = -1e30f;
                if (gj + 1 > gi0 || gj + 1 < gi0 - WIN) sacc[j][1] = -1e30f;
                if (gj > gi1 || gj < gi1 - WIN)         sacc[j][2] = -1e30f;
                if (gj + 1 > gi1 || gj + 1 < gi1 - WIN) sacc[j][3] = -1e30f;
            }
        }

        // ---- online softmax ----
        float rmax0 = -1e30f, rmax1 = -1e30f;
#pragma unroll
        for (int j = 0; j < 8; j++) {
            rmax0 = fmaxf(rmax0, fmaxf(sacc[j][0], sacc[j][1]));
            rmax1 = fmaxf(rmax1, fmaxf(sacc[j][2], sacc[j][3]));
        }
        rmax0 = fmaxf(rmax0, __shfl_xor_sync(0xffffffffu, rmax0, 1));
        rmax0 = fmaxf(rmax0, __shfl_xor_sync(0xffffffffu, rmax0, 2));
        rmax1 = fmaxf(rmax1, __shfl_xor_sync(0xffffffffu, rmax1, 1));
        rmax1 = fmaxf(rmax1, __shfl_xor_sync(0xffffffffu, rmax1, 2));
        const float m0n = fmaxf(m0, rmax0), m1n = fmaxf(m1, rmax1);
        const float c0 = __expf(m0 - m0n), c1 = __expf(m1 - m1n);

        uint32_t pa[4][4];
        float ls0 = 0.f, ls1 = 0.f;
#pragma unroll
        for (int t = 0; t < 4; t++) {
#pragma unroll
            for (int q = 0; q < 2; q++) {
                const int j = 2 * t + q;
                const float p0 = __expf(sacc[j][0] - m0n);
                const float p1 = __expf(sacc[j][1] - m0n);
                const float p2 = __expf(sacc[j][2] - m1n);
                const float p3 = __expf(sacc[j][3] - m1n);
                ls0 += p0 + p1; ls1 += p2 + p3;
                pa[t][2 * q]     = packh2(p0, p1);
                pa[t][2 * q + 1] = packh2(p2, p3);
            }
        }
        ls0 += __shfl_xor_sync(0xffffffffu, ls0, 1);
        ls0 += __shfl_xor_sync(0xffffffffu, ls0, 2);
        ls1 += __shfl_xor_sync(0xffffffffu, ls1, 1);
        ls1 += __shfl_xor_sync(0xffffffffu, ls1, 2);
        l0s = l0s * c0 + ls0;
        l1s = l1s * c1 + ls1;
        m0 = m0n; m1 = m1n;
#pragma unroll
        for (int j = 0; j < 16; j++) {
            oacc[j][0] *= c0; oacc[j][1] *= c0;
            oacc[j][2] *= c1; oacc[j][3] *= c1;
        }

        // ---- O += P @ V ----
#pragma unroll
        for (int t = 0; t < 4; t++) {
#pragma unroll
            for (int dn = 0; dn < 8; dn++) {
                const uint32_t va = kvb + KVTILE
                    + (t * 16 + g8 * 8 + l7) * ROWB2 + dn * 32 + g16 * 16;
                uint32_t vh[4];
                LDM_X4_T(vh[0], vh[1], vh[2], vh[3], va);
                mma_f16(oacc[2 * dn],     pa[t], vh[0], vh[1]);
                mma_f16(oacc[2 * dn + 1], pa[t], vh[2], vh[3]);
            }
        }
        __syncthreads();
    }

    // ---- epilogue: write fp16 attn output ----
    const float inv0 = 1.f / l0s, inv1 = 1.f / l1s;
    const int r0 = qs0 + mr + (lane >> 2);
    const size_t ob0 = (((size_t)b * SS + r0) * HH + h) * HD;
    const size_t ob1 = (((size_t)b * SS + r0 + 8) * HH + h) * HD;
#pragma unroll
    for (int j = 0; j < 16; j++) {
        const int col = j * 8 + (lane & 3) * 2;
        *(uint32_t*)&Oa[ob0 + col] = packh2(oacc[j][0] * inv0, oacc[j][1] * inv0);
        *(uint32_t*)&Oa[ob1 + col] = packh2(oacc[j][2] * inv1, oacc[j][3] * inv1);
    }
}

// ---------------------------------------------------------------------------
extern "C" void kernel_launch(void* const* d_in, const int* in_sizes, int n_in,
                              void* d_out, int out_size)
{
    const float* hidden = (const float*)d_in[0];
    const float* cosb   = (const float*)d_in[1];
    const float* sinb   = (const float*)d_in[2];
    const float* Wq     = (const float*)d_in[3];
    const float* Wk     = (const float*)d_in[4];
    const float* Wv     = (const float*)d_in[5];
    const float* Wo     = (const float*)d_in[6];
    const float* qscale = (const float*)d_in[7];
    const float* kscale = (const float*)d_in[8];
    float* out = (float*)d_out;

    __half *hf, *af, *qf, *kf, *vf, *wq, *wk, *wv, *wo;
    cudaGetSymbolAddress((void**)&hf, g_hf);
    cudaGetSymbolAddress((void**)&af, g_af);
    cudaGetSymbolAddress((void**)&qf, g_qf);
    cudaGetSymbolAddress((void**)&kf, g_kf);
    cudaGetSymbolAddress((void**)&vf, g_vf);
    cudaGetSymbolAddress((void**)&wq, g_wq);
    cudaGetSymbolAddress((void**)&wk, g_wk);
    cudaGetSymbolAddress((void**)&wv, g_wv);
    cudaGetSymbolAddress((void**)&wo, g_wo);

    cudaFuncSetAttribute(flash_hmma_kernel,
                         cudaFuncAttributeMaxDynamicSharedMemorySize, FLASH_SMEM);
    cudaFuncSetAttribute(gemm_mma_kernel<0>,
                         cudaFuncAttributeMaxDynamicSharedMemorySize, GSMEM);
    cudaFuncSetAttribute(gemm_mma_kernel<1>,
                         cudaFuncAttributeMaxDynamicSharedMemorySize, GSMEM);

    const int M = BB * SS;                 // 4096
    const int n4 = M * DD / 4;
    dim3 tgrid(DD / 32, DD / 32);
    dim3 tblk(32, 8);
    dim3 qkv_grid(DD / GBN, M / GBM, 3);   // (16, 16, 3)
    dim3 wo_grid(DD / GBN, M / GBM, 1);

    transpose_half_kernel<<<tgrid, tblk>>>(Wq, wq);
    transpose_half_kernel<<<tgrid, tblk>>>(Wk, wk);
    transpose_half_kernel<<<tgrid, tblk>>>(Wv, wv);
    convert_half_kernel<<<(n4 + 255) / 256, 256>>>(hidden, hf, n4);

    // fused QKV projection + RMSNorm + RoPE + fp16 conversion
    gemm_mma_kernel<0><<<qkv_grid, 512, GSMEM>>>(hf,
        wq, wk, wv, qf, kf, vf, cosb, sinb, qscale, kscale,
        nullptr, M, DD, DD);

    transpose_half_kernel<<<tgrid, tblk>>>(Wo, wo);

    flash_hmma_kernel<<<dim3(SS / FQ, HH, BB), 256, FLASH_SMEM>>>(qf, kf, vf, af);

    // output projection
    gemm_mma_kernel<1><<<wo_grid, 512, GSMEM>>>(af,
        wo, wo, wo, nullptr, nullptr, nullptr,
        nullptr, nullptr, nullptr, nullptr,
        out, M, DD, DD);
}

// round 10
// speedup vs baseline: 8.5983x; 1.0127x over previous
#include <cuda_runtime.h>
#include <cuda_fp16.h>
#include <math.h>
#include <stdint.h>

#define BB 2
#define SS 2048
#define DD 2048
#define HH 16
#define HD 128
#define WIN 1024
#define EPSV 1e-6f
#define SCALEF 0.08838834764831845f   // 128^-0.5
#define QSC2 (0.08838834764831845f * 1.4426950408889634f)   // SCALE * log2(e)

// fp16 operand buffers
__device__ __half g_hf[BB * SS * DD];          // hidden
__device__ __half g_af[BB * SS * DD];          // attn-out
__device__ __half g_qf[BB * SS * DD];          // Q (normed+roped+scaled, base-2)
__device__ __half g_kf[BB * SS * DD];          // K (normed+roped)
__device__ __half g_vf[BB * SS * DD];          // V
__device__ __half g_wq[DD * DD], g_wk[DD * DD], g_wv[DD * DD], g_wo[DD * DD];

// ---------------------------------------------------------------------------
// helpers (compute_103-safe baseline PTX: mma.sync / ldmatrix / cp.async)
// ---------------------------------------------------------------------------
__device__ __forceinline__ uint32_t smem_to_u32(const void* p) {
    uint32_t a;
    asm("{ .reg .u64 t; cvta.to.shared.u64 t, %1; cvt.u32.u64 %0, t; }"
        : "=r"(a) : "l"(p));
    return a;
}

#define LDM_X4(r0, r1, r2, r3, a) \
    asm volatile("ldmatrix.sync.aligned.m8n8.x4.shared.b16 {%0,%1,%2,%3}, [%4];" \
        : "=r"(r0), "=r"(r1), "=r"(r2), "=r"(r3) : "r"(a))

#define LDM_X4_T(r0, r1, r2, r3, a) \
    asm volatile("ldmatrix.sync.aligned.m8n8.x4.trans.shared.b16 {%0,%1,%2,%3}, [%4];" \
        : "=r"(r0), "=r"(r1), "=r"(r2), "=r"(r3) : "r"(a))

__device__ __forceinline__ void mma_f16(float* d, const uint32_t* a,
                                        uint32_t b0, uint32_t b1) {
    asm volatile(
        "mma.sync.aligned.m16n8k16.row.col.f32.f16.f16.f32 "
        "{%0,%1,%2,%3}, {%4,%5,%6,%7}, {%8,%9}, {%0,%1,%2,%3};"
        : "+f"(d[0]), "+f"(d[1]), "+f"(d[2]), "+f"(d[3])
        : "r"(a[0]), "r"(a[1]), "r"(a[2]), "r"(a[3]), "r"(b0), "r"(b1));
}

__device__ __forceinline__ void cp16(uint32_t dst, const void* src) {
    asm volatile("cp.async.cg.shared.global [%0], [%1], 16;" :: "r"(dst), "l"(src));
}
#define CP_COMMIT() asm volatile("cp.async.commit_group;")

__device__ __forceinline__ uint32_t packh2(float x, float y) {
    __half2 h = __floats2half2_rn(x, y);
    return *(uint32_t*)&h;
}

// ---------------------------------------------------------------------------
// fp32 -> fp16 (elementwise)
// ---------------------------------------------------------------------------
__global__ void __launch_bounds__(256) convert_half_kernel(
    const float* __restrict__ x, __half* __restrict__ y, int n4)
{
    int i = blockIdx.x * blockDim.x + threadIdx.x;
    if (i >= n4) return;
    float4 v = ((const float4*)x)[i];
    *(uint2*)(y + 4 * (size_t)i) = make_uint2(packh2(v.x, v.y), packh2(v.z, v.w));
}

// ---------------------------------------------------------------------------
// All 4 weights in one launch: W_z[K][N] fp32 -> transposed fp16 [N][K]
// ---------------------------------------------------------------------------
__global__ void __launch_bounds__(256) transpose_all_kernel(
    const float* __restrict__ W0, const float* __restrict__ W1,
    const float* __restrict__ W2, const float* __restrict__ W3,
    __half* __restrict__ T0, __half* __restrict__ T1,
    __half* __restrict__ T2, __half* __restrict__ T3)
{
    const int z = blockIdx.z;
    const float* W = (z == 0) ? W0 : (z == 1) ? W1 : (z == 2) ? W2 : W3;
    __half*      T = (z == 0) ? T0 : (z == 1) ? T1 : (z == 2) ? T2 : T3;

    __shared__ float t[32][33];
    const int k0 = blockIdx.y * 32, n0 = blockIdx.x * 32;
    const int tx = threadIdx.x, ty = threadIdx.y;
#pragma unroll
    for (int r = 0; r < 32; r += 8)
        t[ty + r][tx] = W[(size_t)(k0 + ty + r) * DD + n0 + tx];
    __syncthreads();
#pragma unroll
    for (int r = 0; r < 32; r += 8)
        T[(size_t)(n0 + ty + r) * DD + k0 + tx] = __float2half_rn(t[tx][ty + r]);
}

// ---------------------------------------------------------------------------
// fp16 single-product GEMM on HMMA. CTA tile 256x128, BK=32, 512 threads,
// 4-stage cp.async pipeline.
// MODE 0: fused QKV — grid.z in {0,1,2}; epilogue does RMSNorm+RoPE (z<2),
//         writes fp16 (Q pre-scaled by SCALE*log2e for base-2 softmax).
// MODE 1: plain fp32 store to C (Wo projection).
// ---------------------------------------------------------------------------
#define GBM 256
#define GBN 128
#define ROWB 80
#define A_OFF 0
#define B_OFF (GBM * ROWB)               // 20480
#define STAGEB (B_OFF + GBN * ROWB)      // 30720
#define NSTAGE 4
#define XSROW 132
#define SUMS_OFF 135168
#define RSQ_OFF  139264
#define GSMEM 140288

template <int MODE>
__global__ void __launch_bounds__(512) gemm_mma_kernel(
    const __half* __restrict__ A,
    const __half* __restrict__ B0, const __half* __restrict__ B1,
    const __half* __restrict__ B2,
    __half* __restrict__ qf, __half* __restrict__ kfp, __half* __restrict__ vfp,
    const float* __restrict__ cosb, const float* __restrict__ sinb,
    const float* __restrict__ qsc, const float* __restrict__ ksc,
    float* __restrict__ C, int M, int N, int K)
{
    extern __shared__ char smc[];
    const uint32_t sb = smem_to_u32(smc);
    const int tid = threadIdx.x, lane = tid & 31, wid = tid >> 5;
    const int bm = blockIdx.y * GBM, bn = blockIdx.x * GBN;
    const int z = blockIdx.z;
    const __half* B = (z == 0) ? B0 : (z == 1) ? B1 : B2;

    const int m0 = (wid & 3) * 64, n0 = (wid >> 2) * 32;

    float acc[4][4][4];
#pragma unroll
    for (int i = 0; i < 4; i++)
#pragma unroll
        for (int j = 0; j < 4; j++)
#pragma unroll
            for (int c = 0; c < 4; c++) acc[i][j][c] = 0.f;

    const __half* gsrc[3];
    uint32_t sdst[3];
#pragma unroll
    for (int j = 0; j < 3; j++) {
        const int idx = j * 512 + tid;
        const int mat = (idx < 1024) ? 0 : 1;
        const int row = (mat == 0) ? (idx >> 2) : ((idx - 1024) >> 2);
        const int cc = idx & 3;
        const __half* base = (mat == 0) ? A : B;
        const int r = ((mat == 0) ? bm : bn) + row;
        gsrc[j] = base + (size_t)r * K + cc * 8;
        sdst[j] = sb + ((mat == 0) ? A_OFF : B_OFF) + row * ROWB + cc * 16;
    }

    const int nk = K >> 5;

#pragma unroll
    for (int s = 0; s < 3; s++) {
        const uint32_t so = s * STAGEB;
        const int kc = s * 32;
#pragma unroll
        for (int j = 0; j < 3; j++) cp16(sdst[j] + so, gsrc[j] + kc);
        CP_COMMIT();
    }

    for (int c = 0; c < nk; c++) {
        if (c + 3 < nk) {
            const uint32_t so = ((c + 3) % NSTAGE) * STAGEB;
            const int kc = (c + 3) * 32;
#pragma unroll
            for (int j = 0; j < 3; j++) cp16(sdst[j] + so, gsrc[j] + kc);
        }
        CP_COMMIT();
        asm volatile("cp.async.wait_group 3;");
        __syncthreads();

        const uint32_t st = sb + (c % NSTAGE) * STAGEB;
#pragma unroll
        for (int ks = 0; ks < 2; ks++) {
            const uint32_t kb = ks * 32;
            uint32_t b0[4], b1[4];
            {
                const uint32_t rb = st + B_OFF + (n0 + lane) * ROWB + kb;
                LDM_X4(b0[0], b0[1], b0[2], b0[3], rb);
                LDM_X4(b1[0], b1[1], b1[2], b1[3], rb + 16);
            }
#pragma unroll
            for (int mi = 0; mi < 4; mi++) {
                uint32_t ah[4];
                const uint32_t ra = st + A_OFF
                    + (m0 + mi * 16 + (lane & 15)) * ROWB + kb + ((lane >> 4) << 4);
                LDM_X4(ah[0], ah[1], ah[2], ah[3], ra);
#pragma unroll
                for (int ni = 0; ni < 4; ni++)
                    mma_f16(acc[mi][ni], ah, b0[ni], b1[ni]);
            }
        }
        __syncthreads();
    }

    if (MODE == 1) {
#pragma unroll
        for (int mi = 0; mi < 4; mi++) {
            const int r0 = bm + m0 + mi * 16 + (lane >> 2);
#pragma unroll
            for (int ni = 0; ni < 4; ni++) {
                const int c0 = bn + n0 + ni * 8 + (lane & 3) * 2;
                *(float2*)&C[(size_t)r0 * N + c0] =
                    make_float2(acc[mi][ni][0], acc[mi][ni][1]);
                *(float2*)&C[(size_t)(r0 + 8) * N + c0] =
                    make_float2(acc[mi][ni][2], acc[mi][ni][3]);
            }
        }
        return;
    }

    // ---- fused QKV epilogue ----
    const int wg = wid >> 2;
    const int rq = lane >> 2;

    if (z == 2) {
#pragma unroll
        for (int mi = 0; mi < 4; mi++) {
            const int rg = bm + m0 + mi * 16 + rq;
#pragma unroll
            for (int ni = 0; ni < 4; ni++) {
                const int d0 = n0 + ni * 8 + (lane & 3) * 2;
                size_t o = (size_t)rg * DD + bn + d0;
                *(uint32_t*)&vfp[o] = packh2(acc[mi][ni][0], acc[mi][ni][1]);
                o += (size_t)8 * DD;
                *(uint32_t*)&vfp[o] = packh2(acc[mi][ni][2], acc[mi][ni][3]);
            }
        }
        return;
    }

    float* xs   = (float*)smc;
    float* sums = (float*)(smc + SUMS_OFF);
    float* rsq  = (float*)(smc + RSQ_OFF);

#pragma unroll
    for (int mi = 0; mi < 4; mi++) {
        float s0 = 0.f, s1 = 0.f;
#pragma unroll
        for (int ni = 0; ni < 4; ni++) {
            s0 += acc[mi][ni][0] * acc[mi][ni][0] + acc[mi][ni][1] * acc[mi][ni][1];
            s1 += acc[mi][ni][2] * acc[mi][ni][2] + acc[mi][ni][3] * acc[mi][ni][3];
        }
        s0 += __shfl_xor_sync(0xffffffffu, s0, 1);
        s0 += __shfl_xor_sync(0xffffffffu, s0, 2);
        s1 += __shfl_xor_sync(0xffffffffu, s1, 1);
        s1 += __shfl_xor_sync(0xffffffffu, s1, 2);
        if ((lane & 3) == 0) {
            sums[wg * 256 + m0 + mi * 16 + rq]     = s0;
            sums[wg * 256 + m0 + mi * 16 + rq + 8] = s1;
        }
    }
    __syncthreads();
    if (tid < 256)
        rsq[tid] = rsqrtf((sums[tid] + sums[256 + tid] + sums[512 + tid]
                           + sums[768 + tid]) * (1.f / HD) + EPSV);
    __syncthreads();

    const float* svec = (z == 0) ? qsc : ksc;
#pragma unroll
    for (int mi = 0; mi < 4; mi++) {
        const int ra = m0 + mi * 16 + rq, rb2 = ra + 8;
#pragma unroll
        for (int ni = 0; ni < 4; ni++) {
            const int d0 = n0 + ni * 8 + (lane & 3) * 2;
            const float sc0 = svec[d0], sc1 = svec[d0 + 1];
            xs[ra * XSROW + d0]      = acc[mi][ni][0] * rsq[ra] * sc0;
            xs[ra * XSROW + d0 + 1]  = acc[mi][ni][1] * rsq[ra] * sc1;
            xs[rb2 * XSROW + d0]     = acc[mi][ni][2] * rsq[rb2] * sc0;
            xs[rb2 * XSROW + d0 + 1] = acc[mi][ni][3] * rsq[rb2] * sc1;
        }
    }
    __syncthreads();

#pragma unroll
    for (int mi = 0; mi < 4; mi++) {
#pragma unroll
        for (int hh2 = 0; hh2 < 2; hh2++) {
            const int rloc = m0 + mi * 16 + rq + hh2 * 8;
            const int rg = bm + rloc;
#pragma unroll
            for (int ni = 0; ni < 4; ni++) {
                const int d0 = n0 + ni * 8 + (lane & 3) * 2;
                const float x0 = xs[rloc * XSROW + d0];
                const float x1 = xs[rloc * XSROW + d0 + 1];
                float rot0, rot1;
                if (d0 < 64) { rot0 = -xs[rloc * XSROW + d0 + 64];
                               rot1 = -xs[rloc * XSROW + d0 + 65]; }
                else         { rot0 =  xs[rloc * XSROW + d0 - 64];
                               rot1 =  xs[rloc * XSROW + d0 - 63]; }
                const size_t cb = (size_t)rg * HD + d0;
                const float y0 = x0 * cosb[cb]     + rot0 * sinb[cb];
                const float y1 = x1 * cosb[cb + 1] + rot1 * sinb[cb + 1];
                const size_t o = (size_t)rg * DD + bn + d0;
                if (z == 0)
                    *(uint32_t*)&qf[o] = packh2(y0 * QSC2, y1 * QSC2);
                else
                    *(uint32_t*)&kfp[o] = packh2(y0, y1);
            }
        }
    }
}

// ---------------------------------------------------------------------------
// HMMA sliding-window flash attention, single fp16 operands, base-2 softmax.
//   S2 = Q2*K (Q2 = Q * SCALE*log2e) ; P = exp2(S2 - m) ; O = P*V.
// Block 256 threads (8 warps), q-tile 128, k-tile 64, double-buffered KV.
// 2 CTAs/SM target via launch_bounds.
// ---------------------------------------------------------------------------
#define FQ 128
#define ROWB2 272
#define Q_BYTES (FQ * ROWB2)           // 34816
#define KVTILE (64 * ROWB2)            // 17408
#define KVBUF (2 * KVTILE)             // 34816
#define FLASH_SMEM (Q_BYTES + 2 * KVBUF)   // 104448

__global__ void __launch_bounds__(256, 2) flash_hmma_kernel(
    const __half* __restrict__ Qf, const __half* __restrict__ Kf,
    const __half* __restrict__ Vf, __half* __restrict__ Oa)
{
    extern __shared__ char sm[];
    const uint32_t sb = smem_to_u32(sm);
    const int tid = threadIdx.x, lane = tid & 31, wid = tid >> 5;
    const int qb = blockIdx.x, h = blockIdx.y, b = blockIdx.z;
    const int qs0 = qb * FQ;
    const int mr = wid * 16;

    const int kb_lo = (qs0 >= WIN) ? (qs0 - WIN) / 64 : 0;
    const int kb_hi = (qs0 + FQ - 1) / 64;

    {
        const size_t qbase = ((size_t)(b * SS + qs0) * HH + h) * HD;
#pragma unroll
        for (int i = 0; i < 8; i++) {
            const int idx = tid + i * 256;
            const int r = idx >> 4, cc = idx & 15;
            cp16(sb + r * ROWB2 + cc * 16, Qf + qbase + (size_t)r * (HH * HD) + cc * 8);
        }
        CP_COMMIT();
    }
    {
        const uint32_t kvb = sb + Q_BYTES;
        const size_t base = ((size_t)(b * SS + kb_lo * 64) * HH + h) * HD;
#pragma unroll
        for (int i = 0; i < 8; i++) {
            const int idx = tid + i * 256;
            const int mat = idx >> 10, w = idx & 1023, r = w >> 4, cc = w & 15;
            const __half* src = (mat == 0) ? Kf : Vf;
            cp16(kvb + mat * KVTILE + r * ROWB2 + cc * 16,
                 src + base + (size_t)r * (HH * HD) + cc * 8);
        }
        CP_COMMIT();
    }

    float oacc[16][4];
#pragma unroll
    for (int j = 0; j < 16; j++)
#pragma unroll
        for (int c = 0; c < 4; c++) oacc[j][c] = 0.f;
    float m0 = 0.f, m1 = 0.f, l0s = 0.f, l1s = 0.f;

    const uint32_t g8 = (lane >> 3) & 1, g16 = (lane >> 4) & 1, l7 = lane & 7;
    const uint32_t a_addr0 = sb + (mr + g8 * 8 + l7) * ROWB2 + g16 * 16;

    for (int kb = kb_lo; kb <= kb_hi; kb++) {
        const int buf = (kb - kb_lo) & 1;
        const uint32_t kvb = sb + Q_BYTES + buf * KVBUF;

        asm volatile("cp.async.wait_group 0;");
        __syncthreads();

        if (kb + 1 <= kb_hi) {
            const uint32_t nb = sb + Q_BYTES + (buf ^ 1) * KVBUF;
            const size_t base = ((size_t)(b * SS + (kb + 1) * 64) * HH + h) * HD;
#pragma unroll
            for (int i = 0; i < 8; i++) {
                const int idx = tid + i * 256;
                const int mat = idx >> 10, w = idx & 1023, r = w >> 4, cc = w & 15;
                const __half* src = (mat == 0) ? Kf : Vf;
                cp16(nb + mat * KVTILE + r * ROWB2 + cc * 16,
                     src + base + (size_t)r * (HH * HD) + cc * 8);
            }
        }
        CP_COMMIT();

        // ---- S = Q @ K^T (base-2 scaled) ----
        float sacc[8][4];
#pragma unroll
        for (int j = 0; j < 8; j++)
#pragma unroll
            for (int c = 0; c < 4; c++) sacc[j][c] = 0.f;

#pragma unroll
        for (int kt = 0; kt < 8; kt++) {
            uint32_t aq[4];
            LDM_X4(aq[0], aq[1], aq[2], aq[3], a_addr0 + kt * 32);
#pragma unroll
            for (int nt = 0; nt < 4; nt++) {
                const uint32_t ba = kvb + (nt * 16 + g16 * 8 + l7) * ROWB2
                                  + kt * 32 + g8 * 16;
                uint32_t bh[4];
                LDM_X4(bh[0], bh[1], bh[2], bh[3], ba);
                mma_f16(sacc[2 * nt],     aq, bh[0], bh[1]);
                mma_f16(sacc[2 * nt + 1], aq, bh[2], bh[3]);
            }
        }

        // ---- mask ----
        const int gi0 = qs0 + mr + (lane >> 2);
        const int gi1 = gi0 + 8;
        const bool interior = (kb * 64 + 63 <= qs0) && (kb * 64 >= qs0 + FQ - 1 - WIN);
        if (!interior) {
#pragma unroll
            for (int j = 0; j < 8; j++) {
                const int gj = kb * 64 + j * 8 + (lane & 3) * 2;
                if (gj > gi0 || gj < gi0 - WIN)         sacc[j][0] = -1e30f;
                if (gj + 1 > gi0 || gj + 1 < gi0 - WIN) sacc[j][1] = -1e30f;
                if (gj > gi1 || gj < gi1 - WIN)         sacc[j][2] = -1e30f;
                if (gj + 1 > gi1 || gj + 1 < gi1 - WIN) sacc[j][3] = -1e30f;
            }
        }

        // ---- online softmax (base 2) ----
        float rmax0 = -1e30f, rmax1 = -1e30f;
#pragma unroll
        for (int j = 0; j < 8; j++) {
            rmax0 = fmaxf(rmax0, fmaxf(sacc[j][0], sacc[j][1]));
            rmax1 = fmaxf(rmax1, fmaxf(sacc[j][2], sacc[j][3]));
        }
        rmax0 = fmaxf(rmax0, __shfl_xor_sync(0xffffffffu, rmax0, 1));
        rmax0 = fmaxf(rmax0, __shfl_xor_sync(0xffffffffu, rmax0, 2));
        rmax1 = fmaxf(rmax1, __shfl_xor_sync(0xffffffffu, rmax1, 1));
        rmax1 = fmaxf(rmax1, __shfl_xor_sync(0xffffffffu, rmax1, 2));
        const float m0n = fmaxf(m0, rmax0), m1n = fmaxf(m1, rmax1);
        const float c0 = exp2f(m0 - m0n), c1 = exp2f(m1 - m1n);

        uint32_t pa[4][4];
        float ls0 = 0.f, ls1 = 0.f;
#pragma unroll
        for (int t = 0; t < 4; t++) {
#pragma unroll
            for (int q = 0; q < 2; q++) {
                const int j = 2 * t + q;
                const float p0 = exp2f(sacc[j][0] - m0n);
                const float p1 = exp2f(sacc[j][1] - m0n);
                const float p2 = exp2f(sacc[j][2] - m1n);
                const float p3 = exp2f(sacc[j][3] - m1n);
                ls0 += p0 + p1; ls1 += p2 + p3;
                pa[t][2 * q]     = packh2(p0, p1);
                pa[t][2 * q + 1] = packh2(p2, p3);
            }
        }
        ls0 += __shfl_xor_sync(0xffffffffu, ls0, 1);
        ls0 += __shfl_xor_sync(0xffffffffu, ls0, 2);
        ls1 += __shfl_xor_sync(0xffffffffu, ls1, 1);
        ls1 += __shfl_xor_sync(0xffffffffu, ls1, 2);
        l0s = l0s * c0 + ls0;
        l1s = l1s * c1 + ls1;
        m0 = m0n; m1 = m1n;
#pragma unroll
        for (int j = 0; j < 16; j++) {
            oacc[j][0] *= c0; oacc[j][1] *= c0;
            oacc[j][2] *= c1; oacc[j][3] *= c1;
        }

        // ---- O += P @ V ----
#pragma unroll
        for (int t = 0; t < 4; t++) {
#pragma unroll
            for (int dn = 0; dn < 8; dn++) {
                const uint32_t va = kvb + KVTILE
                    + (t * 16 + g8 * 8 + l7) * ROWB2 + dn * 32 + g16 * 16;
                uint32_t vh[4];
                LDM_X4_T(vh[0], vh[1], vh[2], vh[3], va);
                mma_f16(oacc[2 * dn],     pa[t], vh[0], vh[1]);
                mma_f16(oacc[2 * dn + 1], pa[t], vh[2], vh[3]);
            }
        }
        __syncthreads();
    }

    // ---- epilogue: write fp16 attn output ----
    const float inv0 = 1.f / l0s, inv1 = 1.f / l1s;
    const int r0 = qs0 + mr + (lane >> 2);
    const size_t ob0 = (((size_t)b * SS + r0) * HH + h) * HD;
    const size_t ob1 = (((size_t)b * SS + r0 + 8) * HH + h) * HD;
#pragma unroll
    for (int j = 0; j < 16; j++) {
        const int col = j * 8 + (lane & 3) * 2;
        *(uint32_t*)&Oa[ob0 + col] = packh2(oacc[j][0] * inv0, oacc[j][1] * inv0);
        *(uint32_t*)&Oa[ob1 + col] = packh2(oacc[j][2] * inv1, oacc[j][3] * inv1);
    }
}

// ---------------------------------------------------------------------------
extern "C" void kernel_launch(void* const* d_in, const int* in_sizes, int n_in,
                              void* d_out, int out_size)
{
    const float* hidden = (const float*)d_in[0];
    const float* cosb   = (const float*)d_in[1];
    const float* sinb   = (const float*)d_in[2];
    const float* Wq     = (const float*)d_in[3];
    const float* Wk     = (const float*)d_in[4];
    const float* Wv     = (const float*)d_in[5];
    const float* Wo     = (const float*)d_in[6];
    const float* qscale = (const float*)d_in[7];
    const float* kscale = (const float*)d_in[8];
    float* out = (float*)d_out;

    __half *hf, *af, *qf, *kf, *vf, *wq, *wk, *wv, *wo;
    cudaGetSymbolAddress((void**)&hf, g_hf);
    cudaGetSymbolAddress((void**)&af, g_af);
    cudaGetSymbolAddress((void**)&qf, g_qf);
    cudaGetSymbolAddress((void**)&kf, g_kf);
    cudaGetSymbolAddress((void**)&vf, g_vf);
    cudaGetSymbolAddress((void**)&wq, g_wq);
    cudaGetSymbolAddress((void**)&wk, g_wk);
    cudaGetSymbolAddress((void**)&wv, g_wv);
    cudaGetSymbolAddress((void**)&wo, g_wo);

    cudaFuncSetAttribute(flash_hmma_kernel,
                         cudaFuncAttributeMaxDynamicSharedMemorySize, FLASH_SMEM);
    cudaFuncSetAttribute(gemm_mma_kernel<0>,
                         cudaFuncAttributeMaxDynamicSharedMemorySize, GSMEM);
    cudaFuncSetAttribute(gemm_mma_kernel<1>,
                         cudaFuncAttributeMaxDynamicSharedMemorySize, GSMEM);

    const int M = BB * SS;                 // 4096
    const int n4 = M * DD / 4;
    dim3 tgrid(DD / 32, DD / 32, 4);       // all 4 weights, one launch
    dim3 tblk(32, 8);
    dim3 qkv_grid(DD / GBN, M / GBM, 3);   // (16, 16, 3)
    dim3 wo_grid(DD / GBN, M / GBM, 1);

    // launch 1: all weight transposes (fused)
    transpose_all_kernel<<<tgrid, tblk>>>(Wq, Wk, Wv, Wo, wq, wk, wv, wo);
    // launch 2: hidden fp32->fp16
    convert_half_kernel<<<(n4 + 255) / 256, 256>>>(hidden, hf, n4);
    // launch 3: fused QKV projection + RMSNorm + RoPE
    gemm_mma_kernel<0><<<qkv_grid, 512, GSMEM>>>(hf,
        wq, wk, wv, qf, kf, vf, cosb, sinb, qscale, kscale,
        nullptr, M, DD, DD);
    // launch 4 (ncu sample target): flash attention
    flash_hmma_kernel<<<dim3(SS / FQ, HH, BB), 256, FLASH_SMEM>>>(qf, kf, vf, af);
    // launch 5: output projection
    gemm_mma_kernel<1><<<wo_grid, 512, GSMEM>>>(af,
        wo, wo, wo, nullptr, nullptr, nullptr,
        nullptr, nullptr, nullptr, nullptr,
        out, M, DD, DD);
}

// round 11
// speedup vs baseline: 9.5771x; 1.1138x over previous
#include <cuda_runtime.h>
#include <cuda_fp16.h>
#include <math.h>
#include <stdint.h>

#define BB 2
#define SS 2048
#define DD 2048
#define HH 16
#define HD 128
#define WIN 1024
#define EPSV 1e-6f
#define SCALEF 0.08838834764831845f   // 128^-0.5
#define QSC2 (0.08838834764831845f * 1.4426950408889634f)   // SCALE * log2(e)

// fp16 operand buffers
__device__ __half g_hf[BB * SS * DD];          // hidden
__device__ __half g_af[BB * SS * DD];          // attn-out
__device__ __half g_qf[BB * SS * DD];          // Q (normed+roped+scaled, base-2)
__device__ __half g_kf[BB * SS * DD];          // K (normed+roped)
__device__ __half g_vf[BB * SS * DD];          // V
__device__ __half g_wq[DD * DD], g_wk[DD * DD], g_wv[DD * DD], g_wo[DD * DD];

// ---------------------------------------------------------------------------
// helpers (compute_103-safe baseline PTX: mma.sync / ldmatrix / cp.async)
// ---------------------------------------------------------------------------
__device__ __forceinline__ uint32_t smem_to_u32(const void* p) {
    uint32_t a;
    asm("{ .reg .u64 t; cvta.to.shared.u64 t, %1; cvt.u32.u64 %0, t; }"
        : "=r"(a) : "l"(p));
    return a;
}

#define LDM_X4(r0, r1, r2, r3, a) \
    asm volatile("ldmatrix.sync.aligned.m8n8.x4.shared.b16 {%0,%1,%2,%3}, [%4];" \
        : "=r"(r0), "=r"(r1), "=r"(r2), "=r"(r3) : "r"(a))

#define LDM_X4_T(r0, r1, r2, r3, a) \
    asm volatile("ldmatrix.sync.aligned.m8n8.x4.trans.shared.b16 {%0,%1,%2,%3}, [%4];" \
        : "=r"(r0), "=r"(r1), "=r"(r2), "=r"(r3) : "r"(a))

__device__ __forceinline__ void mma_f16(float* d, const uint32_t* a,
                                        uint32_t b0, uint32_t b1) {
    asm volatile(
        "mma.sync.aligned.m16n8k16.row.col.f32.f16.f16.f32 "
        "{%0,%1,%2,%3}, {%4,%5,%6,%7}, {%8,%9}, {%0,%1,%2,%3};"
        : "+f"(d[0]), "+f"(d[1]), "+f"(d[2]), "+f"(d[3])
        : "r"(a[0]), "r"(a[1]), "r"(a[2]), "r"(a[3]), "r"(b0), "r"(b1));
}

__device__ __forceinline__ void cp16(uint32_t dst, const void* src) {
    asm volatile("cp.async.cg.shared.global [%0], [%1], 16;" :: "r"(dst), "l"(src));
}
#define CP_COMMIT() asm volatile("cp.async.commit_group;")

__device__ __forceinline__ uint32_t packh2(float x, float y) {
    __half2 h = __floats2half2_rn(x, y);
    return *(uint32_t*)&h;
}

// ---------------------------------------------------------------------------
// fp32 -> fp16 (elementwise)
// ---------------------------------------------------------------------------
__global__ void __launch_bounds__(256) convert_half_kernel(
    const float* __restrict__ x, __half* __restrict__ y, int n4)
{
    int i = blockIdx.x * blockDim.x + threadIdx.x;
    if (i >= n4) return;
    float4 v = ((const float4*)x)[i];
    *(uint2*)(y + 4 * (size_t)i) = make_uint2(packh2(v.x, v.y), packh2(v.z, v.w));
}

// ---------------------------------------------------------------------------
// All 4 weights in one launch: W_z[K][N] fp32 -> transposed fp16 [N][K]
// ---------------------------------------------------------------------------
__global__ void __launch_bounds__(256) transpose_all_kernel(
    const float* __restrict__ W0, const float* __restrict__ W1,
    const float* __restrict__ W2, const float* __restrict__ W3,
    __half* __restrict__ T0, __half* __restrict__ T1,
    __half* __restrict__ T2, __half* __restrict__ T3)
{
    const int z = blockIdx.z;
    const float* W = (z == 0) ? W0 : (z == 1) ? W1 : (z == 2) ? W2 : W3;
    __half*      T = (z == 0) ? T0 : (z == 1) ? T1 : (z == 2) ? T2 : T3;

    __shared__ float t[32][33];
    const int k0 = blockIdx.y * 32, n0 = blockIdx.x * 32;
    const int tx = threadIdx.x, ty = threadIdx.y;
#pragma unroll
    for (int r = 0; r < 32; r += 8)
        t[ty + r][tx] = W[(size_t)(k0 + ty + r) * DD + n0 + tx];
    __syncthreads();
#pragma unroll
    for (int r = 0; r < 32; r += 8)
        T[(size_t)(n0 + ty + r) * DD + k0 + tx] = __float2half_rn(t[tx][ty + r]);
}

// ---------------------------------------------------------------------------
// fp16 single-product GEMM on HMMA. CTA tile 128x128, BK=32, 256 threads
// (8 warps, warp tile 64x32), 4-stage cp.async pipeline, 2 CTAs/SM.
// MODE 0: fused QKV — grid.z in {0,1,2}; epilogue does RMSNorm+RoPE (z<2).
// MODE 1: plain fp32 store to C (Wo projection).
// ---------------------------------------------------------------------------
#define GBM 128
#define GBN 128
#define ROWB 80
#define A_OFF 0
#define B_OFF (GBM * ROWB)               // 10240
#define STAGEB (B_OFF + GBN * ROWB)      // 20480
#define NSTAGE 4
#define XSROW 132
#define SUMS_OFF 67584                    // xs: 128*132*4 = 67584
#define RSQ_OFF  69632                    // sums: 4*128*4 = 2048
#define GSMEM 81920                       // NSTAGE*STAGEB (covers epilogue 70144)

template <int MODE>
__global__ void __launch_bounds__(256, 2) gemm_mma_kernel(
    const __half* __restrict__ A,
    const __half* __restrict__ B0, const __half* __restrict__ B1,
    const __half* __restrict__ B2,
    __half* __restrict__ qf, __half* __restrict__ kfp, __half* __restrict__ vfp,
    const float* __restrict__ cosb, const float* __restrict__ sinb,
    const float* __restrict__ qsc, const float* __restrict__ ksc,
    float* __restrict__ C, int M, int N, int K)
{
    extern __shared__ char smc[];
    const uint32_t sb = smem_to_u32(smc);
    const int tid = threadIdx.x, lane = tid & 31, wid = tid >> 5;
    const int bm = blockIdx.y * GBM, bn = blockIdx.x * GBN;
    const int z = blockIdx.z;
    const __half* B = (z == 0) ? B0 : (z == 1) ? B1 : B2;

    const int m0 = (wid & 1) * 64, n0 = (wid >> 1) * 32;

    float acc[4][4][4];
#pragma unroll
    for (int i = 0; i < 4; i++)
#pragma unroll
        for (int j = 0; j < 4; j++)
#pragma unroll
            for (int c = 0; c < 4; c++) acc[i][j][c] = 0.f;

    // cp.async mapping: 1024 16B chunks / 256 threads = 4 per thread
    const __half* gsrc[4];
    uint32_t sdst[4];
#pragma unroll
    for (int j = 0; j < 4; j++) {
        const int idx = j * 256 + tid;
        const int mat = (idx < 512) ? 0 : 1;
        const int row = (idx & 511) >> 2;
        const int cc = idx & 3;
        const __half* base = (mat == 0) ? A : B;
        const int r = ((mat == 0) ? bm : bn) + row;
        gsrc[j] = base + (size_t)r * K + cc * 8;
        sdst[j] = sb + ((mat == 0) ? A_OFF : B_OFF) + row * ROWB + cc * 16;
    }

    const int nk = K >> 5;

#pragma unroll
    for (int s = 0; s < 3; s++) {
        const uint32_t so = s * STAGEB;
        const int kc = s * 32;
#pragma unroll
        for (int j = 0; j < 4; j++) cp16(sdst[j] + so, gsrc[j] + kc);
        CP_COMMIT();
    }

    for (int c = 0; c < nk; c++) {
        if (c + 3 < nk) {
            const uint32_t so = ((c + 3) % NSTAGE) * STAGEB;
            const int kc = (c + 3) * 32;
#pragma unroll
            for (int j = 0; j < 4; j++) cp16(sdst[j] + so, gsrc[j] + kc);
        }
        CP_COMMIT();
        asm volatile("cp.async.wait_group 3;");
        __syncthreads();

        const uint32_t st = sb + (c % NSTAGE) * STAGEB;
#pragma unroll
        for (int ks = 0; ks < 2; ks++) {
            const uint32_t kb = ks * 32;
            uint32_t b0[4], b1[4];
            {
                const uint32_t rb = st + B_OFF + (n0 + lane) * ROWB + kb;
                LDM_X4(b0[0], b0[1], b0[2], b0[3], rb);
                LDM_X4(b1[0], b1[1], b1[2], b1[3], rb + 16);
            }
#pragma unroll
            for (int mi = 0; mi < 4; mi++) {
                uint32_t ah[4];
                const uint32_t ra = st + A_OFF
                    + (m0 + mi * 16 + (lane & 15)) * ROWB + kb + ((lane >> 4) << 4);
                LDM_X4(ah[0], ah[1], ah[2], ah[3], ra);
#pragma unroll
                for (int ni = 0; ni < 4; ni++)
                    mma_f16(acc[mi][ni], ah, b0[ni], b1[ni]);
            }
        }
        __syncthreads();
    }

    if (MODE == 1) {
#pragma unroll
        for (int mi = 0; mi < 4; mi++) {
            const int r0 = bm + m0 + mi * 16 + (lane >> 2);
#pragma unroll
            for (int ni = 0; ni < 4; ni++) {
                const int c0 = bn + n0 + ni * 8 + (lane & 3) * 2;
                *(float2*)&C[(size_t)r0 * N + c0] =
                    make_float2(acc[mi][ni][0], acc[mi][ni][1]);
                *(float2*)&C[(size_t)(r0 + 8) * N + c0] =
                    make_float2(acc[mi][ni][2], acc[mi][ni][3]);
            }
        }
        return;
    }

    // ---- fused QKV epilogue ----
    const int wg = wid >> 1;     // N-chunk 0..3
    const int rq = lane >> 2;    // 0..7

    if (z == 2) {
#pragma unroll
        for (int mi = 0; mi < 4; mi++) {
            const int rg = bm + m0 + mi * 16 + rq;
#pragma unroll
            for (int ni = 0; ni < 4; ni++) {
                const int d0 = n0 + ni * 8 + (lane & 3) * 2;
                size_t o = (size_t)rg * DD + bn + d0;
                *(uint32_t*)&vfp[o] = packh2(acc[mi][ni][0], acc[mi][ni][1]);
                o += (size_t)8 * DD;
                *(uint32_t*)&vfp[o] = packh2(acc[mi][ni][2], acc[mi][ni][3]);
            }
        }
        return;
    }

    float* xs   = (float*)smc;
    float* sums = (float*)(smc + SUMS_OFF);
    float* rsq  = (float*)(smc + RSQ_OFF);

#pragma unroll
    for (int mi = 0; mi < 4; mi++) {
        float s0 = 0.f, s1 = 0.f;
#pragma unroll
        for (int ni = 0; ni < 4; ni++) {
            s0 += acc[mi][ni][0] * acc[mi][ni][0] + acc[mi][ni][1] * acc[mi][ni][1];
            s1 += acc[mi][ni][2] * acc[mi][ni][2] + acc[mi][ni][3] * acc[mi][ni][3];
        }
        s0 += __shfl_xor_sync(0xffffffffu, s0, 1);
        s0 += __shfl_xor_sync(0xffffffffu, s0, 2);
        s1 += __shfl_xor_sync(0xffffffffu, s1, 1);
        s1 += __shfl_xor_sync(0xffffffffu, s1, 2);
        if ((lane & 3) == 0) {
            sums[wg * 128 + m0 + mi * 16 + rq]     = s0;
            sums[wg * 128 + m0 + mi * 16 + rq + 8] = s1;
        }
    }
    __syncthreads();
    if (tid < 128)
        rsq[tid] = rsqrtf((sums[tid] + sums[128 + tid] + sums[256 + tid]
                           + sums[384 + tid]) * (1.f / HD) + EPSV);
    __syncthreads();

    const float* svec = (z == 0) ? qsc : ksc;
#pragma unroll
    for (int mi = 0; mi < 4; mi++) {
        const int ra = m0 + mi * 16 + rq, rb2 = ra + 8;
#pragma unroll
        for (int ni = 0; ni < 4; ni++) {
            const int d0 = n0 + ni * 8 + (lane & 3) * 2;
            const float sc0 = svec[d0], sc1 = svec[d0 + 1];
            xs[ra * XSROW + d0]      = acc[mi][ni][0] * rsq[ra] * sc0;
            xs[ra * XSROW + d0 + 1]  = acc[mi][ni][1] * rsq[ra] * sc1;
            xs[rb2 * XSROW + d0]     = acc[mi][ni][2] * rsq[rb2] * sc0;
            xs[rb2 * XSROW + d0 + 1] = acc[mi][ni][3] * rsq[rb2] * sc1;
        }
    }
    __syncthreads();

#pragma unroll
    for (int mi = 0; mi < 4; mi++) {
#pragma unroll
        for (int hh2 = 0; hh2 < 2; hh2++) {
            const int rloc = m0 + mi * 16 + rq + hh2 * 8;
            const int rg = bm + rloc;
#pragma unroll
            for (int ni = 0; ni < 4; ni++) {
                const int d0 = n0 + ni * 8 + (lane & 3) * 2;
                const float x0 = xs[rloc * XSROW + d0];
                const float x1 = xs[rloc * XSROW + d0 + 1];
                float rot0, rot1;
                if (d0 < 64) { rot0 = -xs[rloc * XSROW + d0 + 64];
                               rot1 = -xs[rloc * XSROW + d0 + 65]; }
                else         { rot0 =  xs[rloc * XSROW + d0 - 64];
                               rot1 =  xs[rloc * XSROW + d0 - 63]; }
                const size_t cb = (size_t)rg * HD + d0;
                const float y0 = x0 * cosb[cb]     + rot0 * sinb[cb];
                const float y1 = x1 * cosb[cb + 1] + rot1 * sinb[cb + 1];
                const size_t o = (size_t)rg * DD + bn + d0;
                if (z == 0)
                    *(uint32_t*)&qf[o] = packh2(y0 * QSC2, y1 * QSC2);
                else
                    *(uint32_t*)&kfp[o] = packh2(y0, y1);
            }
        }
    }
}

// ---------------------------------------------------------------------------
// HMMA sliding-window flash attention, single fp16 operands, base-2 softmax.
// Softmax/PV interleaved: oacc rescale right after max-reduce, then per
// N-chunk t: exp2 -> pack -> PV MMAs; ls reduction deferred to after PV.
// ---------------------------------------------------------------------------
#define FQ 128
#define ROWB2 272
#define Q_BYTES (FQ * ROWB2)           // 34816
#define KVTILE (64 * ROWB2)            // 17408
#define KVBUF (2 * KVTILE)             // 34816
#define FLASH_SMEM (Q_BYTES + 2 * KVBUF)   // 104448

__global__ void __launch_bounds__(256, 2) flash_hmma_kernel(
    const __half* __restrict__ Qf, const __half* __restrict__ Kf,
    const __half* __restrict__ Vf, __half* __restrict__ Oa)
{
    extern __shared__ char sm[];
    const uint32_t sb = smem_to_u32(sm);
    const int tid = threadIdx.x, lane = tid & 31, wid = tid >> 5;
    const int qb = blockIdx.x, h = blockIdx.y, b = blockIdx.z;
    const int qs0 = qb * FQ;
    const int mr = wid * 16;

    const int kb_lo = (qs0 >= WIN) ? (qs0 - WIN) / 64 : 0;
    const int kb_hi = (qs0 + FQ - 1) / 64;

    {
        const size_t qbase = ((size_t)(b * SS + qs0) * HH + h) * HD;
#pragma unroll
        for (int i = 0; i < 8; i++) {
            const int idx = tid + i * 256;
            const int r = idx >> 4, cc = idx & 15;
            cp16(sb + r * ROWB2 + cc * 16, Qf + qbase + (size_t)r * (HH * HD) + cc * 8);
        }
        CP_COMMIT();
    }
    {
        const uint32_t kvb = sb + Q_BYTES;
        const size_t base = ((size_t)(b * SS + kb_lo * 64) * HH + h) * HD;
#pragma unroll
        for (int i = 0; i < 8; i++) {
            const int idx = tid + i * 256;
            const int mat = idx >> 10, w = idx & 1023, r = w >> 4, cc = w & 15;
            const __half* src = (mat == 0) ? Kf : Vf;
            cp16(kvb + mat * KVTILE + r * ROWB2 + cc * 16,
                 src + base + (size_t)r * (HH * HD) + cc * 8);
        }
        CP_COMMIT();
    }

    float oacc[16][4];
#pragma unroll
    for (int j = 0; j < 16; j++)
#pragma unroll
        for (int c = 0; c < 4; c++) oacc[j][c] = 0.f;
    float m0 = 0.f, m1 = 0.f, l0s = 0.f, l1s = 0.f;

    const uint32_t g8 = (lane >> 3) & 1, g16 = (lane >> 4) & 1, l7 = lane & 7;
    const uint32_t a_addr0 = sb + (mr + g8 * 8 + l7) * ROWB2 + g16 * 16;

    for (int kb = kb_lo; kb <= kb_hi; kb++) {
        const int buf = (kb - kb_lo) & 1;
        const uint32_t kvb = sb + Q_BYTES + buf * KVBUF;

        asm volatile("cp.async.wait_group 0;");
        __syncthreads();

        if (kb + 1 <= kb_hi) {
            const uint32_t nb = sb + Q_BYTES + (buf ^ 1) * KVBUF;
            const size_t base = ((size_t)(b * SS + (kb + 1) * 64) * HH + h) * HD;
#pragma unroll
            for (int i = 0; i < 8; i++) {
                const int idx = tid + i * 256;
                const int mat = idx >> 10, w = idx & 1023, r = w >> 4, cc = w & 15;
                const __half* src = (mat == 0) ? Kf : Vf;
                cp16(nb + mat * KVTILE + r * ROWB2 + cc * 16,
                     src + base + (size_t)r * (HH * HD) + cc * 8);
            }
        }
        CP_COMMIT();

        // ---- S = Q @ K^T (base-2 scaled) ----
        float sacc[8][4];
#pragma unroll
        for (int j = 0; j < 8; j++)
#pragma unroll
            for (int c = 0; c < 4; c++) sacc[j][c] = 0.f;

#pragma unroll
        for (int kt = 0; kt < 8; kt++) {
            uint32_t aq[4];
            LDM_X4(aq[0], aq[1], aq[2], aq[3], a_addr0 + kt * 32);
#pragma unroll
            for (int nt = 0; nt < 4; nt++) {
                const uint32_t ba = kvb + (nt * 16 + g16 * 8 + l7) * ROWB2
                                  + kt * 32 + g8 * 16;
                uint32_t bh[4];
                LDM_X4(bh[0], bh[1], bh[2], bh[3], ba);
                mma_f16(sacc[2 * nt],     aq, bh[0], bh[1]);
                mma_f16(sacc[2 * nt + 1], aq, bh[2], bh[3]);
            }
        }

        // ---- mask ----
        const int gi0 = qs0 + mr + (lane >> 2);
        const int gi1 = gi0 + 8;
        const bool interior = (kb * 64 + 63 <= qs0) && (kb * 64 >= qs0 + FQ - 1 - WIN);
        if (!interior) {
#pragma unroll
            for (int j = 0; j < 8; j++) {
                const int gj = kb * 64 + j * 8 + (lane & 3) * 2;
                if (gj > gi0 || gj < gi0 - WIN)         sacc[j][0] = -1e30f;
                if (gj + 1 > gi0 || gj + 1 < gi0 - WIN) sacc[j][1] = -1e30f;
                if (gj > gi1 || gj < gi1 - WIN)         sacc[j][2] = -1e30f;
                if (gj + 1 > gi1 || gj + 1 < gi1 - WIN) sacc[j][3] = -1e30f;
            }
        }

        // ---- online softmax: max-reduce, rescale O, then per-chunk exp2+PV ----
        float rmax0 = -1e30f, rmax1 = -1e30f;
#pragma unroll
        for (int j = 0; j < 8; j++) {
            rmax0 = fmaxf(rmax0, fmaxf(sacc[j][0], sacc[j][1]));
            rmax1 = fmaxf(rmax1, fmaxf(sacc[j][2], sacc[j][3]));
        }
        rmax0 = fmaxf(rmax0, __shfl_xor_sync(0xffffffffu, rmax0, 1));
        rmax0 = fmaxf(rmax0, __shfl_xor_sync(0xffffffffu, rmax0, 2));
        rmax1 = fmaxf(rmax1, __shfl_xor_sync(0xffffffffu, rmax1, 1));
        rmax1 = fmaxf(rmax1, __shfl_xor_sync(0xffffffffu, rmax1, 2));
        const float m0n = fmaxf(m0, rmax0), m1n = fmaxf(m1, rmax1);
        const float c0 = exp2f(m0 - m0n), c1 = exp2f(m1 - m1n);
        m0 = m0n; m1 = m1n;
#pragma unroll
        for (int j = 0; j < 16; j++) {
            oacc[j][0] *= c0; oacc[j][1] *= c0;
            oacc[j][2] *= c1; oacc[j][3] *= c1;
        }

        float ls0 = 0.f, ls1 = 0.f;
#pragma unroll
        for (int t = 0; t < 4; t++) {
            uint32_t pa[4];
#pragma unroll
            for (int q = 0; q < 2; q++) {
                const int j = 2 * t + q;
                const float p0 = exp2f(sacc[j][0] - m0n);
                const float p1 = exp2f(sacc[j][1] - m0n);
                const float p2 = exp2f(sacc[j][2] - m1n);
                const float p3 = exp2f(sacc[j][3] - m1n);
                ls0 += p0 + p1; ls1 += p2 + p3;
                pa[2 * q]     = packh2(p0, p1);
                pa[2 * q + 1] = packh2(p2, p3);
            }
            // PV for this chunk immediately (overlaps next chunk's exp2)
#pragma unroll
            for (int dn = 0; dn < 8; dn++) {
                const uint32_t va = kvb + KVTILE
                    + (t * 16 + g8 * 8 + l7) * ROWB2 + dn * 32 + g16 * 16;
                uint32_t vh[4];
                LDM_X4_T(vh[0], vh[1], vh[2], vh[3], va);
                mma_f16(oacc[2 * dn],     pa, vh[0], vh[1]);
                mma_f16(oacc[2 * dn + 1], pa, vh[2], vh[3]);
            }
        }

        // deferred l update (off the MMA critical path)
        ls0 += __shfl_xor_sync(0xffffffffu, ls0, 1);
        ls0 += __shfl_xor_sync(0xffffffffu, ls0, 2);
        ls1 += __shfl_xor_sync(0xffffffffu, ls1, 1);
        ls1 += __shfl_xor_sync(0xffffffffu, ls1, 2);
        l0s = l0s * c0 + ls0;
        l1s = l1s * c1 + ls1;

        __syncthreads();
    }

    // ---- epilogue: write fp16 attn output ----
    const float inv0 = 1.f / l0s, inv1 = 1.f / l1s;
    const int r0 = qs0 + mr + (lane >> 2);
    const size_t ob0 = (((size_t)b * SS + r0) * HH + h) * HD;
    const size_t ob1 = (((size_t)b * SS + r0 + 8) * HH + h) * HD;
#pragma unroll
    for (int j = 0; j < 16; j++) {
        const int col = j * 8 + (lane & 3) * 2;
        *(uint32_t*)&Oa[ob0 + col] = packh2(oacc[j][0] * inv0, oacc[j][1] * inv0);
        *(uint32_t*)&Oa[ob1 + col] = packh2(oacc[j][2] * inv1, oacc[j][3] * inv1);
    }
}

// ---------------------------------------------------------------------------
extern "C" void kernel_launch(void* const* d_in, const int* in_sizes, int n_in,
                              void* d_out, int out_size)
{
    const float* hidden = (const float*)d_in[0];
    const float* cosb   = (const float*)d_in[1];
    const float* sinb   = (const float*)d_in[2];
    const float* Wq     = (const float*)d_in[3];
    const float* Wk     = (const float*)d_in[4];
    const float* Wv     = (const float*)d_in[5];
    const float* Wo     = (const float*)d_in[6];
    const float* qscale = (const float*)d_in[7];
    const float* kscale = (const float*)d_in[8];
    float* out = (float*)d_out;

    __half *hf, *af, *qf, *kf, *vf, *wq, *wk, *wv, *wo;
    cudaGetSymbolAddress((void**)&hf, g_hf);
    cudaGetSymbolAddress((void**)&af, g_af);
    cudaGetSymbolAddress((void**)&qf, g_qf);
    cudaGetSymbolAddress((void**)&kf, g_kf);
    cudaGetSymbolAddress((void**)&vf, g_vf);
    cudaGetSymbolAddress((void**)&wq, g_wq);
    cudaGetSymbolAddress((void**)&wk, g_wk);
    cudaGetSymbolAddress((void**)&wv, g_wv);
    cudaGetSymbolAddress((void**)&wo, g_wo);

    cudaFuncSetAttribute(flash_hmma_kernel,
                         cudaFuncAttributeMaxDynamicSharedMemorySize, FLASH_SMEM);
    cudaFuncSetAttribute(gemm_mma_kernel<0>,
                         cudaFuncAttributeMaxDynamicSharedMemorySize, GSMEM);
    cudaFuncSetAttribute(gemm_mma_kernel<1>,
                         cudaFuncAttributeMaxDynamicSharedMemorySize, GSMEM);

    const int M = BB * SS;                 // 4096
    const int n4 = M * DD / 4;
    dim3 tgrid(DD / 32, DD / 32, 4);
    dim3 tblk(32, 8);
    dim3 qkv_grid(DD / GBN, M / GBM, 3);   // (16, 32, 3) = 1536 CTAs
    dim3 wo_grid(DD / GBN, M / GBM, 1);    // 512 CTAs

    // launch 1: all weight transposes (fused)
    transpose_all_kernel<<<tgrid, tblk>>>(Wq, Wk, Wv, Wo, wq, wk, wv, wo);
    // launch 2: hidden fp32->fp16
    convert_half_kernel<<<(n4 + 255) / 256, 256>>>(hidden, hf, n4);
    // launch 3: fused QKV projection + RMSNorm + RoPE
    gemm_mma_kernel<0><<<qkv_grid, 256, GSMEM>>>(hf,
        wq, wk, wv, qf, kf, vf, cosb, sinb, qscale, kscale,
        nullptr, M, DD, DD);
    // launch 4 (ncu sample target): flash attention
    flash_hmma_kernel<<<dim3(SS / FQ, HH, BB), 256, FLASH_SMEM>>>(qf, kf, vf, af);
    // launch 5: output projection
    gemm_mma_kernel<1><<<wo_grid, 256, GSMEM>>>(af,
        wo, wo, wo, nullptr, nullptr, nullptr,
        nullptr, nullptr, nullptr, nullptr,
        out, M, DD, DD);
}